// round 10
// baseline (speedup 1.0000x reference)
#include <cuda_runtime.h>
#include <cuda_bf16.h>
#include <math.h>
#include <stdint.h>

#define B_  2
#define T_  2048
#define DM  2048
#define NH  16
#define HD  128
#define NROWS (B_ * T_)   // 4096

// ---------------- scratch (no runtime allocation allowed) ----------------
__device__ float g_Q[(size_t)NROWS * DM];
__device__ float g_K[(size_t)NROWS * DM];
__device__ float g_V[(size_t)NROWS * DM];
__device__ float g_A[(size_t)NROWS * DM];
__device__ float g_xc[(size_t)NROWS * DM];          // tf32-rounded, k-permuted x
__device__ float g_Wc[4][(size_t)DM * DM];          // tf32-rounded, k-permuted W

__device__ __forceinline__ uint32_t f2tf32(float x) {
    uint32_t r;
    asm("cvt.rna.tf32.f32 %0, %1;" : "=r"(r) : "f"(x));
    return r;
}
__device__ __forceinline__ float tf32f(float x) { return __uint_as_float(f2tf32(x)); }

__device__ __forceinline__ uint32_t smem_u32(const void* p) {
    uint32_t a;
    asm("{ .reg .u64 t; cvta.to.shared.u64 t, %1; cvt.u32.u64 %0, t; }" : "=r"(a) : "l"(p));
    return a;
}

__device__ __forceinline__ void mma_tf32_16n8k8(float c[4], const uint32_t a[4],
                                                const uint32_t b0, const uint32_t b1) {
    asm volatile(
        "mma.sync.aligned.m16n8k8.row.col.f32.tf32.tf32.f32 "
        "{%0,%1,%2,%3}, {%4,%5,%6,%7}, {%8,%9}, {%0,%1,%2,%3};"
        : "+f"(c[0]), "+f"(c[1]), "+f"(c[2]), "+f"(c[3])
        : "r"(a[0]), "r"(a[1]), "r"(a[2]), "r"(a[3]), "r"(b0), "r"(b1));
}

__device__ __forceinline__ void mma_bf16_16n8k16(float c[4], const uint32_t a[4],
                                                 const uint32_t b0, const uint32_t b1) {
    asm volatile(
        "mma.sync.aligned.m16n8k16.row.col.f32.bf16.bf16.f32 "
        "{%0,%1,%2,%3}, {%4,%5,%6,%7}, {%8,%9}, {%0,%1,%2,%3};"
        : "+f"(c[0]), "+f"(c[1]), "+f"(c[2]), "+f"(c[3])
        : "r"(a[0]), "r"(a[1]), "r"(a[2]), "r"(a[3]), "r"(b0), "r"(b1));
}

__device__ __forceinline__ void bf16_split2(float x, float y, uint32_t& hi, uint32_t& lo) {
    __nv_bfloat16 hx = __float2bfloat16(x);
    __nv_bfloat16 hy = __float2bfloat16(y);
    __nv_bfloat16 lx = __float2bfloat16(x - __bfloat162float(hx));
    __nv_bfloat16 ly = __float2bfloat16(y - __bfloat162float(hy));
    hi = (uint32_t)__bfloat16_as_ushort(hx) | ((uint32_t)__bfloat16_as_ushort(hy) << 16);
    lo = (uint32_t)__bfloat16_as_ushort(lx) | ((uint32_t)__bfloat16_as_ushort(ly) << 16);
}

#define LDSM_X4_T(r0, r1, r2, r3, addr) \
    asm volatile("ldmatrix.sync.aligned.m8n8.x4.trans.shared.b16 {%0,%1,%2,%3}, [%4];" \
                 : "=r"(r0), "=r"(r1), "=r"(r2), "=r"(r3) : "r"(addr))

// ============ tf32 round + k-permute (within each 16-group) ==============
__global__ __launch_bounds__(256) void cvt_perm(const float* __restrict__ in,
                                                float* __restrict__ out, int ngroups) {
    int i = blockIdx.x * 256 + threadIdx.x;
    if (i < ngroups) {
        const float4* ip = (const float4*)(in + (size_t)i * 16);
        float4 v0 = ip[0], v1 = ip[1], v2 = ip[2], v3 = ip[3];
        float4* op = (float4*)(out + (size_t)i * 16);
        op[0] = make_float4(tf32f(v0.x), tf32f(v1.x), tf32f(v2.x), tf32f(v3.x));
        op[1] = make_float4(tf32f(v0.y), tf32f(v1.y), tf32f(v2.y), tf32f(v3.y));
        op[2] = make_float4(tf32f(v0.z), tf32f(v1.z), tf32f(v2.z), tf32f(v3.z));
        op[3] = make_float4(tf32f(v0.w), tf32f(v1.w), tf32f(v2.w), tf32f(v3.w));
    }
}

// == TF32 mma GEMM: 256 thr, 8 warps (2Mx4N), warp 64x32, 3-stage cp.async ==
// C[M,N] = A[M,K] @ B[N,K]^T; A,B tf32-rounded + k-permuted.
// smem word(row, chunk) = row*32 + ((chunk ^ ((row&1)<<2)) << 2); no padding.
#define GK 2048
#define GN 2048
#define CSTAGE_F (2 * 128 * 32)              // 8192 floats = 32 KB / stage
#define GEMM_SMEM (3 * CSTAGE_F * 4)         // 98304 bytes

__device__ __forceinline__ uint32_t sw_word(int row, int chunk) {
    return (uint32_t)(row * 32 + ((chunk ^ ((row & 1) << 2)) << 2));
}

__global__ __launch_bounds__(256, 2) void gemm_perm(const float* __restrict__ A,
                                                    const float* __restrict__ Bm,
                                                    float* __restrict__ C) {
    extern __shared__ float sh[];
    const int tid = threadIdx.x;
    const int warp = tid >> 5;
    const int lane = tid & 31;
    const int g = lane >> 2;
    const int t = lane & 3;
    const int warp_m = warp & 1;      // 2 warps over M (64 rows each)
    const int warp_n = warp >> 1;     // 4 warps over N (32 cols each)
    const int m0 = blockIdx.y * 128;
    const int n0 = blockIdx.x * 128;
    const uint32_t sbase = smem_u32(sh);

    float acc[4][4][4];
#pragma unroll
    for (int mt = 0; mt < 4; mt++)
#pragma unroll
        for (int nt = 0; nt < 4; nt++)
#pragma unroll
            for (int j = 0; j < 4; j++) acc[mt][nt][j] = 0.f;

    const int NIT = GK / 32;    // 64

#define GEMM_ISSUE(stage, k0)                                                      \
    do {                                                                           \
        const uint32_t stb = sbase + (stage) * CSTAGE_F * 4;                       \
        _Pragma("unroll")                                                          \
        for (int i_ = 0; i_ < 8; i_++) {                                           \
            int idx = i_ * 256 + tid;                                              \
            int mat = idx >> 10;                                                   \
            int r = (idx >> 3) & 127;                                              \
            int ch = idx & 7;                                                      \
            const float* gp = (mat ? Bm + (size_t)(n0 + r) * GK                    \
                                   : A + (size_t)(m0 + r) * GK) + (k0) + ch * 4;   \
            uint32_t sp = stb + (mat * 128 * 32 + sw_word(r, ch)) * 4;             \
            asm volatile("cp.async.cg.shared.global [%0], [%1], 16;"               \
                         :: "r"(sp), "l"(gp));                                     \
        }                                                                          \
        asm volatile("cp.async.commit_group;" ::: "memory");                       \
    } while (0)

    GEMM_ISSUE(0, 0);
    GEMM_ISSUE(1, 32);

    for (int it = 0; it < NIT; it++) {
        if (it + 1 < NIT) asm volatile("cp.async.wait_group 1;" ::: "memory");
        else              asm volatile("cp.async.wait_group 0;" ::: "memory");
        __syncthreads();

        const float* As = sh + (it % 3) * CSTAGE_F;
        const float* Bs = As + 128 * 32;
#pragma unroll
        for (int ks2 = 0; ks2 < 2; ks2++) {
            const int c0 = 4 * ks2 + t;
            // B fragments: 4 n-tiles (32 cols)
            float4 bv[4];
#pragma unroll
            for (int nt = 0; nt < 4; nt++) {
                int cn = warp_n * 32 + nt * 8 + g;
                bv[nt] = *(const float4*)&Bs[sw_word(cn, c0)];
            }
#pragma unroll
            for (int mt = 0; mt < 4; mt++) {
                int r0 = warp_m * 64 + mt * 16 + g;
                float4 alo = *(const float4*)&As[sw_word(r0, c0)];
                float4 ahi = *(const float4*)&As[sw_word(r0 + 8, c0)];
                uint32_t af0[4] = {__float_as_uint(alo.x), __float_as_uint(ahi.x),
                                   __float_as_uint(alo.y), __float_as_uint(ahi.y)};
                uint32_t af1[4] = {__float_as_uint(alo.z), __float_as_uint(ahi.z),
                                   __float_as_uint(alo.w), __float_as_uint(ahi.w)};
#pragma unroll
                for (int nt = 0; nt < 4; nt++) {
                    mma_tf32_16n8k8(acc[mt][nt], af0,
                                    __float_as_uint(bv[nt].x), __float_as_uint(bv[nt].y));
                    mma_tf32_16n8k8(acc[mt][nt], af1,
                                    __float_as_uint(bv[nt].z), __float_as_uint(bv[nt].w));
                }
            }
        }

        if (it + 2 < NIT) GEMM_ISSUE((it + 2) % 3, (it + 2) * 32);
    }

    // ---- epilogue ----
#pragma unroll
    for (int mt = 0; mt < 4; mt++) {
        int row = m0 + warp_m * 64 + mt * 16 + g;
#pragma unroll
        for (int nt = 0; nt < 4; nt++) {
            int col = n0 + warp_n * 32 + nt * 8 + 2 * t;
            *(float2*)(C + (size_t)row * GN + col) = make_float2(acc[mt][nt][0], acc[mt][nt][1]);
            *(float2*)(C + (size_t)(row + 8) * GN + col) = make_float2(acc[mt][nt][2], acc[mt][nt][3]);
        }
    }
}

// ============================== RoPE ====================================
__global__ __launch_bounds__(256) void rope_kernel(float* __restrict__ Q,
                                                   float* __restrict__ Kt) {
    int idx = blockIdx.x * 256 + threadIdx.x;
    int d = idx & 63;
    int h = (idx >> 6) & (NH - 1);
    int n = idx >> 10;
    int t = n & (T_ - 1);
    size_t base = (size_t)n * DM + h * HD;

    const float LOG2_10000 = 13.287712379549449f;
    float inv = exp2f(-(float)(2 * d) * (LOG2_10000 / 128.0f));
    float ang = (float)t * inv;
    float s, c;
    sincosf(ang, &s, &c);

    float q1 = Q[base + d], q2 = Q[base + d + 64];
    Q[base + d]      = q1 * c - q2 * s;
    Q[base + d + 64] = q2 * c + q1 * s;
    float k1 = Kt[base + d], k2 = Kt[base + d + 64];
    Kt[base + d]      = k1 * c - k2 * s;
    Kt[base + d + 64] = k2 * c + k1 * s;
}

// ============ Flash attention, bf16x3 split on m16n8k16 ==================
#define QS 136
#define KS 136
#define VS 136
#define PS 72
#define OFF_QHI 0
#define OFF_QLO (128 * QS)
#define OFF_KHI (OFF_QLO + 128 * QS)
#define OFF_KLO (OFF_KHI + 64 * KS)
#define OFF_VHI (OFF_KLO + 64 * KS)
#define OFF_VLO (OFF_VHI + 64 * VS)
#define OFF_PHI (OFF_VLO + 64 * VS)
#define OFF_PLO (OFF_PHI + 128 * PS)
#define FLASH_SMEM ((OFF_PLO + 128 * PS) * 2)

__global__ __launch_bounds__(256) void flash_bf16(const float* __restrict__ Qg,
                                                  const float* __restrict__ Kg,
                                                  const float* __restrict__ Vg,
                                                  float* __restrict__ Og) {
    extern __shared__ unsigned short su[];
    unsigned short* Qhi = su + OFF_QHI;
    unsigned short* Qlo = su + OFF_QLO;
    unsigned short* Khi = su + OFF_KHI;
    unsigned short* Klo = su + OFF_KLO;
    unsigned short* Vhi = su + OFF_VHI;
    unsigned short* Vlo = su + OFF_VLO;
    unsigned short* Phi = su + OFF_PHI;
    unsigned short* Plo = su + OFF_PLO;

    const int qb = blockIdx.x;
    const int bh = blockIdx.y;
    const int b = bh >> 4, h = bh & 15;
    const int q0 = qb * 128;
    const int tid = threadIdx.x;
    const int warp = tid >> 5;
    const int lane = tid & 31;
    const int g = lane >> 2;
    const int t = lane & 3;
    const float NEG_INF = __int_as_float(0xff800000);
    const float scale = 0.08838834764831845f;

    const int lq = lane >> 3;
    const int lsl = lane & 7;
    const int srow_off = (lq & 1) * 8 + lsl;
    const int dcol_off = (lq >> 1) * 8;
    const uint32_t vhi_base = smem_u32(Vhi);
    const uint32_t vlo_base = smem_u32(Vlo);

    const float* Qp = Qg + (size_t)(b * T_ + q0) * DM + h * HD;
#pragma unroll
    for (int i = 0; i < 16; i++) {
        int idx = i * 256 + tid;
        int r = idx >> 5;
        int c4 = (idx & 31) * 4;
        float4 v = *(const float4*)(Qp + (size_t)r * DM + c4);
        uint32_t h0, l0, h1, l1;
        bf16_split2(v.x * scale, v.y * scale, h0, l0);
        bf16_split2(v.z * scale, v.w * scale, h1, l1);
        *(uint2*)&Qhi[r * QS + c4] = make_uint2(h0, h1);
        *(uint2*)&Qlo[r * QS + c4] = make_uint2(l0, l1);
    }

    float accO[16][4];
#pragma unroll
    for (int nt = 0; nt < 16; nt++)
#pragma unroll
        for (int j = 0; j < 4; j++) accO[nt][j] = 0.f;
    float m0 = -1e30f, m1 = -1e30f, l0s = 0.f, l1s = 0.f;

    const int rowA = warp * 16 + g;
    const int ntiles = 2 * qb + 2;

    for (int kb = 0; kb < ntiles; kb++) {
        const int k0 = kb * 64;
        __syncthreads();
        const float* Kp = Kg + (size_t)(b * T_ + k0) * DM + h * HD;
        const float* Vp = Vg + (size_t)(b * T_ + k0) * DM + h * HD;
#pragma unroll
        for (int i = 0; i < 8; i++) {
            int idx = i * 256 + tid;
            int r = idx >> 5;
            int c4 = (idx & 31) * 4;
            float4 kv = *(const float4*)(Kp + (size_t)r * DM + c4);
            uint32_t h0, lo0, h1, lo1;
            bf16_split2(kv.x, kv.y, h0, lo0);
            bf16_split2(kv.z, kv.w, h1, lo1);
            *(uint2*)&Khi[r * KS + c4] = make_uint2(h0, h1);
            *(uint2*)&Klo[r * KS + c4] = make_uint2(lo0, lo1);
            float4 vv = *(const float4*)(Vp + (size_t)r * DM + c4);
            bf16_split2(vv.x, vv.y, h0, lo0);
            bf16_split2(vv.z, vv.w, h1, lo1);
            *(uint2*)&Vhi[r * VS + c4] = make_uint2(h0, h1);
            *(uint2*)&Vlo[r * VS + c4] = make_uint2(lo0, lo1);
        }
        __syncthreads();

        float accS[8][4];
#pragma unroll
        for (int nt = 0; nt < 8; nt++)
#pragma unroll
            for (int j = 0; j < 4; j++) accS[nt][j] = 0.f;

#pragma unroll
        for (int ks = 0; ks < 8; ks++) {
            const int k16 = ks * 16;
            uint32_t ah[4], al[4];
            ah[0] = *(uint32_t*)&Qhi[rowA * QS + k16 + 2 * t];
            ah[1] = *(uint32_t*)&Qhi[(rowA + 8) * QS + k16 + 2 * t];
            ah[2] = *(uint32_t*)&Qhi[rowA * QS + k16 + 8 + 2 * t];
            ah[3] = *(uint32_t*)&Qhi[(rowA + 8) * QS + k16 + 8 + 2 * t];
            al[0] = *(uint32_t*)&Qlo[rowA * QS + k16 + 2 * t];
            al[1] = *(uint32_t*)&Qlo[(rowA + 8) * QS + k16 + 2 * t];
            al[2] = *(uint32_t*)&Qlo[rowA * QS + k16 + 8 + 2 * t];
            al[3] = *(uint32_t*)&Qlo[(rowA + 8) * QS + k16 + 8 + 2 * t];
#pragma unroll
            for (int nt = 0; nt < 8; nt++) {
                int krow = nt * 8 + g;
                uint32_t bh0 = *(uint32_t*)&Khi[krow * KS + k16 + 2 * t];
                uint32_t bh1 = *(uint32_t*)&Khi[krow * KS + k16 + 8 + 2 * t];
                uint32_t bl0 = *(uint32_t*)&Klo[krow * KS + k16 + 2 * t];
                uint32_t bl1 = *(uint32_t*)&Klo[krow * KS + k16 + 8 + 2 * t];
                mma_bf16_16n8k16(accS[nt], ah, bh0, bh1);
                mma_bf16_16n8k16(accS[nt], ah, bl0, bl1);
                mma_bf16_16n8k16(accS[nt], al, bh0, bh1);
            }
        }

        const int rowg0 = q0 + rowA;
        const int rowg1 = rowg0 + 8;
        const bool chk = (k0 + 63 > q0 + warp * 16);
        float mx0 = NEG_INF, mx1 = NEG_INF;
#pragma unroll
        for (int nt = 0; nt < 8; nt++) {
#pragma unroll
            for (int j = 0; j < 2; j++) {
                int col = k0 + nt * 8 + 2 * t + j;
                float s0 = accS[nt][j];
                float s1 = accS[nt][2 + j];
                if (chk) {
                    if (col > rowg0) s0 = NEG_INF;
                    if (col > rowg1) s1 = NEG_INF;
                }
                accS[nt][j] = s0;
                accS[nt][2 + j] = s1;
                mx0 = fmaxf(mx0, s0);
                mx1 = fmaxf(mx1, s1);
            }
        }
        mx0 = fmaxf(mx0, __shfl_xor_sync(0xffffffffu, mx0, 1));
        mx0 = fmaxf(mx0, __shfl_xor_sync(0xffffffffu, mx0, 2));
        mx1 = fmaxf(mx1, __shfl_xor_sync(0xffffffffu, mx1, 1));
        mx1 = fmaxf(mx1, __shfl_xor_sync(0xffffffffu, mx1, 2));

        float mn0 = fmaxf(m0, mx0), mn1 = fmaxf(m1, mx1);
        float al0 = __expf(m0 - mn0), al1 = __expf(m1 - mn1);
        float rs0 = 0.f, rs1 = 0.f;
#pragma unroll
        for (int nt = 0; nt < 8; nt++) {
            float p00 = __expf(accS[nt][0] - mn0);
            float p01 = __expf(accS[nt][1] - mn0);
            float p10 = __expf(accS[nt][2] - mn1);
            float p11 = __expf(accS[nt][3] - mn1);
            rs0 += p00 + p01;
            rs1 += p10 + p11;
            uint32_t ph, pl;
            bf16_split2(p00, p01, ph, pl);
            *(uint32_t*)&Phi[rowA * PS + nt * 8 + 2 * t] = ph;
            *(uint32_t*)&Plo[rowA * PS + nt * 8 + 2 * t] = pl;
            bf16_split2(p10, p11, ph, pl);
            *(uint32_t*)&Phi[(rowA + 8) * PS + nt * 8 + 2 * t] = ph;
            *(uint32_t*)&Plo[(rowA + 8) * PS + nt * 8 + 2 * t] = pl;
        }
        rs0 += __shfl_xor_sync(0xffffffffu, rs0, 1);
        rs0 += __shfl_xor_sync(0xffffffffu, rs0, 2);
        rs1 += __shfl_xor_sync(0xffffffffu, rs1, 1);
        rs1 += __shfl_xor_sync(0xffffffffu, rs1, 2);
        l0s = l0s * al0 + rs0;
        l1s = l1s * al1 + rs1;
        m0 = mn0;
        m1 = mn1;
#pragma unroll
        for (int nt = 0; nt < 16; nt++) {
            accO[nt][0] *= al0; accO[nt][1] *= al0;
            accO[nt][2] *= al1; accO[nt][3] *= al1;
        }
        __syncwarp();

#pragma unroll
        for (int si = 0; si < 4; si++) {
            const int s16 = si * 16;
            uint32_t pah[4], pal[4];
            pah[0] = *(uint32_t*)&Phi[rowA * PS + s16 + 2 * t];
            pah[1] = *(uint32_t*)&Phi[(rowA + 8) * PS + s16 + 2 * t];
            pah[2] = *(uint32_t*)&Phi[rowA * PS + s16 + 8 + 2 * t];
            pah[3] = *(uint32_t*)&Phi[(rowA + 8) * PS + s16 + 8 + 2 * t];
            pal[0] = *(uint32_t*)&Plo[rowA * PS + s16 + 2 * t];
            pal[1] = *(uint32_t*)&Plo[(rowA + 8) * PS + s16 + 2 * t];
            pal[2] = *(uint32_t*)&Plo[rowA * PS + s16 + 8 + 2 * t];
            pal[3] = *(uint32_t*)&Plo[(rowA + 8) * PS + s16 + 8 + 2 * t];
#pragma unroll
            for (int pr = 0; pr < 8; pr++) {
                uint32_t off = (uint32_t)((s16 + srow_off) * VS + pr * 16 + dcol_off) * 2;
                uint32_t vh0, vh1, vh2, vh3, vl0, vl1, vl2, vl3;
                LDSM_X4_T(vh0, vh1, vh2, vh3, vhi_base + off);
                LDSM_X4_T(vl0, vl1, vl2, vl3, vlo_base + off);
                const int nt0 = 2 * pr, nt1 = 2 * pr + 1;
                mma_bf16_16n8k16(accO[nt0], pah, vh0, vh1);
                mma_bf16_16n8k16(accO[nt0], pah, vl0, vl1);
                mma_bf16_16n8k16(accO[nt0], pal, vh0, vh1);
                mma_bf16_16n8k16(accO[nt1], pah, vh2, vh3);
                mma_bf16_16n8k16(accO[nt1], pah, vl2, vl3);
                mma_bf16_16n8k16(accO[nt1], pal, vh2, vh3);
            }
        }
    }

    float inv0 = 1.f / l0s, inv1 = 1.f / l1s;
    float* Op = Og + (size_t)(b * T_ + q0 + rowA) * DM + h * HD;
    float* Op8 = Op + (size_t)8 * DM;
#pragma unroll
    for (int nt = 0; nt < 16; nt++) {
        int col = nt * 8 + 2 * t;
        *(float2*)(Op + col)  = make_float2(tf32f(accO[nt][0] * inv0), tf32f(accO[nt][1] * inv0));
        *(float2*)(Op8 + col) = make_float2(tf32f(accO[nt][2] * inv1), tf32f(accO[nt][3] * inv1));
    }
}

// ============================ launcher ==================================
extern "C" void kernel_launch(void* const* d_in, const int* in_sizes, int n_in,
                              void* d_out, int out_size) {
    const float* x  = (const float*)d_in[0];
    const float* Wq = (const float*)d_in[1];
    const float* Wk = (const float*)d_in[2];
    const float* Wv = (const float*)d_in[3];
    const float* Wo = (const float*)d_in[4];
    float* out = (float*)d_out;

    float *pQ, *pK, *pV, *pA, *pXc, *pWc;
    cudaGetSymbolAddress((void**)&pQ, g_Q);
    cudaGetSymbolAddress((void**)&pK, g_K);
    cudaGetSymbolAddress((void**)&pV, g_V);
    cudaGetSymbolAddress((void**)&pA, g_A);
    cudaGetSymbolAddress((void**)&pXc, g_xc);
    cudaGetSymbolAddress((void**)&pWc, g_Wc);
    float* pWqc = pWc;
    float* pWkc = pWc + (size_t)DM * DM;
    float* pWvc = pWc + 2 * (size_t)DM * DM;
    float* pWoc = pWc + 3 * (size_t)DM * DM;

    cudaFuncSetAttribute(gemm_perm, cudaFuncAttributeMaxDynamicSharedMemorySize, GEMM_SMEM);
    cudaFuncSetAttribute(flash_bf16, cudaFuncAttributeMaxDynamicSharedMemorySize, FLASH_SMEM);

    const int NXG = (NROWS * DM) / 16;     // 524288 groups
    const int NWG = (DM * DM) / 16;        // 262144 groups
    dim3 ggrid(DM / 128, NROWS / 128);     // (16, 32)

    // Order chosen so the profiler's captured launch (4th) is gemm_perm.
    cvt_perm<<<NXG / 256, 256>>>(x, pXc, NXG);          // 1
    cvt_perm<<<NWG / 256, 256>>>(Wq, pWqc, NWG);        // 2
    cvt_perm<<<NWG / 256, 256>>>(Wk, pWkc, NWG);        // 3
    gemm_perm<<<ggrid, 256, GEMM_SMEM>>>(pXc, pWqc, pQ);   // 4  <-- profiled
    cvt_perm<<<NWG / 256, 256>>>(Wv, pWvc, NWG);        // 5
    gemm_perm<<<ggrid, 256, GEMM_SMEM>>>(pXc, pWkc, pK);   // 6
    gemm_perm<<<ggrid, 256, GEMM_SMEM>>>(pXc, pWvc, pV);   // 7
    cvt_perm<<<NWG / 256, 256>>>(Wo, pWoc, NWG);        // 8

    rope_kernel<<<(NROWS * NH * 64) / 256, 256>>>(pQ, pK);

    dim3 fgrid(T_ / 128, B_ * NH);         // (16, 32)
    flash_bf16<<<fgrid, 256, FLASH_SMEM>>>(pQ, pK, pV, pA);

    cvt_perm<<<NXG / 256, 256>>>(pA, pA, NXG);
    gemm_perm<<<ggrid, 256, GEMM_SMEM>>>(pA, pWoc, out);
}

// round 11
// speedup vs baseline: 1.1255x; 1.1255x over previous
#include <cuda_runtime.h>
#include <cuda_bf16.h>
#include <math.h>
#include <stdint.h>

#define B_  2
#define T_  2048
#define DM  2048
#define NH  16
#define HD  128
#define NROWS (B_ * T_)   // 4096

// ---------------- scratch (no runtime allocation allowed) ----------------
__device__ float g_Q[(size_t)NROWS * DM];
__device__ float g_K[(size_t)NROWS * DM];
__device__ float g_V[(size_t)NROWS * DM];
__device__ float g_A[(size_t)NROWS * DM];
__device__ float g_xc[(size_t)NROWS * DM];          // tf32-rounded, k-permuted x
__device__ float g_Wc[4][(size_t)DM * DM];          // tf32-rounded, k-permuted W
// pre-split bf16 planes for attention
__device__ unsigned short g_Qhi[(size_t)NROWS * DM];
__device__ unsigned short g_Qlo[(size_t)NROWS * DM];
__device__ unsigned short g_Khi[(size_t)NROWS * DM];
__device__ unsigned short g_Klo[(size_t)NROWS * DM];
__device__ unsigned short g_Vhi[(size_t)NROWS * DM];
__device__ unsigned short g_Vlo[(size_t)NROWS * DM];

__device__ __forceinline__ uint32_t f2tf32(float x) {
    uint32_t r;
    asm("cvt.rna.tf32.f32 %0, %1;" : "=r"(r) : "f"(x));
    return r;
}
__device__ __forceinline__ float tf32f(float x) { return __uint_as_float(f2tf32(x)); }

__device__ __forceinline__ uint32_t smem_u32(const void* p) {
    uint32_t a;
    asm("{ .reg .u64 t; cvta.to.shared.u64 t, %1; cvt.u32.u64 %0, t; }" : "=r"(a) : "l"(p));
    return a;
}

__device__ __forceinline__ void mma_tf32_16n8k8(float c[4], const uint32_t a[4],
                                                const uint32_t b0, const uint32_t b1) {
    asm volatile(
        "mma.sync.aligned.m16n8k8.row.col.f32.tf32.tf32.f32 "
        "{%0,%1,%2,%3}, {%4,%5,%6,%7}, {%8,%9}, {%0,%1,%2,%3};"
        : "+f"(c[0]), "+f"(c[1]), "+f"(c[2]), "+f"(c[3])
        : "r"(a[0]), "r"(a[1]), "r"(a[2]), "r"(a[3]), "r"(b0), "r"(b1));
}

__device__ __forceinline__ void mma_bf16_16n8k16(float c[4], const uint32_t a[4],
                                                 const uint32_t b0, const uint32_t b1) {
    asm volatile(
        "mma.sync.aligned.m16n8k16.row.col.f32.bf16.bf16.f32 "
        "{%0,%1,%2,%3}, {%4,%5,%6,%7}, {%8,%9}, {%0,%1,%2,%3};"
        : "+f"(c[0]), "+f"(c[1]), "+f"(c[2]), "+f"(c[3])
        : "r"(a[0]), "r"(a[1]), "r"(a[2]), "r"(a[3]), "r"(b0), "r"(b1));
}

__device__ __forceinline__ void bf16_split2(float x, float y, uint32_t& hi, uint32_t& lo) {
    __nv_bfloat16 hx = __float2bfloat16(x);
    __nv_bfloat16 hy = __float2bfloat16(y);
    __nv_bfloat16 lx = __float2bfloat16(x - __bfloat162float(hx));
    __nv_bfloat16 ly = __float2bfloat16(y - __bfloat162float(hy));
    hi = (uint32_t)__bfloat16_as_ushort(hx) | ((uint32_t)__bfloat16_as_ushort(hy) << 16);
    lo = (uint32_t)__bfloat16_as_ushort(lx) | ((uint32_t)__bfloat16_as_ushort(ly) << 16);
}

#define LDSM_X4_T(r0, r1, r2, r3, addr) \
    asm volatile("ldmatrix.sync.aligned.m8n8.x4.trans.shared.b16 {%0,%1,%2,%3}, [%4];" \
                 : "=r"(r0), "=r"(r1), "=r"(r2), "=r"(r3) : "r"(addr))

#define CP_ASYNC16(sp, gp) \
    asm volatile("cp.async.cg.shared.global [%0], [%1], 16;" :: "r"(sp), "l"(gp))

// ============ tf32 round + k-permute (within each 16-group) ==============
__global__ __launch_bounds__(256) void cvt_perm(const float* __restrict__ in,
                                                float* __restrict__ out, int ngroups) {
    int i = blockIdx.x * 256 + threadIdx.x;
    if (i < ngroups) {
        const float4* ip = (const float4*)(in + (size_t)i * 16);
        float4 v0 = ip[0], v1 = ip[1], v2 = ip[2], v3 = ip[3];
        float4* op = (float4*)(out + (size_t)i * 16);
        op[0] = make_float4(tf32f(v0.x), tf32f(v1.x), tf32f(v2.x), tf32f(v3.x));
        op[1] = make_float4(tf32f(v0.y), tf32f(v1.y), tf32f(v2.y), tf32f(v3.y));
        op[2] = make_float4(tf32f(v0.z), tf32f(v1.z), tf32f(v2.z), tf32f(v3.z));
        op[3] = make_float4(tf32f(v0.w), tf32f(v1.w), tf32f(v2.w), tf32f(v3.w));
    }
}

// ============ global bf16 hi/lo pre-split of Q (scaled), K, V =============
__global__ __launch_bounds__(256) void split_qkv(const float* __restrict__ Q,
                                                 const float* __restrict__ K,
                                                 const float* __restrict__ V,
                                                 unsigned short* __restrict__ Qhi_g,
                                                 unsigned short* __restrict__ Qlo_g,
                                                 unsigned short* __restrict__ Khi_g,
                                                 unsigned short* __restrict__ Klo_g,
                                                 unsigned short* __restrict__ Vhi_g,
                                                 unsigned short* __restrict__ Vlo_g) {
    const float scale = 0.08838834764831845f;
    int i = blockIdx.x * 256 + threadIdx.x;          // float4 index
    float4 q = ((const float4*)Q)[i];
    uint32_t h0, l0, h1, l1;
    bf16_split2(q.x * scale, q.y * scale, h0, l0);
    bf16_split2(q.z * scale, q.w * scale, h1, l1);
    ((uint2*)Qhi_g)[i] = make_uint2(h0, h1);
    ((uint2*)Qlo_g)[i] = make_uint2(l0, l1);
    float4 k = ((const float4*)K)[i];
    bf16_split2(k.x, k.y, h0, l0);
    bf16_split2(k.z, k.w, h1, l1);
    ((uint2*)Khi_g)[i] = make_uint2(h0, h1);
    ((uint2*)Klo_g)[i] = make_uint2(l0, l1);
    float4 v = ((const float4*)V)[i];
    bf16_split2(v.x, v.y, h0, l0);
    bf16_split2(v.z, v.w, h1, l1);
    ((uint2*)Vhi_g)[i] = make_uint2(h0, h1);
    ((uint2*)Vlo_g)[i] = make_uint2(l0, l1);
}

// == TF32 mma GEMM (R9 config): 128 thr, 4 warps (2x2), warp 64x64, 3-stage ==
#define GK 2048
#define GN 2048
#define CSTAGE_F (2 * 128 * 32)              // 8192 floats = 32 KB / stage
#define GEMM_SMEM (3 * CSTAGE_F * 4)         // 98304 bytes

__device__ __forceinline__ uint32_t sw_word(int row, int chunk) {
    return (uint32_t)(row * 32 + ((chunk ^ ((row & 1) << 2)) << 2));
}

__global__ __launch_bounds__(128) void gemm_perm(const float* __restrict__ A,
                                                 const float* __restrict__ Bm,
                                                 float* __restrict__ C) {
    extern __shared__ float sh[];
    const int tid = threadIdx.x;
    const int warp = tid >> 5;
    const int lane = tid & 31;
    const int g = lane >> 2;
    const int t = lane & 3;
    const int warp_m = warp & 1;
    const int warp_n = warp >> 1;
    const int m0 = blockIdx.y * 128;
    const int n0 = blockIdx.x * 128;
    const uint32_t sbase = smem_u32(sh);

    float acc[4][8][4];
#pragma unroll
    for (int mt = 0; mt < 4; mt++)
#pragma unroll
        for (int nt = 0; nt < 8; nt++)
#pragma unroll
            for (int j = 0; j < 4; j++) acc[mt][nt][j] = 0.f;

    const int NIT = GK / 32;    // 64

#define GEMM_ISSUE(stage, k0)                                                      \
    do {                                                                           \
        const uint32_t stb = sbase + (stage) * CSTAGE_F * 4;                       \
        _Pragma("unroll")                                                          \
        for (int i_ = 0; i_ < 16; i_++) {                                          \
            int idx = i_ * 128 + tid;                                              \
            int mat = idx >> 10;                                                   \
            int r = (idx >> 3) & 127;                                              \
            int ch = idx & 7;                                                      \
            const float* gp = (mat ? Bm + (size_t)(n0 + r) * GK                    \
                                   : A + (size_t)(m0 + r) * GK) + (k0) + ch * 4;   \
            uint32_t sp = stb + (mat * 128 * 32 + sw_word(r, ch)) * 4;             \
            CP_ASYNC16(sp, gp);                                                    \
        }                                                                          \
        asm volatile("cp.async.commit_group;" ::: "memory");                       \
    } while (0)

    GEMM_ISSUE(0, 0);
    GEMM_ISSUE(1, 32);

    for (int it = 0; it < NIT; it++) {
        if (it + 1 < NIT) asm volatile("cp.async.wait_group 1;" ::: "memory");
        else              asm volatile("cp.async.wait_group 0;" ::: "memory");
        __syncthreads();

        const float* As = sh + (it % 3) * CSTAGE_F;
        const float* Bs = As + 128 * 32;
#pragma unroll
        for (int ks2 = 0; ks2 < 2; ks2++) {
            const int c0 = 4 * ks2 + t;
            float4 alo[4], ahi[4];
#pragma unroll
            for (int mt = 0; mt < 4; mt++) {
                int r0 = warp_m * 64 + mt * 16 + g;
                alo[mt] = *(const float4*)&As[sw_word(r0, c0)];
                ahi[mt] = *(const float4*)&As[sw_word(r0 + 8, c0)];
            }
            float4 bv[8];
#pragma unroll
            for (int nt = 0; nt < 8; nt++) {
                int cn = warp_n * 64 + nt * 8 + g;
                bv[nt] = *(const float4*)&Bs[sw_word(cn, c0)];
            }
#pragma unroll
            for (int mt = 0; mt < 4; mt++) {
                uint32_t af[4] = {__float_as_uint(alo[mt].x), __float_as_uint(ahi[mt].x),
                                  __float_as_uint(alo[mt].y), __float_as_uint(ahi[mt].y)};
#pragma unroll
                for (int nt = 0; nt < 8; nt++)
                    mma_tf32_16n8k8(acc[mt][nt], af,
                                    __float_as_uint(bv[nt].x), __float_as_uint(bv[nt].y));
            }
#pragma unroll
            for (int mt = 0; mt < 4; mt++) {
                uint32_t af[4] = {__float_as_uint(alo[mt].z), __float_as_uint(ahi[mt].z),
                                  __float_as_uint(alo[mt].w), __float_as_uint(ahi[mt].w)};
#pragma unroll
                for (int nt = 0; nt < 8; nt++)
                    mma_tf32_16n8k8(acc[mt][nt], af,
                                    __float_as_uint(bv[nt].z), __float_as_uint(bv[nt].w));
            }
        }

        if (it + 2 < NIT) GEMM_ISSUE((it + 2) % 3, (it + 2) * 32);
    }

#pragma unroll
    for (int mt = 0; mt < 4; mt++) {
        int row = m0 + warp_m * 64 + mt * 16 + g;
#pragma unroll
        for (int nt = 0; nt < 8; nt++) {
            int col = n0 + warp_n * 64 + nt * 8 + 2 * t;
            *(float2*)(C + (size_t)row * GN + col) = make_float2(acc[mt][nt][0], acc[mt][nt][1]);
            *(float2*)(C + (size_t)(row + 8) * GN + col) = make_float2(acc[mt][nt][2], acc[mt][nt][3]);
        }
    }
}

// ============================== RoPE ====================================
__global__ __launch_bounds__(256) void rope_kernel(float* __restrict__ Q,
                                                   float* __restrict__ Kt) {
    int idx = blockIdx.x * 256 + threadIdx.x;
    int d = idx & 63;
    int h = (idx >> 6) & (NH - 1);
    int n = idx >> 10;
    int t = n & (T_ - 1);
    size_t base = (size_t)n * DM + h * HD;

    const float LOG2_10000 = 13.287712379549449f;
    float inv = exp2f(-(float)(2 * d) * (LOG2_10000 / 128.0f));
    float ang = (float)t * inv;
    float s, c;
    sincosf(ang, &s, &c);

    float q1 = Q[base + d], q2 = Q[base + d + 64];
    Q[base + d]      = q1 * c - q2 * s;
    Q[base + d + 64] = q2 * c + q1 * s;
    float k1 = Kt[base + d], k2 = Kt[base + d + 64];
    Kt[base + d]      = k1 * c - k2 * s;
    Kt[base + d + 64] = k2 * c + k1 * s;
}

// ===== Flash attention, bf16x3 m16n8k16, pre-split planes + cp.async =====
#define QS 136
#define KS 136
#define VS 136
#define PS 72
#define OFF_QHI 0
#define OFF_QLO (128 * QS)
#define OFF_KHI (OFF_QLO + 128 * QS)
#define OFF_KLO (OFF_KHI + 64 * KS)
#define OFF_VHI (OFF_KLO + 64 * KS)
#define OFF_VLO (OFF_VHI + 64 * VS)
#define OFF_PHI (OFF_VLO + 64 * VS)
#define OFF_PLO (OFF_PHI + 128 * PS)
#define FLASH_SMEM ((OFF_PLO + 128 * PS) * 2)

__global__ __launch_bounds__(256) void flash_bf16(const unsigned short* __restrict__ Qhi_g,
                                                  const unsigned short* __restrict__ Qlo_g,
                                                  const unsigned short* __restrict__ Khi_g,
                                                  const unsigned short* __restrict__ Klo_g,
                                                  const unsigned short* __restrict__ Vhi_g,
                                                  const unsigned short* __restrict__ Vlo_g,
                                                  float* __restrict__ Og) {
    extern __shared__ unsigned short su[];
    unsigned short* Qhi = su + OFF_QHI;
    unsigned short* Qlo = su + OFF_QLO;
    unsigned short* Khi = su + OFF_KHI;
    unsigned short* Klo = su + OFF_KLO;
    unsigned short* Vhi = su + OFF_VHI;
    unsigned short* Vlo = su + OFF_VLO;
    unsigned short* Phi = su + OFF_PHI;
    unsigned short* Plo = su + OFF_PLO;

    const int qb = blockIdx.x;
    const int bh = blockIdx.y;
    const int b = bh >> 4, h = bh & 15;
    const int q0 = qb * 128;
    const int tid = threadIdx.x;
    const int warp = tid >> 5;
    const int lane = tid & 31;
    const int g = lane >> 2;
    const int t = lane & 3;
    const float NEG_INF = __int_as_float(0xff800000);

    const int lq = lane >> 3;
    const int lsl = lane & 7;
    const int srow_off = (lq & 1) * 8 + lsl;
    const int dcol_off = (lq >> 1) * 8;
    const uint32_t sbase = smem_u32(su);
    const uint32_t vhi_base = sbase + OFF_VHI * 2;
    const uint32_t vlo_base = sbase + OFF_VLO * 2;

    // ---- prologue: async-load Q hi/lo tile (128 x 128 bf16 per plane) ----
    {
        const size_t gbase = (size_t)(b * T_ + q0) * DM + h * HD;
#pragma unroll
        for (int i = 0; i < 8; i++) {
            int idx = i * 256 + tid;        // 0..2047 = 128 rows x 16 chunks
            int r = idx >> 4;
            int ch = idx & 15;
            size_t go = gbase + (size_t)r * DM + ch * 8;
            uint32_t so = (uint32_t)(r * QS + ch * 8) * 2;
            CP_ASYNC16(sbase + OFF_QHI * 2 + so, Qhi_g + go);
            CP_ASYNC16(sbase + OFF_QLO * 2 + so, Qlo_g + go);
        }
    }

    float accO[16][4];
#pragma unroll
    for (int nt = 0; nt < 16; nt++)
#pragma unroll
        for (int j = 0; j < 4; j++) accO[nt][j] = 0.f;
    float m0 = -1e30f, m1 = -1e30f, l0s = 0.f, l1s = 0.f;

    const int rowA = warp * 16 + g;
    const int ntiles = 2 * qb + 2;

    for (int kb = 0; kb < ntiles; kb++) {
        const int k0 = kb * 64;
        __syncthreads();    // previous compute done reading K/V smem
        // ---- async-load K/V hi/lo tiles (64 x 128 bf16 each plane) ----
        {
            const size_t gbase = (size_t)(b * T_ + k0) * DM + h * HD;
#pragma unroll
            for (int i = 0; i < 4; i++) {
                int idx = i * 256 + tid;    // 0..1023 = 64 rows x 16 chunks
                int r = idx >> 4;
                int ch = idx & 15;
                size_t go = gbase + (size_t)r * DM + ch * 8;
                uint32_t so = (uint32_t)(r * KS + ch * 8) * 2;
                CP_ASYNC16(sbase + OFF_KHI * 2 + so, Khi_g + go);
                CP_ASYNC16(sbase + OFF_KLO * 2 + so, Klo_g + go);
                CP_ASYNC16(sbase + OFF_VHI * 2 + so, Vhi_g + go);
                CP_ASYNC16(sbase + OFF_VLO * 2 + so, Vlo_g + go);
            }
        }
        asm volatile("cp.async.commit_group;" ::: "memory");
        asm volatile("cp.async.wait_group 0;" ::: "memory");
        __syncthreads();

        float accS[8][4];
#pragma unroll
        for (int nt = 0; nt < 8; nt++)
#pragma unroll
            for (int j = 0; j < 4; j++) accS[nt][j] = 0.f;

#pragma unroll
        for (int ks = 0; ks < 8; ks++) {
            const int k16 = ks * 16;
            uint32_t ah[4], al[4];
            ah[0] = *(uint32_t*)&Qhi[rowA * QS + k16 + 2 * t];
            ah[1] = *(uint32_t*)&Qhi[(rowA + 8) * QS + k16 + 2 * t];
            ah[2] = *(uint32_t*)&Qhi[rowA * QS + k16 + 8 + 2 * t];
            ah[3] = *(uint32_t*)&Qhi[(rowA + 8) * QS + k16 + 8 + 2 * t];
            al[0] = *(uint32_t*)&Qlo[rowA * QS + k16 + 2 * t];
            al[1] = *(uint32_t*)&Qlo[(rowA + 8) * QS + k16 + 2 * t];
            al[2] = *(uint32_t*)&Qlo[rowA * QS + k16 + 8 + 2 * t];
            al[3] = *(uint32_t*)&Qlo[(rowA + 8) * QS + k16 + 8 + 2 * t];
#pragma unroll
            for (int nt = 0; nt < 8; nt++) {
                int krow = nt * 8 + g;
                uint32_t bh0 = *(uint32_t*)&Khi[krow * KS + k16 + 2 * t];
                uint32_t bh1 = *(uint32_t*)&Khi[krow * KS + k16 + 8 + 2 * t];
                uint32_t bl0 = *(uint32_t*)&Klo[krow * KS + k16 + 2 * t];
                uint32_t bl1 = *(uint32_t*)&Klo[krow * KS + k16 + 8 + 2 * t];
                mma_bf16_16n8k16(accS[nt], ah, bh0, bh1);
                mma_bf16_16n8k16(accS[nt], ah, bl0, bl1);
                mma_bf16_16n8k16(accS[nt], al, bh0, bh1);
            }
        }

        const int rowg0 = q0 + rowA;
        const int rowg1 = rowg0 + 8;
        const bool chk = (k0 + 63 > q0 + warp * 16);
        float mx0 = NEG_INF, mx1 = NEG_INF;
#pragma unroll
        for (int nt = 0; nt < 8; nt++) {
#pragma unroll
            for (int j = 0; j < 2; j++) {
                int col = k0 + nt * 8 + 2 * t + j;
                float s0 = accS[nt][j];
                float s1 = accS[nt][2 + j];
                if (chk) {
                    if (col > rowg0) s0 = NEG_INF;
                    if (col > rowg1) s1 = NEG_INF;
                }
                accS[nt][j] = s0;
                accS[nt][2 + j] = s1;
                mx0 = fmaxf(mx0, s0);
                mx1 = fmaxf(mx1, s1);
            }
        }
        mx0 = fmaxf(mx0, __shfl_xor_sync(0xffffffffu, mx0, 1));
        mx0 = fmaxf(mx0, __shfl_xor_sync(0xffffffffu, mx0, 2));
        mx1 = fmaxf(mx1, __shfl_xor_sync(0xffffffffu, mx1, 1));
        mx1 = fmaxf(mx1, __shfl_xor_sync(0xffffffffu, mx1, 2));

        float mn0 = fmaxf(m0, mx0), mn1 = fmaxf(m1, mx1);
        float al0 = __expf(m0 - mn0), al1 = __expf(m1 - mn1);
        float rs0 = 0.f, rs1 = 0.f;
#pragma unroll
        for (int nt = 0; nt < 8; nt++) {
            float p00 = __expf(accS[nt][0] - mn0);
            float p01 = __expf(accS[nt][1] - mn0);
            float p10 = __expf(accS[nt][2] - mn1);
            float p11 = __expf(accS[nt][3] - mn1);
            rs0 += p00 + p01;
            rs1 += p10 + p11;
            uint32_t ph, pl;
            bf16_split2(p00, p01, ph, pl);
            *(uint32_t*)&Phi[rowA * PS + nt * 8 + 2 * t] = ph;
            *(uint32_t*)&Plo[rowA * PS + nt * 8 + 2 * t] = pl;
            bf16_split2(p10, p11, ph, pl);
            *(uint32_t*)&Phi[(rowA + 8) * PS + nt * 8 + 2 * t] = ph;
            *(uint32_t*)&Plo[(rowA + 8) * PS + nt * 8 + 2 * t] = pl;
        }
        rs0 += __shfl_xor_sync(0xffffffffu, rs0, 1);
        rs0 += __shfl_xor_sync(0xffffffffu, rs0, 2);
        rs1 += __shfl_xor_sync(0xffffffffu, rs1, 1);
        rs1 += __shfl_xor_sync(0xffffffffu, rs1, 2);
        l0s = l0s * al0 + rs0;
        l1s = l1s * al1 + rs1;
        m0 = mn0;
        m1 = mn1;
#pragma unroll
        for (int nt = 0; nt < 16; nt++) {
            accO[nt][0] *= al0; accO[nt][1] *= al0;
            accO[nt][2] *= al1; accO[nt][3] *= al1;
        }
        __syncwarp();

#pragma unroll
        for (int si = 0; si < 4; si++) {
            const int s16 = si * 16;
            uint32_t pah[4], pal[4];
            pah[0] = *(uint32_t*)&Phi[rowA * PS + s16 + 2 * t];
            pah[1] = *(uint32_t*)&Phi[(rowA + 8) * PS + s16 + 2 * t];
            pah[2] = *(uint32_t*)&Phi[rowA * PS + s16 + 8 + 2 * t];
            pah[3] = *(uint32_t*)&Phi[(rowA + 8) * PS + s16 + 8 + 2 * t];
            pal[0] = *(uint32_t*)&Plo[rowA * PS + s16 + 2 * t];
            pal[1] = *(uint32_t*)&Plo[(rowA + 8) * PS + s16 + 2 * t];
            pal[2] = *(uint32_t*)&Plo[rowA * PS + s16 + 8 + 2 * t];
            pal[3] = *(uint32_t*)&Plo[(rowA + 8) * PS + s16 + 8 + 2 * t];
#pragma unroll
            for (int pr = 0; pr < 8; pr++) {
                uint32_t off = (uint32_t)((s16 + srow_off) * VS + pr * 16 + dcol_off) * 2;
                uint32_t vh0, vh1, vh2, vh3, vl0, vl1, vl2, vl3;
                LDSM_X4_T(vh0, vh1, vh2, vh3, vhi_base + off);
                LDSM_X4_T(vl0, vl1, vl2, vl3, vlo_base + off);
                const int nt0 = 2 * pr, nt1 = 2 * pr + 1;
                mma_bf16_16n8k16(accO[nt0], pah, vh0, vh1);
                mma_bf16_16n8k16(accO[nt0], pah, vl0, vl1);
                mma_bf16_16n8k16(accO[nt0], pal, vh0, vh1);
                mma_bf16_16n8k16(accO[nt1], pah, vh2, vh3);
                mma_bf16_16n8k16(accO[nt1], pah, vl2, vl3);
                mma_bf16_16n8k16(accO[nt1], pal, vh2, vh3);
            }
        }
    }

    float inv0 = 1.f / l0s, inv1 = 1.f / l1s;
    float* Op = Og + (size_t)(b * T_ + q0 + rowA) * DM + h * HD;
    float* Op8 = Op + (size_t)8 * DM;
#pragma unroll
    for (int nt = 0; nt < 16; nt++) {
        int col = nt * 8 + 2 * t;
        *(float2*)(Op + col)  = make_float2(tf32f(accO[nt][0] * inv0), tf32f(accO[nt][1] * inv0));
        *(float2*)(Op8 + col) = make_float2(tf32f(accO[nt][2] * inv1), tf32f(accO[nt][3] * inv1));
    }
}

// ============================ launcher ==================================
extern "C" void kernel_launch(void* const* d_in, const int* in_sizes, int n_in,
                              void* d_out, int out_size) {
    const float* x  = (const float*)d_in[0];
    const float* Wq = (const float*)d_in[1];
    const float* Wk = (const float*)d_in[2];
    const float* Wv = (const float*)d_in[3];
    const float* Wo = (const float*)d_in[4];
    float* out = (float*)d_out;

    float *pQ, *pK, *pV, *pA, *pXc, *pWc;
    unsigned short *pQh, *pQl, *pKh, *pKl, *pVh, *pVl;
    cudaGetSymbolAddress((void**)&pQ, g_Q);
    cudaGetSymbolAddress((void**)&pK, g_K);
    cudaGetSymbolAddress((void**)&pV, g_V);
    cudaGetSymbolAddress((void**)&pA, g_A);
    cudaGetSymbolAddress((void**)&pXc, g_xc);
    cudaGetSymbolAddress((void**)&pWc, g_Wc);
    cudaGetSymbolAddress((void**)&pQh, g_Qhi);
    cudaGetSymbolAddress((void**)&pQl, g_Qlo);
    cudaGetSymbolAddress((void**)&pKh, g_Khi);
    cudaGetSymbolAddress((void**)&pKl, g_Klo);
    cudaGetSymbolAddress((void**)&pVh, g_Vhi);
    cudaGetSymbolAddress((void**)&pVl, g_Vlo);
    float* pWqc = pWc;
    float* pWkc = pWc + (size_t)DM * DM;
    float* pWvc = pWc + 2 * (size_t)DM * DM;
    float* pWoc = pWc + 3 * (size_t)DM * DM;

    cudaFuncSetAttribute(gemm_perm, cudaFuncAttributeMaxDynamicSharedMemorySize, GEMM_SMEM);
    cudaFuncSetAttribute(flash_bf16, cudaFuncAttributeMaxDynamicSharedMemorySize, FLASH_SMEM);

    const int NXG = (NROWS * DM) / 16;     // 524288 groups
    const int NWG = (DM * DM) / 16;        // 262144 groups
    dim3 ggrid(DM / 128, NROWS / 128);     // (16, 32)

    cvt_perm<<<NXG / 256, 256>>>(x, pXc, NXG);          // 1
    cvt_perm<<<NWG / 256, 256>>>(Wq, pWqc, NWG);        // 2
    cvt_perm<<<NWG / 256, 256>>>(Wk, pWkc, NWG);        // 3
    gemm_perm<<<ggrid, 128, GEMM_SMEM>>>(pXc, pWqc, pQ);   // 4  <-- profiled
    cvt_perm<<<NWG / 256, 256>>>(Wv, pWvc, NWG);        // 5
    gemm_perm<<<ggrid, 128, GEMM_SMEM>>>(pXc, pWkc, pK);   // 6
    gemm_perm<<<ggrid, 128, GEMM_SMEM>>>(pXc, pWvc, pV);   // 7
    cvt_perm<<<NWG / 256, 256>>>(Wo, pWoc, NWG);        // 8

    rope_kernel<<<(NROWS * NH * 64) / 256, 256>>>(pQ, pK);

    split_qkv<<<(NROWS * DM / 4) / 256, 256>>>(pQ, pK, pV, pQh, pQl, pKh, pKl, pVh, pVl);

    dim3 fgrid(T_ / 128, B_ * NH);         // (16, 32)
    flash_bf16<<<fgrid, 256, FLASH_SMEM>>>(pQh, pQl, pKh, pKl, pVh, pVl, pA);

    cvt_perm<<<NXG / 256, 256>>>(pA, pA, NXG);
    gemm_perm<<<ggrid, 128, GEMM_SMEM>>>(pA, pWoc, out);
}

// round 12
// speedup vs baseline: 1.2122x; 1.0769x over previous
#include <cuda_runtime.h>
#include <cuda_bf16.h>
#include <math.h>
#include <stdint.h>

#define B_  2
#define T_  2048
#define DM  2048
#define NH  16
#define HD  128
#define NROWS (B_ * T_)   // 4096

// ---------------- scratch (no runtime allocation allowed) ----------------
__device__ float g_Q[(size_t)NROWS * DM];
__device__ float g_K[(size_t)NROWS * DM];
__device__ float g_V[(size_t)NROWS * DM];
__device__ float g_A[(size_t)NROWS * DM];
__device__ float g_xc[(size_t)NROWS * DM];          // tf32-rounded, k-permuted x
__device__ float g_Wc[4][(size_t)DM * DM];          // tf32-rounded, k-permuted W
// pre-split bf16 planes for attention
__device__ unsigned short g_Qhi[(size_t)NROWS * DM];
__device__ unsigned short g_Qlo[(size_t)NROWS * DM];
__device__ unsigned short g_Khi[(size_t)NROWS * DM];
__device__ unsigned short g_Klo[(size_t)NROWS * DM];
__device__ unsigned short g_Vhi[(size_t)NROWS * DM];
__device__ unsigned short g_Vlo[(size_t)NROWS * DM];

__device__ __forceinline__ uint32_t f2tf32(float x) {
    uint32_t r;
    asm("cvt.rna.tf32.f32 %0, %1;" : "=r"(r) : "f"(x));
    return r;
}
__device__ __forceinline__ float tf32f(float x) { return __uint_as_float(f2tf32(x)); }

__device__ __forceinline__ uint32_t smem_u32(const void* p) {
    uint32_t a;
    asm("{ .reg .u64 t; cvta.to.shared.u64 t, %1; cvt.u32.u64 %0, t; }" : "=r"(a) : "l"(p));
    return a;
}

__device__ __forceinline__ void mma_tf32_16n8k8(float c[4], const uint32_t a[4],
                                                const uint32_t b0, const uint32_t b1) {
    asm volatile(
        "mma.sync.aligned.m16n8k8.row.col.f32.tf32.tf32.f32 "
        "{%0,%1,%2,%3}, {%4,%5,%6,%7}, {%8,%9}, {%0,%1,%2,%3};"
        : "+f"(c[0]), "+f"(c[1]), "+f"(c[2]), "+f"(c[3])
        : "r"(a[0]), "r"(a[1]), "r"(a[2]), "r"(a[3]), "r"(b0), "r"(b1));
}

__device__ __forceinline__ void mma_bf16_16n8k16(float c[4], const uint32_t a[4],
                                                 const uint32_t b0, const uint32_t b1) {
    asm volatile(
        "mma.sync.aligned.m16n8k16.row.col.f32.bf16.bf16.f32 "
        "{%0,%1,%2,%3}, {%4,%5,%6,%7}, {%8,%9}, {%0,%1,%2,%3};"
        : "+f"(c[0]), "+f"(c[1]), "+f"(c[2]), "+f"(c[3])
        : "r"(a[0]), "r"(a[1]), "r"(a[2]), "r"(a[3]), "r"(b0), "r"(b1));
}

__device__ __forceinline__ void bf16_split2(float x, float y, uint32_t& hi, uint32_t& lo) {
    __nv_bfloat16 hx = __float2bfloat16(x);
    __nv_bfloat16 hy = __float2bfloat16(y);
    __nv_bfloat16 lx = __float2bfloat16(x - __bfloat162float(hx));
    __nv_bfloat16 ly = __float2bfloat16(y - __bfloat162float(hy));
    hi = (uint32_t)__bfloat16_as_ushort(hx) | ((uint32_t)__bfloat16_as_ushort(hy) << 16);
    lo = (uint32_t)__bfloat16_as_ushort(lx) | ((uint32_t)__bfloat16_as_ushort(ly) << 16);
}

#define LDSM_X4_T(r0, r1, r2, r3, addr) \
    asm volatile("ldmatrix.sync.aligned.m8n8.x4.trans.shared.b16 {%0,%1,%2,%3}, [%4];" \
                 : "=r"(r0), "=r"(r1), "=r"(r2), "=r"(r3) : "r"(addr))

#define CP_ASYNC16(sp, gp) \
    asm volatile("cp.async.cg.shared.global [%0], [%1], 16;" :: "r"(sp), "l"(gp))

// ============ tf32 round + k-permute (within each 16-group) ==============
__global__ __launch_bounds__(256) void cvt_perm(const float* __restrict__ in,
                                                float* __restrict__ out, int ngroups) {
    int i = blockIdx.x * 256 + threadIdx.x;
    if (i < ngroups) {
        const float4* ip = (const float4*)(in + (size_t)i * 16);
        float4 v0 = ip[0], v1 = ip[1], v2 = ip[2], v3 = ip[3];
        float4* op = (float4*)(out + (size_t)i * 16);
        op[0] = make_float4(tf32f(v0.x), tf32f(v1.x), tf32f(v2.x), tf32f(v3.x));
        op[1] = make_float4(tf32f(v0.y), tf32f(v1.y), tf32f(v2.y), tf32f(v3.y));
        op[2] = make_float4(tf32f(v0.z), tf32f(v1.z), tf32f(v2.z), tf32f(v3.z));
        op[3] = make_float4(tf32f(v0.w), tf32f(v1.w), tf32f(v2.w), tf32f(v3.w));
    }
}

// batched over the 4 weight matrices (z selects input; out = base + z*DM*DM)
__global__ __launch_bounds__(256) void cvt_perm4(const float* __restrict__ w0,
                                                 const float* __restrict__ w1,
                                                 const float* __restrict__ w2,
                                                 const float* __restrict__ w3,
                                                 float* __restrict__ outbase, int ngroups) {
    int z = blockIdx.z;
    const float* in = (z == 0) ? w0 : (z == 1) ? w1 : (z == 2) ? w2 : w3;
    float* out = outbase + (size_t)z * DM * DM;
    int i = blockIdx.x * 256 + threadIdx.x;
    if (i < ngroups) {
        const float4* ip = (const float4*)(in + (size_t)i * 16);
        float4 v0 = ip[0], v1 = ip[1], v2 = ip[2], v3 = ip[3];
        float4* op = (float4*)(out + (size_t)i * 16);
        op[0] = make_float4(tf32f(v0.x), tf32f(v1.x), tf32f(v2.x), tf32f(v3.x));
        op[1] = make_float4(tf32f(v0.y), tf32f(v1.y), tf32f(v2.y), tf32f(v3.y));
        op[2] = make_float4(tf32f(v0.z), tf32f(v1.z), tf32f(v2.z), tf32f(v3.z));
        op[3] = make_float4(tf32f(v0.w), tf32f(v1.w), tf32f(v2.w), tf32f(v3.w));
    }
}

// ======== fused RoPE + bf16 hi/lo split of Q (scaled), K, V ==============
// One thread: head-dim pair block [d4, d4+4) and [d4+64, d4+68).
__global__ __launch_bounds__(256) void rope_split(const float* __restrict__ Q,
                                                  const float* __restrict__ K,
                                                  const float* __restrict__ V,
                                                  unsigned short* __restrict__ Qhi_g,
                                                  unsigned short* __restrict__ Qlo_g,
                                                  unsigned short* __restrict__ Khi_g,
                                                  unsigned short* __restrict__ Klo_g,
                                                  unsigned short* __restrict__ Vhi_g,
                                                  unsigned short* __restrict__ Vlo_g) {
    const float scale = 0.08838834764831845f;
    const float LOG2_10000 = 13.287712379549449f;
    int idx = blockIdx.x * 256 + threadIdx.x;        // < NROWS*NH*16
    int d4 = (idx & 15) * 4;                         // 0,4,...,60
    int h = (idx >> 4) & (NH - 1);
    int n = idx >> 8;
    int t = n & (T_ - 1);
    size_t base = (size_t)n * DM + h * HD;

    float c[4], s[4];
#pragma unroll
    for (int j = 0; j < 4; j++) {
        float inv = exp2f(-(float)(2 * (d4 + j)) * (LOG2_10000 / 128.0f));
        sincosf((float)t * inv, &s[j], &c[j]);
    }

    uint32_t h0, l0, h1, l1;
    // ---- Q: rope + scale + split ----
    {
        float4 q1 = *(const float4*)(Q + base + d4);
        float4 q2 = *(const float4*)(Q + base + d4 + 64);
        float a0 = (q1.x * c[0] - q2.x * s[0]) * scale;
        float a1 = (q1.y * c[1] - q2.y * s[1]) * scale;
        float a2 = (q1.z * c[2] - q2.z * s[2]) * scale;
        float a3 = (q1.w * c[3] - q2.w * s[3]) * scale;
        float b0 = (q2.x * c[0] + q1.x * s[0]) * scale;
        float b1 = (q2.y * c[1] + q1.y * s[1]) * scale;
        float b2 = (q2.z * c[2] + q1.z * s[2]) * scale;
        float b3 = (q2.w * c[3] + q1.w * s[3]) * scale;
        bf16_split2(a0, a1, h0, l0); bf16_split2(a2, a3, h1, l1);
        *(uint2*)(Qhi_g + base + d4) = make_uint2(h0, h1);
        *(uint2*)(Qlo_g + base + d4) = make_uint2(l0, l1);
        bf16_split2(b0, b1, h0, l0); bf16_split2(b2, b3, h1, l1);
        *(uint2*)(Qhi_g + base + d4 + 64) = make_uint2(h0, h1);
        *(uint2*)(Qlo_g + base + d4 + 64) = make_uint2(l0, l1);
    }
    // ---- K: rope + split ----
    {
        float4 k1 = *(const float4*)(K + base + d4);
        float4 k2 = *(const float4*)(K + base + d4 + 64);
        float a0 = k1.x * c[0] - k2.x * s[0];
        float a1 = k1.y * c[1] - k2.y * s[1];
        float a2 = k1.z * c[2] - k2.z * s[2];
        float a3 = k1.w * c[3] - k2.w * s[3];
        float b0 = k2.x * c[0] + k1.x * s[0];
        float b1 = k2.y * c[1] + k1.y * s[1];
        float b2 = k2.z * c[2] + k1.z * s[2];
        float b3 = k2.w * c[3] + k1.w * s[3];
        bf16_split2(a0, a1, h0, l0); bf16_split2(a2, a3, h1, l1);
        *(uint2*)(Khi_g + base + d4) = make_uint2(h0, h1);
        *(uint2*)(Klo_g + base + d4) = make_uint2(l0, l1);
        bf16_split2(b0, b1, h0, l0); bf16_split2(b2, b3, h1, l1);
        *(uint2*)(Khi_g + base + d4 + 64) = make_uint2(h0, h1);
        *(uint2*)(Klo_g + base + d4 + 64) = make_uint2(l0, l1);
    }
    // ---- V: split only ----
    {
        float4 v1 = *(const float4*)(V + base + d4);
        float4 v2 = *(const float4*)(V + base + d4 + 64);
        bf16_split2(v1.x, v1.y, h0, l0); bf16_split2(v1.z, v1.w, h1, l1);
        *(uint2*)(Vhi_g + base + d4) = make_uint2(h0, h1);
        *(uint2*)(Vlo_g + base + d4) = make_uint2(l0, l1);
        bf16_split2(v2.x, v2.y, h0, l0); bf16_split2(v2.z, v2.w, h1, l1);
        *(uint2*)(Vhi_g + base + d4 + 64) = make_uint2(h0, h1);
        *(uint2*)(Vlo_g + base + d4 + 64) = make_uint2(l0, l1);
    }
}

// == TF32 mma GEMM (R9 config): 128 thr, 4 warps (2x2), warp 64x64, 3-stage ==
// z-batched: blockIdx.z selects (B, C) pair.
#define GK 2048
#define GN 2048
#define CSTAGE_F (2 * 128 * 32)              // 8192 floats = 32 KB / stage
#define GEMM_SMEM (3 * CSTAGE_F * 4)         // 98304 bytes

__device__ __forceinline__ uint32_t sw_word(int row, int chunk) {
    return (uint32_t)(row * 32 + ((chunk ^ ((row & 1) << 2)) << 2));
}

__global__ __launch_bounds__(128) void gemm_perm(const float* __restrict__ A,
                                                 const float* __restrict__ B0, float* __restrict__ C0,
                                                 const float* __restrict__ B1, float* __restrict__ C1,
                                                 const float* __restrict__ B2, float* __restrict__ C2) {
    extern __shared__ float sh[];
    const int z = blockIdx.z;
    const float* Bm = (z == 0) ? B0 : (z == 1) ? B1 : B2;
    float* C = (z == 0) ? C0 : (z == 1) ? C1 : C2;
    const int tid = threadIdx.x;
    const int warp = tid >> 5;
    const int lane = tid & 31;
    const int g = lane >> 2;
    const int t = lane & 3;
    const int warp_m = warp & 1;
    const int warp_n = warp >> 1;
    const int m0 = blockIdx.y * 128;
    const int n0 = blockIdx.x * 128;
    const uint32_t sbase = smem_u32(sh);

    float acc[4][8][4];
#pragma unroll
    for (int mt = 0; mt < 4; mt++)
#pragma unroll
        for (int nt = 0; nt < 8; nt++)
#pragma unroll
            for (int j = 0; j < 4; j++) acc[mt][nt][j] = 0.f;

    const int NIT = GK / 32;    // 64

#define GEMM_ISSUE(stage, k0)                                                      \
    do {                                                                           \
        const uint32_t stb = sbase + (stage) * CSTAGE_F * 4;                       \
        _Pragma("unroll")                                                          \
        for (int i_ = 0; i_ < 16; i_++) {                                          \
            int idx = i_ * 128 + tid;                                              \
            int mat = idx >> 10;                                                   \
            int r = (idx >> 3) & 127;                                              \
            int ch = idx & 7;                                                      \
            const float* gp = (mat ? Bm + (size_t)(n0 + r) * GK                    \
                                   : A + (size_t)(m0 + r) * GK) + (k0) + ch * 4;   \
            uint32_t sp = stb + (mat * 128 * 32 + sw_word(r, ch)) * 4;             \
            CP_ASYNC16(sp, gp);                                                    \
        }                                                                          \
        asm volatile("cp.async.commit_group;" ::: "memory");                       \
    } while (0)

    GEMM_ISSUE(0, 0);
    GEMM_ISSUE(1, 32);

    for (int it = 0; it < NIT; it++) {
        if (it + 1 < NIT) asm volatile("cp.async.wait_group 1;" ::: "memory");
        else              asm volatile("cp.async.wait_group 0;" ::: "memory");
        __syncthreads();

        const float* As = sh + (it % 3) * CSTAGE_F;
        const float* Bs = As + 128 * 32;
#pragma unroll
        for (int ks2 = 0; ks2 < 2; ks2++) {
            const int c0 = 4 * ks2 + t;
            float4 alo[4], ahi[4];
#pragma unroll
            for (int mt = 0; mt < 4; mt++) {
                int r0 = warp_m * 64 + mt * 16 + g;
                alo[mt] = *(const float4*)&As[sw_word(r0, c0)];
                ahi[mt] = *(const float4*)&As[sw_word(r0 + 8, c0)];
            }
            float4 bv[8];
#pragma unroll
            for (int nt = 0; nt < 8; nt++) {
                int cn = warp_n * 64 + nt * 8 + g;
                bv[nt] = *(const float4*)&Bs[sw_word(cn, c0)];
            }
#pragma unroll
            for (int mt = 0; mt < 4; mt++) {
                uint32_t af[4] = {__float_as_uint(alo[mt].x), __float_as_uint(ahi[mt].x),
                                  __float_as_uint(alo[mt].y), __float_as_uint(ahi[mt].y)};
#pragma unroll
                for (int nt = 0; nt < 8; nt++)
                    mma_tf32_16n8k8(acc[mt][nt], af,
                                    __float_as_uint(bv[nt].x), __float_as_uint(bv[nt].y));
            }
#pragma unroll
            for (int mt = 0; mt < 4; mt++) {
                uint32_t af[4] = {__float_as_uint(alo[mt].z), __float_as_uint(ahi[mt].z),
                                  __float_as_uint(alo[mt].w), __float_as_uint(ahi[mt].w)};
#pragma unroll
                for (int nt = 0; nt < 8; nt++)
                    mma_tf32_16n8k8(acc[mt][nt], af,
                                    __float_as_uint(bv[nt].z), __float_as_uint(bv[nt].w));
            }
        }

        if (it + 2 < NIT) GEMM_ISSUE((it + 2) % 3, (it + 2) * 32);
    }

#pragma unroll
    for (int mt = 0; mt < 4; mt++) {
        int row = m0 + warp_m * 64 + mt * 16 + g;
#pragma unroll
        for (int nt = 0; nt < 8; nt++) {
            int col = n0 + warp_n * 64 + nt * 8 + 2 * t;
            *(float2*)(C + (size_t)row * GN + col) = make_float2(acc[mt][nt][0], acc[mt][nt][1]);
            *(float2*)(C + (size_t)(row + 8) * GN + col) = make_float2(acc[mt][nt][2], acc[mt][nt][3]);
        }
    }
}

// ===== Flash attention, bf16x3 m16n8k16, pre-split planes + cp.async =====
// Epilogue writes tf32-rounded values at k-permuted positions (feeds gemm_perm).
#define QS 136
#define KS 136
#define VS 136
#define PS 72
#define OFF_QHI 0
#define OFF_QLO (128 * QS)
#define OFF_KHI (OFF_QLO + 128 * QS)
#define OFF_KLO (OFF_KHI + 64 * KS)
#define OFF_VHI (OFF_KLO + 64 * KS)
#define OFF_VLO (OFF_VHI + 64 * VS)
#define OFF_PHI (OFF_VLO + 64 * VS)
#define OFF_PLO (OFF_PHI + 128 * PS)
#define FLASH_SMEM ((OFF_PLO + 128 * PS) * 2)

__global__ __launch_bounds__(256) void flash_bf16(const unsigned short* __restrict__ Qhi_g,
                                                  const unsigned short* __restrict__ Qlo_g,
                                                  const unsigned short* __restrict__ Khi_g,
                                                  const unsigned short* __restrict__ Klo_g,
                                                  const unsigned short* __restrict__ Vhi_g,
                                                  const unsigned short* __restrict__ Vlo_g,
                                                  float* __restrict__ Og) {
    extern __shared__ unsigned short su[];
    unsigned short* Qhi = su + OFF_QHI;
    unsigned short* Qlo = su + OFF_QLO;
    unsigned short* Khi = su + OFF_KHI;
    unsigned short* Klo = su + OFF_KLO;
    unsigned short* Phi = su + OFF_PHI;
    unsigned short* Plo = su + OFF_PLO;

    const int qb = blockIdx.x;
    const int bh = blockIdx.y;
    const int b = bh >> 4, h = bh & 15;
    const int q0 = qb * 128;
    const int tid = threadIdx.x;
    const int warp = tid >> 5;
    const int lane = tid & 31;
    const int g = lane >> 2;
    const int t = lane & 3;
    const float NEG_INF = __int_as_float(0xff800000);

    const int lq = lane >> 3;
    const int lsl = lane & 7;
    const int srow_off = (lq & 1) * 8 + lsl;
    const int dcol_off = (lq >> 1) * 8;
    const uint32_t sbase = smem_u32(su);
    const uint32_t vhi_base = sbase + OFF_VHI * 2;
    const uint32_t vlo_base = sbase + OFF_VLO * 2;

    // ---- prologue: async-load Q hi/lo tile ----
    {
        const size_t gbase = (size_t)(b * T_ + q0) * DM + h * HD;
#pragma unroll
        for (int i = 0; i < 8; i++) {
            int idx = i * 256 + tid;
            int r = idx >> 4;
            int ch = idx & 15;
            size_t go = gbase + (size_t)r * DM + ch * 8;
            uint32_t so = (uint32_t)(r * QS + ch * 8) * 2;
            CP_ASYNC16(sbase + OFF_QHI * 2 + so, Qhi_g + go);
            CP_ASYNC16(sbase + OFF_QLO * 2 + so, Qlo_g + go);
        }
    }

    float accO[16][4];
#pragma unroll
    for (int nt = 0; nt < 16; nt++)
#pragma unroll
        for (int j = 0; j < 4; j++) accO[nt][j] = 0.f;
    float m0 = -1e30f, m1 = -1e30f, l0s = 0.f, l1s = 0.f;

    const int rowA = warp * 16 + g;
    const int ntiles = 2 * qb + 2;

    for (int kb = 0; kb < ntiles; kb++) {
        const int k0 = kb * 64;
        __syncthreads();
        {
            const size_t gbase = (size_t)(b * T_ + k0) * DM + h * HD;
#pragma unroll
            for (int i = 0; i < 4; i++) {
                int idx = i * 256 + tid;
                int r = idx >> 4;
                int ch = idx & 15;
                size_t go = gbase + (size_t)r * DM + ch * 8;
                uint32_t so = (uint32_t)(r * KS + ch * 8) * 2;
                CP_ASYNC16(sbase + OFF_KHI * 2 + so, Khi_g + go);
                CP_ASYNC16(sbase + OFF_KLO * 2 + so, Klo_g + go);
                CP_ASYNC16(sbase + OFF_VHI * 2 + so, Vhi_g + go);
                CP_ASYNC16(sbase + OFF_VLO * 2 + so, Vlo_g + go);
            }
        }
        asm volatile("cp.async.commit_group;" ::: "memory");
        asm volatile("cp.async.wait_group 0;" ::: "memory");
        __syncthreads();

        float accS[8][4];
#pragma unroll
        for (int nt = 0; nt < 8; nt++)
#pragma unroll
            for (int j = 0; j < 4; j++) accS[nt][j] = 0.f;

#pragma unroll
        for (int ks = 0; ks < 8; ks++) {
            const int k16 = ks * 16;
            uint32_t ah[4], al[4];
            ah[0] = *(uint32_t*)&Qhi[rowA * QS + k16 + 2 * t];
            ah[1] = *(uint32_t*)&Qhi[(rowA + 8) * QS + k16 + 2 * t];
            ah[2] = *(uint32_t*)&Qhi[rowA * QS + k16 + 8 + 2 * t];
            ah[3] = *(uint32_t*)&Qhi[(rowA + 8) * QS + k16 + 8 + 2 * t];
            al[0] = *(uint32_t*)&Qlo[rowA * QS + k16 + 2 * t];
            al[1] = *(uint32_t*)&Qlo[(rowA + 8) * QS + k16 + 2 * t];
            al[2] = *(uint32_t*)&Qlo[rowA * QS + k16 + 8 + 2 * t];
            al[3] = *(uint32_t*)&Qlo[(rowA + 8) * QS + k16 + 8 + 2 * t];
#pragma unroll
            for (int nt = 0; nt < 8; nt++) {
                int krow = nt * 8 + g;
                uint32_t bh0 = *(uint32_t*)&Khi[krow * KS + k16 + 2 * t];
                uint32_t bh1 = *(uint32_t*)&Khi[krow * KS + k16 + 8 + 2 * t];
                uint32_t bl0 = *(uint32_t*)&Klo[krow * KS + k16 + 2 * t];
                uint32_t bl1 = *(uint32_t*)&Klo[krow * KS + k16 + 8 + 2 * t];
                mma_bf16_16n8k16(accS[nt], ah, bh0, bh1);
                mma_bf16_16n8k16(accS[nt], ah, bl0, bl1);
                mma_bf16_16n8k16(accS[nt], al, bh0, bh1);
            }
        }

        const int rowg0 = q0 + rowA;
        const int rowg1 = rowg0 + 8;
        const bool chk = (k0 + 63 > q0 + warp * 16);
        float mx0 = NEG_INF, mx1 = NEG_INF;
#pragma unroll
        for (int nt = 0; nt < 8; nt++) {
#pragma unroll
            for (int j = 0; j < 2; j++) {
                int col = k0 + nt * 8 + 2 * t + j;
                float s0 = accS[nt][j];
                float s1 = accS[nt][2 + j];
                if (chk) {
                    if (col > rowg0) s0 = NEG_INF;
                    if (col > rowg1) s1 = NEG_INF;
                }
                accS[nt][j] = s0;
                accS[nt][2 + j] = s1;
                mx0 = fmaxf(mx0, s0);
                mx1 = fmaxf(mx1, s1);
            }
        }
        mx0 = fmaxf(mx0, __shfl_xor_sync(0xffffffffu, mx0, 1));
        mx0 = fmaxf(mx0, __shfl_xor_sync(0xffffffffu, mx0, 2));
        mx1 = fmaxf(mx1, __shfl_xor_sync(0xffffffffu, mx1, 1));
        mx1 = fmaxf(mx1, __shfl_xor_sync(0xffffffffu, mx1, 2));

        float mn0 = fmaxf(m0, mx0), mn1 = fmaxf(m1, mx1);
        float al0 = __expf(m0 - mn0), al1 = __expf(m1 - mn1);
        float rs0 = 0.f, rs1 = 0.f;
#pragma unroll
        for (int nt = 0; nt < 8; nt++) {
            float p00 = __expf(accS[nt][0] - mn0);
            float p01 = __expf(accS[nt][1] - mn0);
            float p10 = __expf(accS[nt][2] - mn1);
            float p11 = __expf(accS[nt][3] - mn1);
            rs0 += p00 + p01;
            rs1 += p10 + p11;
            uint32_t ph, pl;
            bf16_split2(p00, p01, ph, pl);
            *(uint32_t*)&Phi[rowA * PS + nt * 8 + 2 * t] = ph;
            *(uint32_t*)&Plo[rowA * PS + nt * 8 + 2 * t] = pl;
            bf16_split2(p10, p11, ph, pl);
            *(uint32_t*)&Phi[(rowA + 8) * PS + nt * 8 + 2 * t] = ph;
            *(uint32_t*)&Plo[(rowA + 8) * PS + nt * 8 + 2 * t] = pl;
        }
        rs0 += __shfl_xor_sync(0xffffffffu, rs0, 1);
        rs0 += __shfl_xor_sync(0xffffffffu, rs0, 2);
        rs1 += __shfl_xor_sync(0xffffffffu, rs1, 1);
        rs1 += __shfl_xor_sync(0xffffffffu, rs1, 2);
        l0s = l0s * al0 + rs0;
        l1s = l1s * al1 + rs1;
        m0 = mn0;
        m1 = mn1;
#pragma unroll
        for (int nt = 0; nt < 16; nt++) {
            accO[nt][0] *= al0; accO[nt][1] *= al0;
            accO[nt][2] *= al1; accO[nt][3] *= al1;
        }
        __syncwarp();

#pragma unroll
        for (int si = 0; si < 4; si++) {
            const int s16 = si * 16;
            uint32_t pah[4], pal[4];
            pah[0] = *(uint32_t*)&Phi[rowA * PS + s16 + 2 * t];
            pah[1] = *(uint32_t*)&Phi[(rowA + 8) * PS + s16 + 2 * t];
            pah[2] = *(uint32_t*)&Phi[rowA * PS + s16 + 8 + 2 * t];
            pah[3] = *(uint32_t*)&Phi[(rowA + 8) * PS + s16 + 8 + 2 * t];
            pal[0] = *(uint32_t*)&Plo[rowA * PS + s16 + 2 * t];
            pal[1] = *(uint32_t*)&Plo[(rowA + 8) * PS + s16 + 2 * t];
            pal[2] = *(uint32_t*)&Plo[rowA * PS + s16 + 8 + 2 * t];
            pal[3] = *(uint32_t*)&Plo[(rowA + 8) * PS + s16 + 8 + 2 * t];
#pragma unroll
            for (int pr = 0; pr < 8; pr++) {
                uint32_t off = (uint32_t)((s16 + srow_off) * VS + pr * 16 + dcol_off) * 2;
                uint32_t vh0, vh1, vh2, vh3, vl0, vl1, vl2, vl3;
                LDSM_X4_T(vh0, vh1, vh2, vh3, vhi_base + off);
                LDSM_X4_T(vl0, vl1, vl2, vl3, vlo_base + off);
                const int nt0 = 2 * pr, nt1 = 2 * pr + 1;
                mma_bf16_16n8k16(accO[nt0], pah, vh0, vh1);
                mma_bf16_16n8k16(accO[nt0], pah, vl0, vl1);
                mma_bf16_16n8k16(accO[nt0], pal, vh0, vh1);
                mma_bf16_16n8k16(accO[nt1], pah, vh2, vh3);
                mma_bf16_16n8k16(accO[nt1], pah, vl2, vl3);
                mma_bf16_16n8k16(accO[nt1], pal, vh2, vh3);
            }
        }
    }

    // ---- epilogue: normalize + tf32 round + k-permuted scatter ----
    float inv0 = 1.f / l0s, inv1 = 1.f / l1s;
    float* Op = Og + (size_t)(b * T_ + q0 + rowA) * DM + h * HD;
    float* Op8 = Op + (size_t)8 * DM;
#pragma unroll
    for (int nt = 0; nt < 16; nt++) {
#pragma unroll
        for (int j = 0; j < 2; j++) {
            int col = nt * 8 + 2 * t + j;
            int jj = col & 15;
            int p = (col & ~15) + ((jj & 3) << 2) + (jj >> 2);
            Op[p]  = tf32f(accO[nt][j] * inv0);
            Op8[p] = tf32f(accO[nt][2 + j] * inv1);
        }
    }
}

// ============================ launcher ==================================
extern "C" void kernel_launch(void* const* d_in, const int* in_sizes, int n_in,
                              void* d_out, int out_size) {
    const float* x  = (const float*)d_in[0];
    const float* Wq = (const float*)d_in[1];
    const float* Wk = (const float*)d_in[2];
    const float* Wv = (const float*)d_in[3];
    const float* Wo = (const float*)d_in[4];
    float* out = (float*)d_out;

    float *pQ, *pK, *pV, *pA, *pXc, *pWc;
    unsigned short *pQh, *pQl, *pKh, *pKl, *pVh, *pVl;
    cudaGetSymbolAddress((void**)&pQ, g_Q);
    cudaGetSymbolAddress((void**)&pK, g_K);
    cudaGetSymbolAddress((void**)&pV, g_V);
    cudaGetSymbolAddress((void**)&pA, g_A);
    cudaGetSymbolAddress((void**)&pXc, g_xc);
    cudaGetSymbolAddress((void**)&pWc, g_Wc);
    cudaGetSymbolAddress((void**)&pQh, g_Qhi);
    cudaGetSymbolAddress((void**)&pQl, g_Qlo);
    cudaGetSymbolAddress((void**)&pKh, g_Khi);
    cudaGetSymbolAddress((void**)&pKl, g_Klo);
    cudaGetSymbolAddress((void**)&pVh, g_Vhi);
    cudaGetSymbolAddress((void**)&pVl, g_Vlo);
    float* pWqc = pWc;
    float* pWkc = pWc + (size_t)DM * DM;
    float* pWvc = pWc + 2 * (size_t)DM * DM;
    float* pWoc = pWc + 3 * (size_t)DM * DM;

    cudaFuncSetAttribute(gemm_perm, cudaFuncAttributeMaxDynamicSharedMemorySize, GEMM_SMEM);
    cudaFuncSetAttribute(flash_bf16, cudaFuncAttributeMaxDynamicSharedMemorySize, FLASH_SMEM);

    const int NXG = (NROWS * DM) / 16;     // 524288 groups
    const int NWG = (DM * DM) / 16;        // 262144 groups
    dim3 ggrid3(DM / 128, NROWS / 128, 3); // (16, 32, 3)
    dim3 ggrid1(DM / 128, NROWS / 128, 1);

    // 6 launches total; profiled launch (#6) is the Wo gemm.
    cvt_perm<<<NXG / 256, 256>>>(x, pXc, NXG);                         // 1
    cvt_perm4<<<dim3(NWG / 256, 1, 4), 256>>>(Wq, Wk, Wv, Wo, pWc, NWG); // 2
    gemm_perm<<<ggrid3, 128, GEMM_SMEM>>>(pXc, pWqc, pQ, pWkc, pK, pWvc, pV); // 3
    rope_split<<<(NROWS * NH * 16) / 256, 256>>>(pQ, pK, pV,
                                                 pQh, pQl, pKh, pKl, pVh, pVl); // 4
    dim3 fgrid(T_ / 128, B_ * NH);         // (16, 32)
    flash_bf16<<<fgrid, 256, FLASH_SMEM>>>(pQh, pQl, pKh, pKl, pVh, pVl, pA);  // 5
    gemm_perm<<<ggrid1, 128, GEMM_SMEM>>>(pA, pWoc, out, pWoc, out, pWoc, out); // 6
}

// round 13
// speedup vs baseline: 1.2424x; 1.0249x over previous
#include <cuda_runtime.h>
#include <cuda_bf16.h>
#include <math.h>
#include <stdint.h>

#define B_  2
#define T_  2048
#define DM  2048
#define NH  16
#define HD  128
#define NROWS (B_ * T_)   // 4096

// ---------------- scratch (no runtime allocation allowed) ----------------
__device__ float g_Q[(size_t)NROWS * DM];
__device__ float g_K[(size_t)NROWS * DM];
__device__ float g_V[(size_t)NROWS * DM];
__device__ float g_A[(size_t)NROWS * DM];
__device__ float g_xc[(size_t)NROWS * DM];          // tf32-rounded, k-permuted x
__device__ float g_Wc[4][(size_t)DM * DM];          // tf32-rounded, k-permuted W
// pre-split bf16 planes for attention
__device__ unsigned short g_Qhi[(size_t)NROWS * DM];
__device__ unsigned short g_Qlo[(size_t)NROWS * DM];
__device__ unsigned short g_Khi[(size_t)NROWS * DM];
__device__ unsigned short g_Klo[(size_t)NROWS * DM];
__device__ unsigned short g_Vhi[(size_t)NROWS * DM];
__device__ unsigned short g_Vlo[(size_t)NROWS * DM];

__device__ __forceinline__ uint32_t f2tf32(float x) {
    uint32_t r;
    asm("cvt.rna.tf32.f32 %0, %1;" : "=r"(r) : "f"(x));
    return r;
}
__device__ __forceinline__ float tf32f(float x) { return __uint_as_float(f2tf32(x)); }

__device__ __forceinline__ uint32_t smem_u32(const void* p) {
    uint32_t a;
    asm("{ .reg .u64 t; cvta.to.shared.u64 t, %1; cvt.u32.u64 %0, t; }" : "=r"(a) : "l"(p));
    return a;
}

__device__ __forceinline__ void mma_tf32_16n8k8(float c[4], const uint32_t a[4],
                                                const uint32_t b0, const uint32_t b1) {
    asm volatile(
        "mma.sync.aligned.m16n8k8.row.col.f32.tf32.tf32.f32 "
        "{%0,%1,%2,%3}, {%4,%5,%6,%7}, {%8,%9}, {%0,%1,%2,%3};"
        : "+f"(c[0]), "+f"(c[1]), "+f"(c[2]), "+f"(c[3])
        : "r"(a[0]), "r"(a[1]), "r"(a[2]), "r"(a[3]), "r"(b0), "r"(b1));
}

__device__ __forceinline__ void mma_bf16_16n8k16(float c[4], const uint32_t a[4],
                                                 const uint32_t b0, const uint32_t b1) {
    asm volatile(
        "mma.sync.aligned.m16n8k16.row.col.f32.bf16.bf16.f32 "
        "{%0,%1,%2,%3}, {%4,%5,%6,%7}, {%8,%9}, {%0,%1,%2,%3};"
        : "+f"(c[0]), "+f"(c[1]), "+f"(c[2]), "+f"(c[3])
        : "r"(a[0]), "r"(a[1]), "r"(a[2]), "r"(a[3]), "r"(b0), "r"(b1));
}

__device__ __forceinline__ void bf16_split2(float x, float y, uint32_t& hi, uint32_t& lo) {
    __nv_bfloat16 hx = __float2bfloat16(x);
    __nv_bfloat16 hy = __float2bfloat16(y);
    __nv_bfloat16 lx = __float2bfloat16(x - __bfloat162float(hx));
    __nv_bfloat16 ly = __float2bfloat16(y - __bfloat162float(hy));
    hi = (uint32_t)__bfloat16_as_ushort(hx) | ((uint32_t)__bfloat16_as_ushort(hy) << 16);
    lo = (uint32_t)__bfloat16_as_ushort(lx) | ((uint32_t)__bfloat16_as_ushort(ly) << 16);
}

#define LDSM_X4_T(r0, r1, r2, r3, addr) \
    asm volatile("ldmatrix.sync.aligned.m8n8.x4.trans.shared.b16 {%0,%1,%2,%3}, [%4];" \
                 : "=r"(r0), "=r"(r1), "=r"(r2), "=r"(r3) : "r"(addr))

#define CP_ASYNC16(sp, gp) \
    asm volatile("cp.async.cg.shared.global [%0], [%1], 16;" :: "r"(sp), "l"(gp))

// ==== tf32 round + k-permute, batched over x (2 halves) + 4 weights ======
__global__ __launch_bounds__(256) void cvt_all(const float* __restrict__ x,
                                               const float* __restrict__ w0,
                                               const float* __restrict__ w1,
                                               const float* __restrict__ w2,
                                               const float* __restrict__ w3,
                                               float* __restrict__ xout,
                                               float* __restrict__ wout, int ngroups) {
    int z = blockIdx.z;
    const float* in;
    float* out;
    if (z < 2) {
        in = x + (size_t)z * ngroups * 16;
        out = xout + (size_t)z * ngroups * 16;
    } else {
        int w = z - 2;
        in = (w == 0) ? w0 : (w == 1) ? w1 : (w == 2) ? w2 : w3;
        out = wout + (size_t)w * DM * DM;
    }
    int i = blockIdx.x * 256 + threadIdx.x;
    if (i < ngroups) {
        const float4* ip = (const float4*)(in + (size_t)i * 16);
        float4 v0 = ip[0], v1 = ip[1], v2 = ip[2], v3 = ip[3];
        float4* op = (float4*)(out + (size_t)i * 16);
        op[0] = make_float4(tf32f(v0.x), tf32f(v1.x), tf32f(v2.x), tf32f(v3.x));
        op[1] = make_float4(tf32f(v0.y), tf32f(v1.y), tf32f(v2.y), tf32f(v3.y));
        op[2] = make_float4(tf32f(v0.z), tf32f(v1.z), tf32f(v2.z), tf32f(v3.z));
        op[3] = make_float4(tf32f(v0.w), tf32f(v1.w), tf32f(v2.w), tf32f(v3.w));
    }
}

// ======== fused RoPE + bf16 hi/lo split of Q (scaled), K, V ==============
__global__ __launch_bounds__(256) void rope_split(const float* __restrict__ Q,
                                                  const float* __restrict__ K,
                                                  const float* __restrict__ V,
                                                  unsigned short* __restrict__ Qhi_g,
                                                  unsigned short* __restrict__ Qlo_g,
                                                  unsigned short* __restrict__ Khi_g,
                                                  unsigned short* __restrict__ Klo_g,
                                                  unsigned short* __restrict__ Vhi_g,
                                                  unsigned short* __restrict__ Vlo_g) {
    const float scale = 0.08838834764831845f;
    const float LOG2_10000 = 13.287712379549449f;
    int idx = blockIdx.x * 256 + threadIdx.x;        // < NROWS*NH*16
    int d4 = (idx & 15) * 4;
    int h = (idx >> 4) & (NH - 1);
    int n = idx >> 8;
    int t = n & (T_ - 1);
    size_t base = (size_t)n * DM + h * HD;

    float c[4], s[4];
#pragma unroll
    for (int j = 0; j < 4; j++) {
        float inv = exp2f(-(float)(2 * (d4 + j)) * (LOG2_10000 / 128.0f));
        sincosf((float)t * inv, &s[j], &c[j]);
    }

    uint32_t h0, l0, h1, l1;
    {
        float4 q1 = *(const float4*)(Q + base + d4);
        float4 q2 = *(const float4*)(Q + base + d4 + 64);
        float a0 = (q1.x * c[0] - q2.x * s[0]) * scale;
        float a1 = (q1.y * c[1] - q2.y * s[1]) * scale;
        float a2 = (q1.z * c[2] - q2.z * s[2]) * scale;
        float a3 = (q1.w * c[3] - q2.w * s[3]) * scale;
        float b0 = (q2.x * c[0] + q1.x * s[0]) * scale;
        float b1 = (q2.y * c[1] + q1.y * s[1]) * scale;
        float b2 = (q2.z * c[2] + q1.z * s[2]) * scale;
        float b3 = (q2.w * c[3] + q1.w * s[3]) * scale;
        bf16_split2(a0, a1, h0, l0); bf16_split2(a2, a3, h1, l1);
        *(uint2*)(Qhi_g + base + d4) = make_uint2(h0, h1);
        *(uint2*)(Qlo_g + base + d4) = make_uint2(l0, l1);
        bf16_split2(b0, b1, h0, l0); bf16_split2(b2, b3, h1, l1);
        *(uint2*)(Qhi_g + base + d4 + 64) = make_uint2(h0, h1);
        *(uint2*)(Qlo_g + base + d4 + 64) = make_uint2(l0, l1);
    }
    {
        float4 k1 = *(const float4*)(K + base + d4);
        float4 k2 = *(const float4*)(K + base + d4 + 64);
        float a0 = k1.x * c[0] - k2.x * s[0];
        float a1 = k1.y * c[1] - k2.y * s[1];
        float a2 = k1.z * c[2] - k2.z * s[2];
        float a3 = k1.w * c[3] - k2.w * s[3];
        float b0 = k2.x * c[0] + k1.x * s[0];
        float b1 = k2.y * c[1] + k1.y * s[1];
        float b2 = k2.z * c[2] + k1.z * s[2];
        float b3 = k2.w * c[3] + k1.w * s[3];
        bf16_split2(a0, a1, h0, l0); bf16_split2(a2, a3, h1, l1);
        *(uint2*)(Khi_g + base + d4) = make_uint2(h0, h1);
        *(uint2*)(Klo_g + base + d4) = make_uint2(l0, l1);
        bf16_split2(b0, b1, h0, l0); bf16_split2(b2, b3, h1, l1);
        *(uint2*)(Khi_g + base + d4 + 64) = make_uint2(h0, h1);
        *(uint2*)(Klo_g + base + d4 + 64) = make_uint2(l0, l1);
    }
    {
        float4 v1 = *(const float4*)(V + base + d4);
        float4 v2 = *(const float4*)(V + base + d4 + 64);
        bf16_split2(v1.x, v1.y, h0, l0); bf16_split2(v1.z, v1.w, h1, l1);
        *(uint2*)(Vhi_g + base + d4) = make_uint2(h0, h1);
        *(uint2*)(Vlo_g + base + d4) = make_uint2(l0, l1);
        bf16_split2(v2.x, v2.y, h0, l0); bf16_split2(v2.z, v2.w, h1, l1);
        *(uint2*)(Vhi_g + base + d4 + 64) = make_uint2(h0, h1);
        *(uint2*)(Vlo_g + base + d4 + 64) = make_uint2(l0, l1);
    }
}

// == TF32 mma GEMM (R9 config): 128 thr, 4 warps (2x2), warp 64x64, 3-stage ==
#define GK 2048
#define GN 2048
#define CSTAGE_F (2 * 128 * 32)
#define GEMM_SMEM (3 * CSTAGE_F * 4)

__device__ __forceinline__ uint32_t sw_word(int row, int chunk) {
    return (uint32_t)(row * 32 + ((chunk ^ ((row & 1) << 2)) << 2));
}

__global__ __launch_bounds__(128) void gemm_perm(const float* __restrict__ A,
                                                 const float* __restrict__ B0, float* __restrict__ C0,
                                                 const float* __restrict__ B1, float* __restrict__ C1,
                                                 const float* __restrict__ B2, float* __restrict__ C2) {
    extern __shared__ float sh[];
    const int z = blockIdx.z;
    const float* Bm = (z == 0) ? B0 : (z == 1) ? B1 : B2;
    float* C = (z == 0) ? C0 : (z == 1) ? C1 : C2;
    const int tid = threadIdx.x;
    const int warp = tid >> 5;
    const int lane = tid & 31;
    const int g = lane >> 2;
    const int t = lane & 3;
    const int warp_m = warp & 1;
    const int warp_n = warp >> 1;
    const int m0 = blockIdx.y * 128;
    const int n0 = blockIdx.x * 128;
    const uint32_t sbase = smem_u32(sh);

    float acc[4][8][4];
#pragma unroll
    for (int mt = 0; mt < 4; mt++)
#pragma unroll
        for (int nt = 0; nt < 8; nt++)
#pragma unroll
            for (int j = 0; j < 4; j++) acc[mt][nt][j] = 0.f;

    const int NIT = GK / 32;

#define GEMM_ISSUE(stage, k0)                                                      \
    do {                                                                           \
        const uint32_t stb = sbase + (stage) * CSTAGE_F * 4;                       \
        _Pragma("unroll")                                                          \
        for (int i_ = 0; i_ < 16; i_++) {                                          \
            int idx = i_ * 128 + tid;                                              \
            int mat = idx >> 10;                                                   \
            int r = (idx >> 3) & 127;                                              \
            int ch = idx & 7;                                                      \
            const float* gp = (mat ? Bm + (size_t)(n0 + r) * GK                    \
                                   : A + (size_t)(m0 + r) * GK) + (k0) + ch * 4;   \
            uint32_t sp = stb + (mat * 128 * 32 + sw_word(r, ch)) * 4;             \
            CP_ASYNC16(sp, gp);                                                    \
        }                                                                          \
        asm volatile("cp.async.commit_group;" ::: "memory");                       \
    } while (0)

    GEMM_ISSUE(0, 0);
    GEMM_ISSUE(1, 32);

    for (int it = 0; it < NIT; it++) {
        if (it + 1 < NIT) asm volatile("cp.async.wait_group 1;" ::: "memory");
        else              asm volatile("cp.async.wait_group 0;" ::: "memory");
        __syncthreads();

        const float* As = sh + (it % 3) * CSTAGE_F;
        const float* Bs = As + 128 * 32;
#pragma unroll
        for (int ks2 = 0; ks2 < 2; ks2++) {
            const int c0 = 4 * ks2 + t;
            float4 alo[4], ahi[4];
#pragma unroll
            for (int mt = 0; mt < 4; mt++) {
                int r0 = warp_m * 64 + mt * 16 + g;
                alo[mt] = *(const float4*)&As[sw_word(r0, c0)];
                ahi[mt] = *(const float4*)&As[sw_word(r0 + 8, c0)];
            }
            float4 bv[8];
#pragma unroll
            for (int nt = 0; nt < 8; nt++) {
                int cn = warp_n * 64 + nt * 8 + g;
                bv[nt] = *(const float4*)&Bs[sw_word(cn, c0)];
            }
#pragma unroll
            for (int mt = 0; mt < 4; mt++) {
                uint32_t af[4] = {__float_as_uint(alo[mt].x), __float_as_uint(ahi[mt].x),
                                  __float_as_uint(alo[mt].y), __float_as_uint(ahi[mt].y)};
#pragma unroll
                for (int nt = 0; nt < 8; nt++)
                    mma_tf32_16n8k8(acc[mt][nt], af,
                                    __float_as_uint(bv[nt].x), __float_as_uint(bv[nt].y));
            }
#pragma unroll
            for (int mt = 0; mt < 4; mt++) {
                uint32_t af[4] = {__float_as_uint(alo[mt].z), __float_as_uint(ahi[mt].z),
                                  __float_as_uint(alo[mt].w), __float_as_uint(ahi[mt].w)};
#pragma unroll
                for (int nt = 0; nt < 8; nt++)
                    mma_tf32_16n8k8(acc[mt][nt], af,
                                    __float_as_uint(bv[nt].z), __float_as_uint(bv[nt].w));
            }
        }

        if (it + 2 < NIT) GEMM_ISSUE((it + 2) % 3, (it + 2) * 32);
    }

#pragma unroll
    for (int mt = 0; mt < 4; mt++) {
        int row = m0 + warp_m * 64 + mt * 16 + g;
#pragma unroll
        for (int nt = 0; nt < 8; nt++) {
            int col = n0 + warp_n * 64 + nt * 8 + 2 * t;
            *(float2*)(C + (size_t)row * GN + col) = make_float2(acc[mt][nt][0], acc[mt][nt][1]);
            *(float2*)(C + (size_t)(row + 8) * GN + col) = make_float2(acc[mt][nt][2], acc[mt][nt][3]);
        }
    }
}

// ===== Flash attention: Q in registers, double-buffered K/V, bf16x3 =====
#define KS 136
#define VS 136
#define PS 72
#define PLANE (64 * KS)                      // 8704 u16 per K/V plane
#define OFF_KV(buf) ((buf) * 4 * PLANE)      // Khi,Klo,Vhi,Vlo per buffer
#define OFF_PHI (8 * PLANE)                  // 69632
#define OFF_PLO (OFF_PHI + 128 * PS)
#define FLASH_SMEM ((OFF_PLO + 128 * PS) * 2)   // 176128 bytes

__global__ __launch_bounds__(256) void flash_bf16(const unsigned short* __restrict__ Qhi_g,
                                                  const unsigned short* __restrict__ Qlo_g,
                                                  const unsigned short* __restrict__ Khi_g,
                                                  const unsigned short* __restrict__ Klo_g,
                                                  const unsigned short* __restrict__ Vhi_g,
                                                  const unsigned short* __restrict__ Vlo_g,
                                                  float* __restrict__ Og) {
    extern __shared__ unsigned short su[];
    unsigned short* Phi = su + OFF_PHI;
    unsigned short* Plo = su + OFF_PLO;

    const int qb = blockIdx.x;
    const int bh = blockIdx.y;
    const int b = bh >> 4, h = bh & 15;
    const int q0 = qb * 128;
    const int tid = threadIdx.x;
    const int warp = tid >> 5;
    const int lane = tid & 31;
    const int g = lane >> 2;
    const int t = lane & 3;
    const float NEG_INF = __int_as_float(0xff800000);

    const int lq = lane >> 3;
    const int lsl = lane & 7;
    const int srow_off = (lq & 1) * 8 + lsl;
    const int dcol_off = (lq >> 1) * 8;
    const uint32_t sbase = smem_u32(su);

    const int rowA = warp * 16 + g;
    const int ntiles = 2 * qb + 2;

    // ---- load Q fragments into registers (loop-invariant) ----
    uint32_t Qh[8][4], Ql[8][4];
    {
        const unsigned short* q0p = Qhi_g + (size_t)(b * T_ + q0 + rowA) * DM + h * HD;
        const unsigned short* q1p = Qlo_g + (size_t)(b * T_ + q0 + rowA) * DM + h * HD;
#pragma unroll
        for (int ks = 0; ks < 8; ks++) {
            const int k16 = ks * 16;
            Qh[ks][0] = *(const uint32_t*)(q0p + k16 + 2 * t);
            Qh[ks][1] = *(const uint32_t*)(q0p + 8 * DM + k16 + 2 * t);
            Qh[ks][2] = *(const uint32_t*)(q0p + k16 + 8 + 2 * t);
            Qh[ks][3] = *(const uint32_t*)(q0p + 8 * DM + k16 + 8 + 2 * t);
            Ql[ks][0] = *(const uint32_t*)(q1p + k16 + 2 * t);
            Ql[ks][1] = *(const uint32_t*)(q1p + 8 * DM + k16 + 2 * t);
            Ql[ks][2] = *(const uint32_t*)(q1p + k16 + 8 + 2 * t);
            Ql[ks][3] = *(const uint32_t*)(q1p + 8 * DM + k16 + 8 + 2 * t);
        }
    }

    float accO[16][4];
#pragma unroll
    for (int nt = 0; nt < 16; nt++)
#pragma unroll
        for (int j = 0; j < 4; j++) accO[nt][j] = 0.f;
    float m0 = -1e30f, m1 = -1e30f, l0s = 0.f, l1s = 0.f;

    // tile loader: K/V hi+lo planes into buffer `dbuf`
#define FLASH_ISSUE(kb_, dbuf)                                                    \
    do {                                                                          \
        const size_t gbase = (size_t)(b * T_ + (kb_) * 64) * DM + h * HD;         \
        const uint32_t kv = sbase + OFF_KV(dbuf) * 2;                             \
        _Pragma("unroll")                                                         \
        for (int i_ = 0; i_ < 4; i_++) {                                          \
            int idx = i_ * 256 + tid;                                             \
            int r = idx >> 4;                                                     \
            int ch = idx & 15;                                                    \
            size_t go = gbase + (size_t)r * DM + ch * 8;                          \
            uint32_t so = (uint32_t)(r * KS + ch * 8) * 2;                        \
            CP_ASYNC16(kv + so, Khi_g + go);                                      \
            CP_ASYNC16(kv + PLANE * 2 + so, Klo_g + go);                          \
            CP_ASYNC16(kv + PLANE * 4 + so, Vhi_g + go);                          \
            CP_ASYNC16(kv + PLANE * 6 + so, Vlo_g + go);                          \
        }                                                                         \
        asm volatile("cp.async.commit_group;" ::: "memory");                      \
    } while (0)

    FLASH_ISSUE(0, 0);

    for (int kb = 0; kb < ntiles; kb++) {
        const int k0 = kb * 64;
        const int buf = kb & 1;
        if (kb + 1 < ntiles) {
            __syncthreads();                 // all warps done with buf^1
            FLASH_ISSUE(kb + 1, buf ^ 1);
            asm volatile("cp.async.wait_group 1;" ::: "memory");
        } else {
            asm volatile("cp.async.wait_group 0;" ::: "memory");
        }
        __syncthreads();

        const unsigned short* Khi = su + OFF_KV(buf);
        const unsigned short* Klo = Khi + PLANE;
        const uint32_t vhi_base = sbase + (OFF_KV(buf) + 2 * PLANE) * 2;
        const uint32_t vlo_base = vhi_base + PLANE * 2;

        // ---- S = Q K^T ----
        float accS[8][4];
#pragma unroll
        for (int nt = 0; nt < 8; nt++)
#pragma unroll
            for (int j = 0; j < 4; j++) accS[nt][j] = 0.f;

#pragma unroll
        for (int ks = 0; ks < 8; ks++) {
            const int k16 = ks * 16;
#pragma unroll
            for (int nt = 0; nt < 8; nt++) {
                int krow = nt * 8 + g;
                uint32_t bh0 = *(uint32_t*)&Khi[krow * KS + k16 + 2 * t];
                uint32_t bh1 = *(uint32_t*)&Khi[krow * KS + k16 + 8 + 2 * t];
                uint32_t bl0 = *(uint32_t*)&Klo[krow * KS + k16 + 2 * t];
                uint32_t bl1 = *(uint32_t*)&Klo[krow * KS + k16 + 8 + 2 * t];
                mma_bf16_16n8k16(accS[nt], Qh[ks], bh0, bh1);
                mma_bf16_16n8k16(accS[nt], Qh[ks], bl0, bl1);
                mma_bf16_16n8k16(accS[nt], Ql[ks], bh0, bh1);
            }
        }

        // ---- mask + online softmax ----
        const int rowg0 = q0 + rowA;
        const int rowg1 = rowg0 + 8;
        const bool chk = (k0 + 63 > q0 + warp * 16);
        float mx0 = NEG_INF, mx1 = NEG_INF;
#pragma unroll
        for (int nt = 0; nt < 8; nt++) {
#pragma unroll
            for (int j = 0; j < 2; j++) {
                int col = k0 + nt * 8 + 2 * t + j;
                float s0 = accS[nt][j];
                float s1 = accS[nt][2 + j];
                if (chk) {
                    if (col > rowg0) s0 = NEG_INF;
                    if (col > rowg1) s1 = NEG_INF;
                }
                accS[nt][j] = s0;
                accS[nt][2 + j] = s1;
                mx0 = fmaxf(mx0, s0);
                mx1 = fmaxf(mx1, s1);
            }
        }
        mx0 = fmaxf(mx0, __shfl_xor_sync(0xffffffffu, mx0, 1));
        mx0 = fmaxf(mx0, __shfl_xor_sync(0xffffffffu, mx0, 2));
        mx1 = fmaxf(mx1, __shfl_xor_sync(0xffffffffu, mx1, 1));
        mx1 = fmaxf(mx1, __shfl_xor_sync(0xffffffffu, mx1, 2));

        float mn0 = fmaxf(m0, mx0), mn1 = fmaxf(m1, mx1);
        float al0 = __expf(m0 - mn0), al1 = __expf(m1 - mn1);
        float rs0 = 0.f, rs1 = 0.f;
#pragma unroll
        for (int nt = 0; nt < 8; nt++) {
            float p00 = __expf(accS[nt][0] - mn0);
            float p01 = __expf(accS[nt][1] - mn0);
            float p10 = __expf(accS[nt][2] - mn1);
            float p11 = __expf(accS[nt][3] - mn1);
            rs0 += p00 + p01;
            rs1 += p10 + p11;
            uint32_t ph, pl;
            bf16_split2(p00, p01, ph, pl);
            *(uint32_t*)&Phi[rowA * PS + nt * 8 + 2 * t] = ph;
            *(uint32_t*)&Plo[rowA * PS + nt * 8 + 2 * t] = pl;
            bf16_split2(p10, p11, ph, pl);
            *(uint32_t*)&Phi[(rowA + 8) * PS + nt * 8 + 2 * t] = ph;
            *(uint32_t*)&Plo[(rowA + 8) * PS + nt * 8 + 2 * t] = pl;
        }
        rs0 += __shfl_xor_sync(0xffffffffu, rs0, 1);
        rs0 += __shfl_xor_sync(0xffffffffu, rs0, 2);
        rs1 += __shfl_xor_sync(0xffffffffu, rs1, 1);
        rs1 += __shfl_xor_sync(0xffffffffu, rs1, 2);
        l0s = l0s * al0 + rs0;
        l1s = l1s * al1 + rs1;
        m0 = mn0;
        m1 = mn1;
#pragma unroll
        for (int nt = 0; nt < 16; nt++) {
            accO[nt][0] *= al0; accO[nt][1] *= al0;
            accO[nt][2] *= al1; accO[nt][3] *= al1;
        }
        __syncwarp();

        // ---- O += P V ----
#pragma unroll
        for (int si = 0; si < 4; si++) {
            const int s16 = si * 16;
            uint32_t pah[4], pal[4];
            pah[0] = *(uint32_t*)&Phi[rowA * PS + s16 + 2 * t];
            pah[1] = *(uint32_t*)&Phi[(rowA + 8) * PS + s16 + 2 * t];
            pah[2] = *(uint32_t*)&Phi[rowA * PS + s16 + 8 + 2 * t];
            pah[3] = *(uint32_t*)&Phi[(rowA + 8) * PS + s16 + 8 + 2 * t];
            pal[0] = *(uint32_t*)&Plo[rowA * PS + s16 + 2 * t];
            pal[1] = *(uint32_t*)&Plo[(rowA + 8) * PS + s16 + 2 * t];
            pal[2] = *(uint32_t*)&Plo[rowA * PS + s16 + 8 + 2 * t];
            pal[3] = *(uint32_t*)&Plo[(rowA + 8) * PS + s16 + 8 + 2 * t];
#pragma unroll
            for (int pr = 0; pr < 8; pr++) {
                uint32_t off = (uint32_t)((s16 + srow_off) * VS + pr * 16 + dcol_off) * 2;
                uint32_t vh0, vh1, vh2, vh3, vl0, vl1, vl2, vl3;
                LDSM_X4_T(vh0, vh1, vh2, vh3, vhi_base + off);
                LDSM_X4_T(vl0, vl1, vl2, vl3, vlo_base + off);
                const int nt0 = 2 * pr, nt1 = 2 * pr + 1;
                mma_bf16_16n8k16(accO[nt0], pah, vh0, vh1);
                mma_bf16_16n8k16(accO[nt0], pah, vl0, vl1);
                mma_bf16_16n8k16(accO[nt0], pal, vh0, vh1);
                mma_bf16_16n8k16(accO[nt1], pah, vh2, vh3);
                mma_bf16_16n8k16(accO[nt1], pah, vl2, vl3);
                mma_bf16_16n8k16(accO[nt1], pal, vh2, vh3);
            }
        }
    }

    // ---- epilogue: normalize + tf32 round + k-permuted scatter ----
    float inv0 = 1.f / l0s, inv1 = 1.f / l1s;
    float* Op = Og + (size_t)(b * T_ + q0 + rowA) * DM + h * HD;
    float* Op8 = Op + (size_t)8 * DM;
#pragma unroll
    for (int nt = 0; nt < 16; nt++) {
#pragma unroll
        for (int j = 0; j < 2; j++) {
            int col = nt * 8 + 2 * t + j;
            int jj = col & 15;
            int p = (col & ~15) + ((jj & 3) << 2) + (jj >> 2);
            Op[p]  = tf32f(accO[nt][j] * inv0);
            Op8[p] = tf32f(accO[nt][2 + j] * inv1);
        }
    }
}

// ============================ launcher ==================================
extern "C" void kernel_launch(void* const* d_in, const int* in_sizes, int n_in,
                              void* d_out, int out_size) {
    const float* x  = (const float*)d_in[0];
    const float* Wq = (const float*)d_in[1];
    const float* Wk = (const float*)d_in[2];
    const float* Wv = (const float*)d_in[3];
    const float* Wo = (const float*)d_in[4];
    float* out = (float*)d_out;

    float *pQ, *pK, *pV, *pA, *pXc, *pWc;
    unsigned short *pQh, *pQl, *pKh, *pKl, *pVh, *pVl;
    cudaGetSymbolAddress((void**)&pQ, g_Q);
    cudaGetSymbolAddress((void**)&pK, g_K);
    cudaGetSymbolAddress((void**)&pV, g_V);
    cudaGetSymbolAddress((void**)&pA, g_A);
    cudaGetSymbolAddress((void**)&pXc, g_xc);
    cudaGetSymbolAddress((void**)&pWc, g_Wc);
    cudaGetSymbolAddress((void**)&pQh, g_Qhi);
    cudaGetSymbolAddress((void**)&pQl, g_Qlo);
    cudaGetSymbolAddress((void**)&pKh, g_Khi);
    cudaGetSymbolAddress((void**)&pKl, g_Klo);
    cudaGetSymbolAddress((void**)&pVh, g_Vhi);
    cudaGetSymbolAddress((void**)&pVl, g_Vlo);
    float* pWqc = pWc;
    float* pWkc = pWc + (size_t)DM * DM;
    float* pWvc = pWc + 2 * (size_t)DM * DM;
    float* pWoc = pWc + 3 * (size_t)DM * DM;

    cudaFuncSetAttribute(gemm_perm, cudaFuncAttributeMaxDynamicSharedMemorySize, GEMM_SMEM);
    cudaFuncSetAttribute(flash_bf16, cudaFuncAttributeMaxDynamicSharedMemorySize, FLASH_SMEM);

    const int NWG = (DM * DM) / 16;        // 262144 groups (x = 2 such slices)
    dim3 ggrid3(DM / 128, NROWS / 128, 3);
    dim3 ggrid1(DM / 128, NROWS / 128, 1);
    dim3 fgrid(T_ / 128, B_ * NH);

    // 5 launches; #4 (flash) is the profiled one.
    cvt_all<<<dim3(NWG / 256, 1, 6), 256>>>(x, Wq, Wk, Wv, Wo, pXc, pWc, NWG);   // 1
    gemm_perm<<<ggrid3, 128, GEMM_SMEM>>>(pXc, pWqc, pQ, pWkc, pK, pWvc, pV);    // 2
    rope_split<<<(NROWS * NH * 16) / 256, 256>>>(pQ, pK, pV,
                                                 pQh, pQl, pKh, pKl, pVh, pVl);  // 3
    flash_bf16<<<fgrid, 256, FLASH_SMEM>>>(pQh, pQl, pKh, pKl, pVh, pVl, pA);    // 4
    gemm_perm<<<ggrid1, 128, GEMM_SMEM>>>(pA, pWoc, out, pWoc, out, pWoc, out);  // 5
}

// round 14
// speedup vs baseline: 1.2701x; 1.0223x over previous
#include <cuda_runtime.h>
#include <cuda_bf16.h>
#include <math.h>
#include <stdint.h>

#define B_  2
#define T_  2048
#define DM  2048
#define NH  16
#define HD  128
#define NROWS (B_ * T_)   // 4096

// ---------------- scratch (no runtime allocation allowed) ----------------
__device__ float g_Q[(size_t)NROWS * DM];
__device__ float g_K[(size_t)NROWS * DM];
__device__ float g_V[(size_t)NROWS * DM];
__device__ float g_A[(size_t)NROWS * DM];
__device__ float g_xc[(size_t)NROWS * DM];          // tf32-rounded, k-permuted x
__device__ float g_Wc[4][(size_t)DM * DM];          // tf32-rounded, k-permuted W
// pre-split bf16 planes for attention
__device__ unsigned short g_Qhi[(size_t)NROWS * DM];
__device__ unsigned short g_Qlo[(size_t)NROWS * DM];
__device__ unsigned short g_Khi[(size_t)NROWS * DM];
__device__ unsigned short g_Klo[(size_t)NROWS * DM];
__device__ unsigned short g_Vhi[(size_t)NROWS * DM];
__device__ unsigned short g_Vlo[(size_t)NROWS * DM];

__device__ __forceinline__ uint32_t f2tf32(float x) {
    uint32_t r;
    asm("cvt.rna.tf32.f32 %0, %1;" : "=r"(r) : "f"(x));
    return r;
}
__device__ __forceinline__ float tf32f(float x) { return __uint_as_float(f2tf32(x)); }

__device__ __forceinline__ uint32_t smem_u32(const void* p) {
    uint32_t a;
    asm("{ .reg .u64 t; cvta.to.shared.u64 t, %1; cvt.u32.u64 %0, t; }" : "=r"(a) : "l"(p));
    return a;
}

__device__ __forceinline__ void mma_tf32_16n8k8(float c[4], const uint32_t a[4],
                                                const uint32_t b0, const uint32_t b1) {
    asm volatile(
        "mma.sync.aligned.m16n8k8.row.col.f32.tf32.tf32.f32 "
        "{%0,%1,%2,%3}, {%4,%5,%6,%7}, {%8,%9}, {%0,%1,%2,%3};"
        : "+f"(c[0]), "+f"(c[1]), "+f"(c[2]), "+f"(c[3])
        : "r"(a[0]), "r"(a[1]), "r"(a[2]), "r"(a[3]), "r"(b0), "r"(b1));
}

__device__ __forceinline__ void mma_bf16_16n8k16(float c[4], const uint32_t a[4],
                                                 const uint32_t b0, const uint32_t b1) {
    asm volatile(
        "mma.sync.aligned.m16n8k16.row.col.f32.bf16.bf16.f32 "
        "{%0,%1,%2,%3}, {%4,%5,%6,%7}, {%8,%9}, {%0,%1,%2,%3};"
        : "+f"(c[0]), "+f"(c[1]), "+f"(c[2]), "+f"(c[3])
        : "r"(a[0]), "r"(a[1]), "r"(a[2]), "r"(a[3]), "r"(b0), "r"(b1));
}

__device__ __forceinline__ void bf16_split2(float x, float y, uint32_t& hi, uint32_t& lo) {
    __nv_bfloat16 hx = __float2bfloat16(x);
    __nv_bfloat16 hy = __float2bfloat16(y);
    __nv_bfloat16 lx = __float2bfloat16(x - __bfloat162float(hx));
    __nv_bfloat16 ly = __float2bfloat16(y - __bfloat162float(hy));
    hi = (uint32_t)__bfloat16_as_ushort(hx) | ((uint32_t)__bfloat16_as_ushort(hy) << 16);
    lo = (uint32_t)__bfloat16_as_ushort(lx) | ((uint32_t)__bfloat16_as_ushort(ly) << 16);
}

#define LDSM_X4_T(r0, r1, r2, r3, addr) \
    asm volatile("ldmatrix.sync.aligned.m8n8.x4.trans.shared.b16 {%0,%1,%2,%3}, [%4];" \
                 : "=r"(r0), "=r"(r1), "=r"(r2), "=r"(r3) : "r"(addr))

#define CP_ASYNC16(sp, gp) \
    asm volatile("cp.async.cg.shared.global [%0], [%1], 16;" :: "r"(sp), "l"(gp))

// ==== tf32 round + k-permute, batched over x (2 halves) + 4 weights ======
__global__ __launch_bounds__(256) void cvt_all(const float* __restrict__ x,
                                               const float* __restrict__ w0,
                                               const float* __restrict__ w1,
                                               const float* __restrict__ w2,
                                               const float* __restrict__ w3,
                                               float* __restrict__ xout,
                                               float* __restrict__ wout, int ngroups) {
    int z = blockIdx.z;
    const float* in;
    float* out;
    if (z < 2) {
        in = x + (size_t)z * ngroups * 16;
        out = xout + (size_t)z * ngroups * 16;
    } else {
        int w = z - 2;
        in = (w == 0) ? w0 : (w == 1) ? w1 : (w == 2) ? w2 : w3;
        out = wout + (size_t)w * DM * DM;
    }
    int i = blockIdx.x * 256 + threadIdx.x;
    if (i < ngroups) {
        const float4* ip = (const float4*)(in + (size_t)i * 16);
        float4 v0 = ip[0], v1 = ip[1], v2 = ip[2], v3 = ip[3];
        float4* op = (float4*)(out + (size_t)i * 16);
        op[0] = make_float4(tf32f(v0.x), tf32f(v1.x), tf32f(v2.x), tf32f(v3.x));
        op[1] = make_float4(tf32f(v0.y), tf32f(v1.y), tf32f(v2.y), tf32f(v3.y));
        op[2] = make_float4(tf32f(v0.z), tf32f(v1.z), tf32f(v2.z), tf32f(v3.z));
        op[3] = make_float4(tf32f(v0.w), tf32f(v1.w), tf32f(v2.w), tf32f(v3.w));
    }
}

// ======== fused RoPE + bf16 hi/lo split of Q (scaled), K, V ==============
__global__ __launch_bounds__(256) void rope_split(const float* __restrict__ Q,
                                                  const float* __restrict__ K,
                                                  const float* __restrict__ V,
                                                  unsigned short* __restrict__ Qhi_g,
                                                  unsigned short* __restrict__ Qlo_g,
                                                  unsigned short* __restrict__ Khi_g,
                                                  unsigned short* __restrict__ Klo_g,
                                                  unsigned short* __restrict__ Vhi_g,
                                                  unsigned short* __restrict__ Vlo_g) {
    const float scale = 0.08838834764831845f;
    const float LOG2_10000 = 13.287712379549449f;
    int idx = blockIdx.x * 256 + threadIdx.x;        // < NROWS*NH*16
    int d4 = (idx & 15) * 4;
    int h = (idx >> 4) & (NH - 1);
    int n = idx >> 8;
    int t = n & (T_ - 1);
    size_t base = (size_t)n * DM + h * HD;

    float c[4], s[4];
#pragma unroll
    for (int j = 0; j < 4; j++) {
        float inv = exp2f(-(float)(2 * (d4 + j)) * (LOG2_10000 / 128.0f));
        sincosf((float)t * inv, &s[j], &c[j]);
    }

    uint32_t h0, l0, h1, l1;
    {
        float4 q1 = *(const float4*)(Q + base + d4);
        float4 q2 = *(const float4*)(Q + base + d4 + 64);
        float a0 = (q1.x * c[0] - q2.x * s[0]) * scale;
        float a1 = (q1.y * c[1] - q2.y * s[1]) * scale;
        float a2 = (q1.z * c[2] - q2.z * s[2]) * scale;
        float a3 = (q1.w * c[3] - q2.w * s[3]) * scale;
        float b0 = (q2.x * c[0] + q1.x * s[0]) * scale;
        float b1 = (q2.y * c[1] + q1.y * s[1]) * scale;
        float b2 = (q2.z * c[2] + q1.z * s[2]) * scale;
        float b3 = (q2.w * c[3] + q1.w * s[3]) * scale;
        bf16_split2(a0, a1, h0, l0); bf16_split2(a2, a3, h1, l1);
        *(uint2*)(Qhi_g + base + d4) = make_uint2(h0, h1);
        *(uint2*)(Qlo_g + base + d4) = make_uint2(l0, l1);
        bf16_split2(b0, b1, h0, l0); bf16_split2(b2, b3, h1, l1);
        *(uint2*)(Qhi_g + base + d4 + 64) = make_uint2(h0, h1);
        *(uint2*)(Qlo_g + base + d4 + 64) = make_uint2(l0, l1);
    }
    {
        float4 k1 = *(const float4*)(K + base + d4);
        float4 k2 = *(const float4*)(K + base + d4 + 64);
        float a0 = k1.x * c[0] - k2.x * s[0];
        float a1 = k1.y * c[1] - k2.y * s[1];
        float a2 = k1.z * c[2] - k2.z * s[2];
        float a3 = k1.w * c[3] - k2.w * s[3];
        float b0 = k2.x * c[0] + k1.x * s[0];
        float b1 = k2.y * c[1] + k1.y * s[1];
        float b2 = k2.z * c[2] + k1.z * s[2];
        float b3 = k2.w * c[3] + k1.w * s[3];
        bf16_split2(a0, a1, h0, l0); bf16_split2(a2, a3, h1, l1);
        *(uint2*)(Khi_g + base + d4) = make_uint2(h0, h1);
        *(uint2*)(Klo_g + base + d4) = make_uint2(l0, l1);
        bf16_split2(b0, b1, h0, l0); bf16_split2(b2, b3, h1, l1);
        *(uint2*)(Khi_g + base + d4 + 64) = make_uint2(h0, h1);
        *(uint2*)(Klo_g + base + d4 + 64) = make_uint2(l0, l1);
    }
    {
        float4 v1 = *(const float4*)(V + base + d4);
        float4 v2 = *(const float4*)(V + base + d4 + 64);
        bf16_split2(v1.x, v1.y, h0, l0); bf16_split2(v1.z, v1.w, h1, l1);
        *(uint2*)(Vhi_g + base + d4) = make_uint2(h0, h1);
        *(uint2*)(Vlo_g + base + d4) = make_uint2(l0, l1);
        bf16_split2(v2.x, v2.y, h0, l0); bf16_split2(v2.z, v2.w, h1, l1);
        *(uint2*)(Vhi_g + base + d4 + 64) = make_uint2(h0, h1);
        *(uint2*)(Vlo_g + base + d4 + 64) = make_uint2(l0, l1);
    }
}

// == TF32 mma GEMM (R9 config): 128 thr, 4 warps (2x2), warp 64x64, 3-stage ==
#define GK 2048
#define GN 2048
#define CSTAGE_F (2 * 128 * 32)
#define GEMM_SMEM (3 * CSTAGE_F * 4)

__device__ __forceinline__ uint32_t sw_word(int row, int chunk) {
    return (uint32_t)(row * 32 + ((chunk ^ ((row & 1) << 2)) << 2));
}

__global__ __launch_bounds__(128) void gemm_perm(const float* __restrict__ A,
                                                 const float* __restrict__ B0, float* __restrict__ C0,
                                                 const float* __restrict__ B1, float* __restrict__ C1,
                                                 const float* __restrict__ B2, float* __restrict__ C2) {
    extern __shared__ float sh[];
    const int z = blockIdx.z;
    const float* Bm = (z == 0) ? B0 : (z == 1) ? B1 : B2;
    float* C = (z == 0) ? C0 : (z == 1) ? C1 : C2;
    const int tid = threadIdx.x;
    const int warp = tid >> 5;
    const int lane = tid & 31;
    const int g = lane >> 2;
    const int t = lane & 3;
    const int warp_m = warp & 1;
    const int warp_n = warp >> 1;
    const int m0 = blockIdx.y * 128;
    const int n0 = blockIdx.x * 128;
    const uint32_t sbase = smem_u32(sh);

    float acc[4][8][4];
#pragma unroll
    for (int mt = 0; mt < 4; mt++)
#pragma unroll
        for (int nt = 0; nt < 8; nt++)
#pragma unroll
            for (int j = 0; j < 4; j++) acc[mt][nt][j] = 0.f;

    const int NIT = GK / 32;

#define GEMM_ISSUE(stage, k0)                                                      \
    do {                                                                           \
        const uint32_t stb = sbase + (stage) * CSTAGE_F * 4;                       \
        _Pragma("unroll")                                                          \
        for (int i_ = 0; i_ < 16; i_++) {                                          \
            int idx = i_ * 128 + tid;                                              \
            int mat = idx >> 10;                                                   \
            int r = (idx >> 3) & 127;                                              \
            int ch = idx & 7;                                                      \
            const float* gp = (mat ? Bm + (size_t)(n0 + r) * GK                    \
                                   : A + (size_t)(m0 + r) * GK) + (k0) + ch * 4;   \
            uint32_t sp = stb + (mat * 128 * 32 + sw_word(r, ch)) * 4;             \
            CP_ASYNC16(sp, gp);                                                    \
        }                                                                          \
        asm volatile("cp.async.commit_group;" ::: "memory");                       \
    } while (0)

    GEMM_ISSUE(0, 0);
    GEMM_ISSUE(1, 32);

    for (int it = 0; it < NIT; it++) {
        if (it + 1 < NIT) asm volatile("cp.async.wait_group 1;" ::: "memory");
        else              asm volatile("cp.async.wait_group 0;" ::: "memory");
        __syncthreads();

        const float* As = sh + (it % 3) * CSTAGE_F;
        const float* Bs = As + 128 * 32;
#pragma unroll
        for (int ks2 = 0; ks2 < 2; ks2++) {
            const int c0 = 4 * ks2 + t;
            float4 alo[4], ahi[4];
#pragma unroll
            for (int mt = 0; mt < 4; mt++) {
                int r0 = warp_m * 64 + mt * 16 + g;
                alo[mt] = *(const float4*)&As[sw_word(r0, c0)];
                ahi[mt] = *(const float4*)&As[sw_word(r0 + 8, c0)];
            }
            float4 bv[8];
#pragma unroll
            for (int nt = 0; nt < 8; nt++) {
                int cn = warp_n * 64 + nt * 8 + g;
                bv[nt] = *(const float4*)&Bs[sw_word(cn, c0)];
            }
#pragma unroll
            for (int mt = 0; mt < 4; mt++) {
                uint32_t af[4] = {__float_as_uint(alo[mt].x), __float_as_uint(ahi[mt].x),
                                  __float_as_uint(alo[mt].y), __float_as_uint(ahi[mt].y)};
#pragma unroll
                for (int nt = 0; nt < 8; nt++)
                    mma_tf32_16n8k8(acc[mt][nt], af,
                                    __float_as_uint(bv[nt].x), __float_as_uint(bv[nt].y));
            }
#pragma unroll
            for (int mt = 0; mt < 4; mt++) {
                uint32_t af[4] = {__float_as_uint(alo[mt].z), __float_as_uint(ahi[mt].z),
                                  __float_as_uint(alo[mt].w), __float_as_uint(ahi[mt].w)};
#pragma unroll
                for (int nt = 0; nt < 8; nt++)
                    mma_tf32_16n8k8(acc[mt][nt], af,
                                    __float_as_uint(bv[nt].z), __float_as_uint(bv[nt].w));
            }
        }

        if (it + 2 < NIT) GEMM_ISSUE((it + 2) % 3, (it + 2) * 32);
    }

#pragma unroll
    for (int mt = 0; mt < 4; mt++) {
        int row = m0 + warp_m * 64 + mt * 16 + g;
#pragma unroll
        for (int nt = 0; nt < 8; nt++) {
            int col = n0 + warp_n * 64 + nt * 8 + 2 * t;
            *(float2*)(C + (size_t)row * GN + col) = make_float2(acc[mt][nt][0], acc[mt][nt][1]);
            *(float2*)(C + (size_t)(row + 8) * GN + col) = make_float2(acc[mt][nt][2], acc[mt][nt][3]);
        }
    }
}

// ===== Flash attention: 64-row CTA, 4 warps, 2 CTAs/SM, split K/V prefetch =====
#define KS 136
#define VS 136
#define PS 72
#define PLANE (64 * KS)                      // 8704 u16 per plane
#define OFF_PHI (4 * PLANE)                  // after Khi,Klo,Vhi,Vlo
#define OFF_PLO (OFF_PHI + 64 * PS)
#define FLASH_SMEM ((OFF_PLO + 64 * PS) * 2)    // 88064 bytes

__global__ __launch_bounds__(128, 2) void flash_bf16(const unsigned short* __restrict__ Qhi_g,
                                                     const unsigned short* __restrict__ Qlo_g,
                                                     const unsigned short* __restrict__ Khi_g,
                                                     const unsigned short* __restrict__ Klo_g,
                                                     const unsigned short* __restrict__ Vhi_g,
                                                     const unsigned short* __restrict__ Vlo_g,
                                                     float* __restrict__ Og) {
    extern __shared__ unsigned short su[];
    unsigned short* Khi = su;
    unsigned short* Klo = su + PLANE;
    unsigned short* Phi = su + OFF_PHI;
    unsigned short* Plo = su + OFF_PLO;

    const int qb = blockIdx.x;
    const int bh = blockIdx.y;
    const int b = bh >> 4, h = bh & 15;
    const int q0 = qb * 64;
    const int tid = threadIdx.x;
    const int warp = tid >> 5;
    const int lane = tid & 31;
    const int g = lane >> 2;
    const int t = lane & 3;
    const float NEG_INF = __int_as_float(0xff800000);

    const int lq = lane >> 3;
    const int lsl = lane & 7;
    const int srow_off = (lq & 1) * 8 + lsl;
    const int dcol_off = (lq >> 1) * 8;
    const uint32_t sbase = smem_u32(su);
    const uint32_t vhi_base = sbase + 2 * PLANE * 2;
    const uint32_t vlo_base = sbase + 3 * PLANE * 2;

    const int rowA = warp * 16 + g;
    const int ntiles = qb + 1;

    // ---- load Q fragments into registers (loop-invariant) ----
    uint32_t Qh[8][4], Ql[8][4];
    {
        const unsigned short* q0p = Qhi_g + (size_t)(b * T_ + q0 + rowA) * DM + h * HD;
        const unsigned short* q1p = Qlo_g + (size_t)(b * T_ + q0 + rowA) * DM + h * HD;
#pragma unroll
        for (int ks = 0; ks < 8; ks++) {
            const int k16 = ks * 16;
            Qh[ks][0] = *(const uint32_t*)(q0p + k16 + 2 * t);
            Qh[ks][1] = *(const uint32_t*)(q0p + 8 * DM + k16 + 2 * t);
            Qh[ks][2] = *(const uint32_t*)(q0p + k16 + 8 + 2 * t);
            Qh[ks][3] = *(const uint32_t*)(q0p + 8 * DM + k16 + 8 + 2 * t);
            Ql[ks][0] = *(const uint32_t*)(q1p + k16 + 2 * t);
            Ql[ks][1] = *(const uint32_t*)(q1p + 8 * DM + k16 + 2 * t);
            Ql[ks][2] = *(const uint32_t*)(q1p + k16 + 8 + 2 * t);
            Ql[ks][3] = *(const uint32_t*)(q1p + 8 * DM + k16 + 8 + 2 * t);
        }
    }

    float accO[16][4];
#pragma unroll
    for (int nt = 0; nt < 16; nt++)
#pragma unroll
        for (int j = 0; j < 4; j++) accO[nt][j] = 0.f;
    float m0 = -1e30f, m1 = -1e30f, l0s = 0.f, l1s = 0.f;

    // plane loaders: 64 rows x 16 chunks = 1024 16B-chunks per plane, 128 thr
#define ISSUE_K(kb_)                                                              \
    do {                                                                          \
        const size_t gbase = (size_t)(b * T_ + (kb_) * 64) * DM + h * HD;         \
        _Pragma("unroll")                                                         \
        for (int i_ = 0; i_ < 8; i_++) {                                          \
            int idx = i_ * 128 + tid;                                             \
            int r = idx >> 4;                                                     \
            int ch = idx & 15;                                                    \
            size_t go = gbase + (size_t)r * DM + ch * 8;                          \
            uint32_t so = (uint32_t)(r * KS + ch * 8) * 2;                        \
            CP_ASYNC16(sbase + so, Khi_g + go);                                   \
            CP_ASYNC16(sbase + PLANE * 2 + so, Klo_g + go);                       \
        }                                                                         \
        asm volatile("cp.async.commit_group;" ::: "memory");                      \
    } while (0)

#define ISSUE_V(kb_)                                                              \
    do {                                                                          \
        const size_t gbase = (size_t)(b * T_ + (kb_) * 64) * DM + h * HD;         \
        _Pragma("unroll")                                                         \
        for (int i_ = 0; i_ < 8; i_++) {                                          \
            int idx = i_ * 128 + tid;                                             \
            int r = idx >> 4;                                                     \
            int ch = idx & 15;                                                    \
            size_t go = gbase + (size_t)r * DM + ch * 8;                          \
            uint32_t so = (uint32_t)(r * KS + ch * 8) * 2;                        \
            CP_ASYNC16(sbase + PLANE * 4 + so, Vhi_g + go);                       \
            CP_ASYNC16(sbase + PLANE * 6 + so, Vlo_g + go);                       \
        }                                                                         \
        asm volatile("cp.async.commit_group;" ::: "memory");                      \
    } while (0)

    ISSUE_K(0);
    ISSUE_V(0);
    // loop invariant entering iter kb: pending groups = { K(kb or kb+1 tail), V(kb) } as managed below

    for (int kb = 0; kb < ntiles; kb++) {
        const int k0 = kb * 64;
        // wait for K(kb): it is the oldest pending group (pending: K(kb), V(kb))
        asm volatile("cp.async.wait_group 1;" ::: "memory");
        __syncthreads();

        // ---- S = Q K^T ----
        float accS[8][4];
#pragma unroll
        for (int nt = 0; nt < 8; nt++)
#pragma unroll
            for (int j = 0; j < 4; j++) accS[nt][j] = 0.f;

#pragma unroll
        for (int ks = 0; ks < 8; ks++) {
            const int k16 = ks * 16;
#pragma unroll
            for (int nt = 0; nt < 8; nt++) {
                int krow = nt * 8 + g;
                uint32_t bh0 = *(uint32_t*)&Khi[krow * KS + k16 + 2 * t];
                uint32_t bh1 = *(uint32_t*)&Khi[krow * KS + k16 + 8 + 2 * t];
                uint32_t bl0 = *(uint32_t*)&Klo[krow * KS + k16 + 2 * t];
                uint32_t bl1 = *(uint32_t*)&Klo[krow * KS + k16 + 8 + 2 * t];
                mma_bf16_16n8k16(accS[nt], Qh[ks], bh0, bh1);
                mma_bf16_16n8k16(accS[nt], Qh[ks], bl0, bl1);
                mma_bf16_16n8k16(accS[nt], Ql[ks], bh0, bh1);
            }
        }
        __syncthreads();                      // all warps done reading K planes
        if (kb + 1 < ntiles) ISSUE_K(kb + 1); // overlaps softmax + PV; pending: V(kb), K(kb+1)

        // ---- mask + online softmax ----
        const int rowg0 = q0 + rowA;
        const int rowg1 = rowg0 + 8;
        const bool chk = (k0 + 63 > q0 + warp * 16);
        float mx0 = NEG_INF, mx1 = NEG_INF;
#pragma unroll
        for (int nt = 0; nt < 8; nt++) {
#pragma unroll
            for (int j = 0; j < 2; j++) {
                int col = k0 + nt * 8 + 2 * t + j;
                float s0 = accS[nt][j];
                float s1 = accS[nt][2 + j];
                if (chk) {
                    if (col > rowg0) s0 = NEG_INF;
                    if (col > rowg1) s1 = NEG_INF;
                }
                accS[nt][j] = s0;
                accS[nt][2 + j] = s1;
                mx0 = fmaxf(mx0, s0);
                mx1 = fmaxf(mx1, s1);
            }
        }
        mx0 = fmaxf(mx0, __shfl_xor_sync(0xffffffffu, mx0, 1));
        mx0 = fmaxf(mx0, __shfl_xor_sync(0xffffffffu, mx0, 2));
        mx1 = fmaxf(mx1, __shfl_xor_sync(0xffffffffu, mx1, 1));
        mx1 = fmaxf(mx1, __shfl_xor_sync(0xffffffffu, mx1, 2));

        float mn0 = fmaxf(m0, mx0), mn1 = fmaxf(m1, mx1);
        float al0 = __expf(m0 - mn0), al1 = __expf(m1 - mn1);
        float rs0 = 0.f, rs1 = 0.f;
#pragma unroll
        for (int nt = 0; nt < 8; nt++) {
            float p00 = __expf(accS[nt][0] - mn0);
            float p01 = __expf(accS[nt][1] - mn0);
            float p10 = __expf(accS[nt][2] - mn1);
            float p11 = __expf(accS[nt][3] - mn1);
            rs0 += p00 + p01;
            rs1 += p10 + p11;
            uint32_t ph, pl;
            bf16_split2(p00, p01, ph, pl);
            *(uint32_t*)&Phi[rowA * PS + nt * 8 + 2 * t] = ph;
            *(uint32_t*)&Plo[rowA * PS + nt * 8 + 2 * t] = pl;
            bf16_split2(p10, p11, ph, pl);
            *(uint32_t*)&Phi[(rowA + 8) * PS + nt * 8 + 2 * t] = ph;
            *(uint32_t*)&Plo[(rowA + 8) * PS + nt * 8 + 2 * t] = pl;
        }
        rs0 += __shfl_xor_sync(0xffffffffu, rs0, 1);
        rs0 += __shfl_xor_sync(0xffffffffu, rs0, 2);
        rs1 += __shfl_xor_sync(0xffffffffu, rs1, 1);
        rs1 += __shfl_xor_sync(0xffffffffu, rs1, 2);
        l0s = l0s * al0 + rs0;
        l1s = l1s * al1 + rs1;
        m0 = mn0;
        m1 = mn1;
#pragma unroll
        for (int nt = 0; nt < 16; nt++) {
            accO[nt][0] *= al0; accO[nt][1] *= al0;
            accO[nt][2] *= al1; accO[nt][3] *= al1;
        }
        __syncwarp();

        // wait for V(kb): oldest pending group. If K(kb+1) was issued, allow it pending.
        if (kb + 1 < ntiles) asm volatile("cp.async.wait_group 1;" ::: "memory");
        else                 asm volatile("cp.async.wait_group 0;" ::: "memory");
        __syncthreads();                      // V visible to all warps

        // ---- O += P V ----
#pragma unroll
        for (int si = 0; si < 4; si++) {
            const int s16 = si * 16;
            uint32_t pah[4], pal[4];
            pah[0] = *(uint32_t*)&Phi[rowA * PS + s16 + 2 * t];
            pah[1] = *(uint32_t*)&Phi[(rowA + 8) * PS + s16 + 2 * t];
            pah[2] = *(uint32_t*)&Phi[rowA * PS + s16 + 8 + 2 * t];
            pah[3] = *(uint32_t*)&Phi[(rowA + 8) * PS + s16 + 8 + 2 * t];
            pal[0] = *(uint32_t*)&Plo[rowA * PS + s16 + 2 * t];
            pal[1] = *(uint32_t*)&Plo[(rowA + 8) * PS + s16 + 2 * t];
            pal[2] = *(uint32_t*)&Plo[rowA * PS + s16 + 8 + 2 * t];
            pal[3] = *(uint32_t*)&Plo[(rowA + 8) * PS + s16 + 8 + 2 * t];
#pragma unroll
            for (int pr = 0; pr < 8; pr++) {
                uint32_t off = (uint32_t)((s16 + srow_off) * VS + pr * 16 + dcol_off) * 2;
                uint32_t vh0, vh1, vh2, vh3, vl0, vl1, vl2, vl3;
                LDSM_X4_T(vh0, vh1, vh2, vh3, vhi_base + off);
                LDSM_X4_T(vl0, vl1, vl2, vl3, vlo_base + off);
                const int nt0 = 2 * pr, nt1 = 2 * pr + 1;
                mma_bf16_16n8k16(accO[nt0], pah, vh0, vh1);
                mma_bf16_16n8k16(accO[nt0], pah, vl0, vl1);
                mma_bf16_16n8k16(accO[nt0], pal, vh0, vh1);
                mma_bf16_16n8k16(accO[nt1], pah, vh2, vh3);
                mma_bf16_16n8k16(accO[nt1], pah, vl2, vl3);
                mma_bf16_16n8k16(accO[nt1], pal, vh2, vh3);
            }
        }
        __syncthreads();                      // all warps done reading V planes
        if (kb + 1 < ntiles) ISSUE_V(kb + 1); // pending: K(kb+1), V(kb+1)
    }

    // ---- epilogue: normalize + tf32 round + k-permuted scatter ----
    float inv0 = 1.f / l0s, inv1 = 1.f / l1s;
    float* Op = Og + (size_t)(b * T_ + q0 + rowA) * DM + h * HD;
    float* Op8 = Op + (size_t)8 * DM;
#pragma unroll
    for (int nt = 0; nt < 16; nt++) {
#pragma unroll
        for (int j = 0; j < 2; j++) {
            int col = nt * 8 + 2 * t + j;
            int jj = col & 15;
            int p = (col & ~15) + ((jj & 3) << 2) + (jj >> 2);
            Op[p]  = tf32f(accO[nt][j] * inv0);
            Op8[p] = tf32f(accO[nt][2 + j] * inv1);
        }
    }
}

// ============================ launcher ==================================
extern "C" void kernel_launch(void* const* d_in, const int* in_sizes, int n_in,
                              void* d_out, int out_size) {
    const float* x  = (const float*)d_in[0];
    const float* Wq = (const float*)d_in[1];
    const float* Wk = (const float*)d_in[2];
    const float* Wv = (const float*)d_in[3];
    const float* Wo = (const float*)d_in[4];
    float* out = (float*)d_out;

    float *pQ, *pK, *pV, *pA, *pXc, *pWc;
    unsigned short *pQh, *pQl, *pKh, *pKl, *pVh, *pVl;
    cudaGetSymbolAddress((void**)&pQ, g_Q);
    cudaGetSymbolAddress((void**)&pK, g_K);
    cudaGetSymbolAddress((void**)&pV, g_V);
    cudaGetSymbolAddress((void**)&pA, g_A);
    cudaGetSymbolAddress((void**)&pXc, g_xc);
    cudaGetSymbolAddress((void**)&pWc, g_Wc);
    cudaGetSymbolAddress((void**)&pQh, g_Qhi);
    cudaGetSymbolAddress((void**)&pQl, g_Qlo);
    cudaGetSymbolAddress((void**)&pKh, g_Khi);
    cudaGetSymbolAddress((void**)&pKl, g_Klo);
    cudaGetSymbolAddress((void**)&pVh, g_Vhi);
    cudaGetSymbolAddress((void**)&pVl, g_Vlo);
    float* pWqc = pWc;
    float* pWkc = pWc + (size_t)DM * DM;
    float* pWvc = pWc + 2 * (size_t)DM * DM;
    float* pWoc = pWc + 3 * (size_t)DM * DM;

    cudaFuncSetAttribute(gemm_perm, cudaFuncAttributeMaxDynamicSharedMemorySize, GEMM_SMEM);
    cudaFuncSetAttribute(flash_bf16, cudaFuncAttributeMaxDynamicSharedMemorySize, FLASH_SMEM);

    const int NWG = (DM * DM) / 16;
    dim3 ggrid3(DM / 128, NROWS / 128, 3);
    dim3 ggrid1(DM / 128, NROWS / 128, 1);
    dim3 fgrid(T_ / 64, B_ * NH);          // (32, 32) = 1024 CTAs

    // 5 launches; #4 (flash) is the profiled one.
    cvt_all<<<dim3(NWG / 256, 1, 6), 256>>>(x, Wq, Wk, Wv, Wo, pXc, pWc, NWG);   // 1
    gemm_perm<<<ggrid3, 128, GEMM_SMEM>>>(pXc, pWqc, pQ, pWkc, pK, pWvc, pV);    // 2
    rope_split<<<(NROWS * NH * 16) / 256, 256>>>(pQ, pK, pV,
                                                 pQh, pQl, pKh, pKl, pVh, pVl);  // 3
    flash_bf16<<<fgrid, 128, FLASH_SMEM>>>(pQh, pQl, pKh, pKl, pVh, pVl, pA);    // 4
    gemm_perm<<<ggrid1, 128, GEMM_SMEM>>>(pA, pWoc, out, pWoc, out, pWoc, out);  // 5
}

// round 15
// speedup vs baseline: 1.2976x; 1.0217x over previous
#include <cuda_runtime.h>
#include <cuda_bf16.h>
#include <math.h>
#include <stdint.h>

#define B_  2
#define T_  2048
#define DM  2048
#define NH  16
#define HD  128
#define NROWS (B_ * T_)   // 4096

// ---------------- scratch (no runtime allocation allowed) ----------------
__device__ float g_Q[(size_t)NROWS * DM];
__device__ float g_K[(size_t)NROWS * DM];
__device__ float g_V[(size_t)NROWS * DM];
__device__ float g_A[(size_t)NROWS * DM];
__device__ float g_xc[(size_t)NROWS * DM];
__device__ float g_Wc[4][(size_t)DM * DM];
__device__ unsigned short g_Qhi[(size_t)NROWS * DM];
__device__ unsigned short g_Qlo[(size_t)NROWS * DM];
__device__ unsigned short g_Khi[(size_t)NROWS * DM];
__device__ unsigned short g_Klo[(size_t)NROWS * DM];
__device__ unsigned short g_Vhi[(size_t)NROWS * DM];
__device__ unsigned short g_Vlo[(size_t)NROWS * DM];

__device__ __forceinline__ uint32_t f2tf32(float x) {
    uint32_t r;
    asm("cvt.rna.tf32.f32 %0, %1;" : "=r"(r) : "f"(x));
    return r;
}
__device__ __forceinline__ float tf32f(float x) { return __uint_as_float(f2tf32(x)); }

__device__ __forceinline__ uint32_t smem_u32(const void* p) {
    uint32_t a;
    asm("{ .reg .u64 t; cvta.to.shared.u64 t, %1; cvt.u32.u64 %0, t; }" : "=r"(a) : "l"(p));
    return a;
}

__device__ __forceinline__ void mma_tf32_16n8k8(float c[4], const uint32_t a[4],
                                                const uint32_t b0, const uint32_t b1) {
    asm volatile(
        "mma.sync.aligned.m16n8k8.row.col.f32.tf32.tf32.f32 "
        "{%0,%1,%2,%3}, {%4,%5,%6,%7}, {%8,%9}, {%0,%1,%2,%3};"
        : "+f"(c[0]), "+f"(c[1]), "+f"(c[2]), "+f"(c[3])
        : "r"(a[0]), "r"(a[1]), "r"(a[2]), "r"(a[3]), "r"(b0), "r"(b1));
}

__device__ __forceinline__ void mma_bf16_16n8k16(float c[4], const uint32_t a[4],
                                                 const uint32_t b0, const uint32_t b1) {
    asm volatile(
        "mma.sync.aligned.m16n8k16.row.col.f32.bf16.bf16.f32 "
        "{%0,%1,%2,%3}, {%4,%5,%6,%7}, {%8,%9}, {%0,%1,%2,%3};"
        : "+f"(c[0]), "+f"(c[1]), "+f"(c[2]), "+f"(c[3])
        : "r"(a[0]), "r"(a[1]), "r"(a[2]), "r"(a[3]), "r"(b0), "r"(b1));
}

__device__ __forceinline__ void bf16_split2(float x, float y, uint32_t& hi, uint32_t& lo) {
    __nv_bfloat16 hx = __float2bfloat16(x);
    __nv_bfloat16 hy = __float2bfloat16(y);
    __nv_bfloat16 lx = __float2bfloat16(x - __bfloat162float(hx));
    __nv_bfloat16 ly = __float2bfloat16(y - __bfloat162float(hy));
    hi = (uint32_t)__bfloat16_as_ushort(hx) | ((uint32_t)__bfloat16_as_ushort(hy) << 16);
    lo = (uint32_t)__bfloat16_as_ushort(lx) | ((uint32_t)__bfloat16_as_ushort(ly) << 16);
}

#define LDSM_X4(r0, r1, r2, r3, addr) \
    asm volatile("ldmatrix.sync.aligned.m8n8.x4.shared.b16 {%0,%1,%2,%3}, [%4];" \
                 : "=r"(r0), "=r"(r1), "=r"(r2), "=r"(r3) : "r"(addr))

#define LDSM_X4_T(r0, r1, r2, r3, addr) \
    asm volatile("ldmatrix.sync.aligned.m8n8.x4.trans.shared.b16 {%0,%1,%2,%3}, [%4];" \
                 : "=r"(r0), "=r"(r1), "=r"(r2), "=r"(r3) : "r"(addr))

#define CP_ASYNC16(sp, gp) \
    asm volatile("cp.async.cg.shared.global [%0], [%1], 16;" :: "r"(sp), "l"(gp))

// ==== tf32 round + k-permute, batched over x (2 halves) + 4 weights ======
__global__ __launch_bounds__(256) void cvt_all(const float* __restrict__ x,
                                               const float* __restrict__ w0,
                                               const float* __restrict__ w1,
                                               const float* __restrict__ w2,
                                               const float* __restrict__ w3,
                                               float* __restrict__ xout,
                                               float* __restrict__ wout, int ngroups) {
    int z = blockIdx.z;
    const float* in;
    float* out;
    if (z < 2) {
        in = x + (size_t)z * ngroups * 16;
        out = xout + (size_t)z * ngroups * 16;
    } else {
        int w = z - 2;
        in = (w == 0) ? w0 : (w == 1) ? w1 : (w == 2) ? w2 : w3;
        out = wout + (size_t)w * DM * DM;
    }
    int i = blockIdx.x * 256 + threadIdx.x;
    if (i < ngroups) {
        const float4* ip = (const float4*)(in + (size_t)i * 16);
        float4 v0 = ip[0], v1 = ip[1], v2 = ip[2], v3 = ip[3];
        float4* op = (float4*)(out + (size_t)i * 16);
        op[0] = make_float4(tf32f(v0.x), tf32f(v1.x), tf32f(v2.x), tf32f(v3.x));
        op[1] = make_float4(tf32f(v0.y), tf32f(v1.y), tf32f(v2.y), tf32f(v3.y));
        op[2] = make_float4(tf32f(v0.z), tf32f(v1.z), tf32f(v2.z), tf32f(v3.z));
        op[3] = make_float4(tf32f(v0.w), tf32f(v1.w), tf32f(v2.w), tf32f(v3.w));
    }
}

// ======== fused RoPE + bf16 hi/lo split of Q (scaled), K, V ==============
__global__ __launch_bounds__(256) void rope_split(const float* __restrict__ Q,
                                                  const float* __restrict__ K,
                                                  const float* __restrict__ V,
                                                  unsigned short* __restrict__ Qhi_g,
                                                  unsigned short* __restrict__ Qlo_g,
                                                  unsigned short* __restrict__ Khi_g,
                                                  unsigned short* __restrict__ Klo_g,
                                                  unsigned short* __restrict__ Vhi_g,
                                                  unsigned short* __restrict__ Vlo_g) {
    const float scale = 0.08838834764831845f;
    const float LOG2_10000 = 13.287712379549449f;
    int idx = blockIdx.x * 256 + threadIdx.x;
    int d4 = (idx & 15) * 4;
    int h = (idx >> 4) & (NH - 1);
    int n = idx >> 8;
    int t = n & (T_ - 1);
    size_t base = (size_t)n * DM + h * HD;

    float c[4], s[4];
#pragma unroll
    for (int j = 0; j < 4; j++) {
        float inv = exp2f(-(float)(2 * (d4 + j)) * (LOG2_10000 / 128.0f));
        sincosf((float)t * inv, &s[j], &c[j]);
    }

    uint32_t h0, l0, h1, l1;
    {
        float4 q1 = *(const float4*)(Q + base + d4);
        float4 q2 = *(const float4*)(Q + base + d4 + 64);
        float a0 = (q1.x * c[0] - q2.x * s[0]) * scale;
        float a1 = (q1.y * c[1] - q2.y * s[1]) * scale;
        float a2 = (q1.z * c[2] - q2.z * s[2]) * scale;
        float a3 = (q1.w * c[3] - q2.w * s[3]) * scale;
        float b0 = (q2.x * c[0] + q1.x * s[0]) * scale;
        float b1 = (q2.y * c[1] + q1.y * s[1]) * scale;
        float b2 = (q2.z * c[2] + q1.z * s[2]) * scale;
        float b3 = (q2.w * c[3] + q1.w * s[3]) * scale;
        bf16_split2(a0, a1, h0, l0); bf16_split2(a2, a3, h1, l1);
        *(uint2*)(Qhi_g + base + d4) = make_uint2(h0, h1);
        *(uint2*)(Qlo_g + base + d4) = make_uint2(l0, l1);
        bf16_split2(b0, b1, h0, l0); bf16_split2(b2, b3, h1, l1);
        *(uint2*)(Qhi_g + base + d4 + 64) = make_uint2(h0, h1);
        *(uint2*)(Qlo_g + base + d4 + 64) = make_uint2(l0, l1);
    }
    {
        float4 k1 = *(const float4*)(K + base + d4);
        float4 k2 = *(const float4*)(K + base + d4 + 64);
        float a0 = k1.x * c[0] - k2.x * s[0];
        float a1 = k1.y * c[1] - k2.y * s[1];
        float a2 = k1.z * c[2] - k2.z * s[2];
        float a3 = k1.w * c[3] - k2.w * s[3];
        float b0 = k2.x * c[0] + k1.x * s[0];
        float b1 = k2.y * c[1] + k1.y * s[1];
        float b2 = k2.z * c[2] + k1.z * s[2];
        float b3 = k2.w * c[3] + k1.w * s[3];
        bf16_split2(a0, a1, h0, l0); bf16_split2(a2, a3, h1, l1);
        *(uint2*)(Khi_g + base + d4) = make_uint2(h0, h1);
        *(uint2*)(Klo_g + base + d4) = make_uint2(l0, l1);
        bf16_split2(b0, b1, h0, l0); bf16_split2(b2, b3, h1, l1);
        *(uint2*)(Khi_g + base + d4 + 64) = make_uint2(h0, h1);
        *(uint2*)(Klo_g + base + d4 + 64) = make_uint2(l0, l1);
    }
    {
        float4 v1 = *(const float4*)(V + base + d4);
        float4 v2 = *(const float4*)(V + base + d4 + 64);
        bf16_split2(v1.x, v1.y, h0, l0); bf16_split2(v1.z, v1.w, h1, l1);
        *(uint2*)(Vhi_g + base + d4) = make_uint2(h0, h1);
        *(uint2*)(Vlo_g + base + d4) = make_uint2(l0, l1);
        bf16_split2(v2.x, v2.y, h0, l0); bf16_split2(v2.z, v2.w, h1, l1);
        *(uint2*)(Vhi_g + base + d4 + 64) = make_uint2(h0, h1);
        *(uint2*)(Vlo_g + base + d4 + 64) = make_uint2(l0, l1);
    }
}

// == TF32 mma GEMM (R9 config): 128 thr, 4 warps (2x2), warp 64x64, 3-stage ==
#define GK 2048
#define GN 2048
#define CSTAGE_F (2 * 128 * 32)
#define GEMM_SMEM (3 * CSTAGE_F * 4)

__device__ __forceinline__ uint32_t sw_word(int row, int chunk) {
    return (uint32_t)(row * 32 + ((chunk ^ ((row & 1) << 2)) << 2));
}

__global__ __launch_bounds__(128) void gemm_perm(const float* __restrict__ A,
                                                 const float* __restrict__ B0, float* __restrict__ C0,
                                                 const float* __restrict__ B1, float* __restrict__ C1,
                                                 const float* __restrict__ B2, float* __restrict__ C2) {
    extern __shared__ float sh[];
    const int z = blockIdx.z;
    const float* Bm = (z == 0) ? B0 : (z == 1) ? B1 : B2;
    float* C = (z == 0) ? C0 : (z == 1) ? C1 : C2;
    const int tid = threadIdx.x;
    const int warp = tid >> 5;
    const int lane = tid & 31;
    const int g = lane >> 2;
    const int t = lane & 3;
    const int warp_m = warp & 1;
    const int warp_n = warp >> 1;
    const int m0 = blockIdx.y * 128;
    const int n0 = blockIdx.x * 128;
    const uint32_t sbase = smem_u32(sh);

    float acc[4][8][4];
#pragma unroll
    for (int mt = 0; mt < 4; mt++)
#pragma unroll
        for (int nt = 0; nt < 8; nt++)
#pragma unroll
            for (int j = 0; j < 4; j++) acc[mt][nt][j] = 0.f;

    const int NIT = GK / 32;

#define GEMM_ISSUE(stage, k0)                                                      \
    do {                                                                           \
        const uint32_t stb = sbase + (stage) * CSTAGE_F * 4;                       \
        _Pragma("unroll")                                                          \
        for (int i_ = 0; i_ < 16; i_++) {                                          \
            int idx = i_ * 128 + tid;                                              \
            int mat = idx >> 10;                                                   \
            int r = (idx >> 3) & 127;                                              \
            int ch = idx & 7;                                                      \
            const float* gp = (mat ? Bm + (size_t)(n0 + r) * GK                    \
                                   : A + (size_t)(m0 + r) * GK) + (k0) + ch * 4;   \
            uint32_t sp = stb + (mat * 128 * 32 + sw_word(r, ch)) * 4;             \
            CP_ASYNC16(sp, gp);                                                    \
        }                                                                          \
        asm volatile("cp.async.commit_group;" ::: "memory");                       \
    } while (0)

    GEMM_ISSUE(0, 0);
    GEMM_ISSUE(1, 32);

    for (int it = 0; it < NIT; it++) {
        if (it + 1 < NIT) asm volatile("cp.async.wait_group 1;" ::: "memory");
        else              asm volatile("cp.async.wait_group 0;" ::: "memory");
        __syncthreads();

        const float* As = sh + (it % 3) * CSTAGE_F;
        const float* Bs = As + 128 * 32;
#pragma unroll
        for (int ks2 = 0; ks2 < 2; ks2++) {
            const int c0 = 4 * ks2 + t;
            float4 alo[4], ahi[4];
#pragma unroll
            for (int mt = 0; mt < 4; mt++) {
                int r0 = warp_m * 64 + mt * 16 + g;
                alo[mt] = *(const float4*)&As[sw_word(r0, c0)];
                ahi[mt] = *(const float4*)&As[sw_word(r0 + 8, c0)];
            }
            float4 bv[8];
#pragma unroll
            for (int nt = 0; nt < 8; nt++) {
                int cn = warp_n * 64 + nt * 8 + g;
                bv[nt] = *(const float4*)&Bs[sw_word(cn, c0)];
            }
#pragma unroll
            for (int mt = 0; mt < 4; mt++) {
                uint32_t af[4] = {__float_as_uint(alo[mt].x), __float_as_uint(ahi[mt].x),
                                  __float_as_uint(alo[mt].y), __float_as_uint(ahi[mt].y)};
#pragma unroll
                for (int nt = 0; nt < 8; nt++)
                    mma_tf32_16n8k8(acc[mt][nt], af,
                                    __float_as_uint(bv[nt].x), __float_as_uint(bv[nt].y));
            }
#pragma unroll
            for (int mt = 0; mt < 4; mt++) {
                uint32_t af[4] = {__float_as_uint(alo[mt].z), __float_as_uint(ahi[mt].z),
                                  __float_as_uint(alo[mt].w), __float_as_uint(ahi[mt].w)};
#pragma unroll
                for (int nt = 0; nt < 8; nt++)
                    mma_tf32_16n8k8(acc[mt][nt], af,
                                    __float_as_uint(bv[nt].z), __float_as_uint(bv[nt].w));
            }
        }

        if (it + 2 < NIT) GEMM_ISSUE((it + 2) % 3, (it + 2) * 32);
    }

#pragma unroll
    for (int mt = 0; mt < 4; mt++) {
        int row = m0 + warp_m * 64 + mt * 16 + g;
#pragma unroll
        for (int nt = 0; nt < 8; nt++) {
            int col = n0 + warp_n * 64 + nt * 8 + 2 * t;
            *(float2*)(C + (size_t)row * GN + col) = make_float2(acc[mt][nt][0], acc[mt][nt][1]);
            *(float2*)(C + (size_t)(row + 8) * GN + col) = make_float2(acc[mt][nt][2], acc[mt][nt][3]);
        }
    }
}

// ===== Flash attention: 64-row CTA, P in registers, K via ldmatrix ======
#define KS 136
#define VS 136
#define PLANE (64 * KS)                      // 8704 u16 per plane
#define FLASH_SMEM (4 * PLANE * 2)           // 69632 bytes (Khi,Klo,Vhi,Vlo)

__global__ __launch_bounds__(128, 2) void flash_bf16(const unsigned short* __restrict__ Qhi_g,
                                                     const unsigned short* __restrict__ Qlo_g,
                                                     const unsigned short* __restrict__ Khi_g,
                                                     const unsigned short* __restrict__ Klo_g,
                                                     const unsigned short* __restrict__ Vhi_g,
                                                     const unsigned short* __restrict__ Vlo_g,
                                                     float* __restrict__ Og) {
    extern __shared__ unsigned short su[];

    const int qb = blockIdx.x;
    const int bh = blockIdx.y;
    const int b = bh >> 4, h = bh & 15;
    const int q0 = qb * 64;
    const int tid = threadIdx.x;
    const int warp = tid >> 5;
    const int lane = tid & 31;
    const int g = lane >> 2;
    const int t = lane & 3;
    const float NEG_INF = __int_as_float(0xff800000);

    // ldmatrix.trans lane addr components (V)
    const int lq = lane >> 3;
    const int lsl = lane & 7;
    const int srow_off = (lq & 1) * 8 + lsl;
    const int dcol_off = (lq >> 1) * 8;
    const uint32_t sbase = smem_u32(su);
    const uint32_t vhi_base = sbase + 2 * PLANE * 2;
    const uint32_t vlo_base = sbase + 3 * PLANE * 2;

    // ldmatrix (non-trans) lane addr for K: tile = lane>>3 selects (k-half, nt-in-pair)
    const int lrow = lane & 7;
    const int lk8 = ((lane >> 3) & 1) * 8;       // k offset 0/8
    const int lnt8 = (lane >> 4) * 8;            // row offset for 2nd nt of pair
    const uint32_t klane_off = (uint32_t)(((lnt8 + lrow) * KS + lk8) * 2);

    const int rowA = warp * 16 + g;
    const int ntiles = qb + 1;

    // ---- Q fragments in registers (loop-invariant) ----
    uint32_t Qh[8][4], Ql[8][4];
    {
        const unsigned short* q0p = Qhi_g + (size_t)(b * T_ + q0 + rowA) * DM + h * HD;
        const unsigned short* q1p = Qlo_g + (size_t)(b * T_ + q0 + rowA) * DM + h * HD;
#pragma unroll
        for (int ks = 0; ks < 8; ks++) {
            const int k16 = ks * 16;
            Qh[ks][0] = *(const uint32_t*)(q0p + k16 + 2 * t);
            Qh[ks][1] = *(const uint32_t*)(q0p + 8 * DM + k16 + 2 * t);
            Qh[ks][2] = *(const uint32_t*)(q0p + k16 + 8 + 2 * t);
            Qh[ks][3] = *(const uint32_t*)(q0p + 8 * DM + k16 + 8 + 2 * t);
            Ql[ks][0] = *(const uint32_t*)(q1p + k16 + 2 * t);
            Ql[ks][1] = *(const uint32_t*)(q1p + 8 * DM + k16 + 2 * t);
            Ql[ks][2] = *(const uint32_t*)(q1p + k16 + 8 + 2 * t);
            Ql[ks][3] = *(const uint32_t*)(q1p + 8 * DM + k16 + 8 + 2 * t);
        }
    }

    float accO[16][4];
#pragma unroll
    for (int nt = 0; nt < 16; nt++)
#pragma unroll
        for (int j = 0; j < 4; j++) accO[nt][j] = 0.f;
    float m0 = -1e30f, m1 = -1e30f, l0s = 0.f, l1s = 0.f;

#define ISSUE_K(kb_)                                                              \
    do {                                                                          \
        const size_t gbase = (size_t)(b * T_ + (kb_) * 64) * DM + h * HD;         \
        _Pragma("unroll")                                                         \
        for (int i_ = 0; i_ < 8; i_++) {                                          \
            int idx = i_ * 128 + tid;                                             \
            int r = idx >> 4;                                                     \
            int ch = idx & 15;                                                    \
            size_t go = gbase + (size_t)r * DM + ch * 8;                          \
            uint32_t so = (uint32_t)(r * KS + ch * 8) * 2;                        \
            CP_ASYNC16(sbase + so, Khi_g + go);                                   \
            CP_ASYNC16(sbase + PLANE * 2 + so, Klo_g + go);                       \
        }                                                                         \
        asm volatile("cp.async.commit_group;" ::: "memory");                      \
    } while (0)

#define ISSUE_V(kb_)                                                              \
    do {                                                                          \
        const size_t gbase = (size_t)(b * T_ + (kb_) * 64) * DM + h * HD;         \
        _Pragma("unroll")                                                         \
        for (int i_ = 0; i_ < 8; i_++) {                                          \
            int idx = i_ * 128 + tid;                                             \
            int r = idx >> 4;                                                     \
            int ch = idx & 15;                                                    \
            size_t go = gbase + (size_t)r * DM + ch * 8;                          \
            uint32_t so = (uint32_t)(r * KS + ch * 8) * 2;                        \
            CP_ASYNC16(sbase + PLANE * 4 + so, Vhi_g + go);                       \
            CP_ASYNC16(sbase + PLANE * 6 + so, Vlo_g + go);                       \
        }                                                                         \
        asm volatile("cp.async.commit_group;" ::: "memory");                      \
    } while (0)

    ISSUE_K(0);
    ISSUE_V(0);

    for (int kb = 0; kb < ntiles; kb++) {
        const int k0 = kb * 64;
        asm volatile("cp.async.wait_group 1;" ::: "memory");   // K(kb) done
        __syncthreads();

        // ---- S = Q K^T (K fragments via ldmatrix.x4) ----
        float accS[8][4];
#pragma unroll
        for (int nt = 0; nt < 8; nt++)
#pragma unroll
            for (int j = 0; j < 4; j++) accS[nt][j] = 0.f;

#pragma unroll
        for (int ks = 0; ks < 8; ks++) {
            const uint32_t kb_hi = sbase + klane_off + ks * 32;
            const uint32_t kb_lo = kb_hi + PLANE * 2;
#pragma unroll
            for (int np = 0; np < 4; np++) {
                const uint32_t off = np * (32 * KS);
                uint32_t h0, h1, h2, h3, lo0, lo1, lo2, lo3;
                LDSM_X4(h0, h1, h2, h3, kb_hi + off);
                LDSM_X4(lo0, lo1, lo2, lo3, kb_lo + off);
                mma_bf16_16n8k16(accS[2 * np], Qh[ks], h0, h1);
                mma_bf16_16n8k16(accS[2 * np], Qh[ks], lo0, lo1);
                mma_bf16_16n8k16(accS[2 * np], Ql[ks], h0, h1);
                mma_bf16_16n8k16(accS[2 * np + 1], Qh[ks], h2, h3);
                mma_bf16_16n8k16(accS[2 * np + 1], Qh[ks], lo2, lo3);
                mma_bf16_16n8k16(accS[2 * np + 1], Ql[ks], h2, h3);
            }
        }
        __syncthreads();                      // all warps done reading K planes
        if (kb + 1 < ntiles) ISSUE_K(kb + 1);

        // ---- mask + online softmax ----
        const int rowg0 = q0 + rowA;
        const int rowg1 = rowg0 + 8;
        const bool chk = (k0 + 63 > q0 + warp * 16);
        float mx0 = NEG_INF, mx1 = NEG_INF;
#pragma unroll
        for (int nt = 0; nt < 8; nt++) {
#pragma unroll
            for (int j = 0; j < 2; j++) {
                int col = k0 + nt * 8 + 2 * t + j;
                float s0 = accS[nt][j];
                float s1 = accS[nt][2 + j];
                if (chk) {
                    if (col > rowg0) s0 = NEG_INF;
                    if (col > rowg1) s1 = NEG_INF;
                }
                accS[nt][j] = s0;
                accS[nt][2 + j] = s1;
                mx0 = fmaxf(mx0, s0);
                mx1 = fmaxf(mx1, s1);
            }
        }
        mx0 = fmaxf(mx0, __shfl_xor_sync(0xffffffffu, mx0, 1));
        mx0 = fmaxf(mx0, __shfl_xor_sync(0xffffffffu, mx0, 2));
        mx1 = fmaxf(mx1, __shfl_xor_sync(0xffffffffu, mx1, 1));
        mx1 = fmaxf(mx1, __shfl_xor_sync(0xffffffffu, mx1, 2));

        float mn0 = fmaxf(m0, mx0), mn1 = fmaxf(m1, mx1);
        float al0 = __expf(m0 - mn0), al1 = __expf(m1 - mn1);
        float rs0 = 0.f, rs1 = 0.f;
        uint32_t Pha[8][2], Pla[8][2];       // P fragments, rows g / g+8
#pragma unroll
        for (int nt = 0; nt < 8; nt++) {
            float p00 = __expf(accS[nt][0] - mn0);
            float p01 = __expf(accS[nt][1] - mn0);
            float p10 = __expf(accS[nt][2] - mn1);
            float p11 = __expf(accS[nt][3] - mn1);
            rs0 += p00 + p01;
            rs1 += p10 + p11;
            bf16_split2(p00, p01, Pha[nt][0], Pla[nt][0]);
            bf16_split2(p10, p11, Pha[nt][1], Pla[nt][1]);
        }
        rs0 += __shfl_xor_sync(0xffffffffu, rs0, 1);
        rs0 += __shfl_xor_sync(0xffffffffu, rs0, 2);
        rs1 += __shfl_xor_sync(0xffffffffu, rs1, 1);
        rs1 += __shfl_xor_sync(0xffffffffu, rs1, 2);
        l0s = l0s * al0 + rs0;
        l1s = l1s * al1 + rs1;
        m0 = mn0;
        m1 = mn1;
#pragma unroll
        for (int nt = 0; nt < 16; nt++) {
            accO[nt][0] *= al0; accO[nt][1] *= al0;
            accO[nt][2] *= al1; accO[nt][3] *= al1;
        }

        // wait for V(kb)
        if (kb + 1 < ntiles) asm volatile("cp.async.wait_group 1;" ::: "memory");
        else                 asm volatile("cp.async.wait_group 0;" ::: "memory");
        __syncthreads();

        // ---- O += P V (P fragments straight from registers) ----
#pragma unroll
        for (int si = 0; si < 4; si++) {
            uint32_t pah[4] = {Pha[2 * si][0], Pha[2 * si][1],
                               Pha[2 * si + 1][0], Pha[2 * si + 1][1]};
            uint32_t pal[4] = {Pla[2 * si][0], Pla[2 * si][1],
                               Pla[2 * si + 1][0], Pla[2 * si + 1][1]};
            const int s16 = si * 16;
#pragma unroll
            for (int pr = 0; pr < 8; pr++) {
                uint32_t off = (uint32_t)((s16 + srow_off) * VS + pr * 16 + dcol_off) * 2;
                uint32_t vh0, vh1, vh2, vh3, vl0, vl1, vl2, vl3;
                LDSM_X4_T(vh0, vh1, vh2, vh3, vhi_base + off);
                LDSM_X4_T(vl0, vl1, vl2, vl3, vlo_base + off);
                const int nt0 = 2 * pr, nt1 = 2 * pr + 1;
                mma_bf16_16n8k16(accO[nt0], pah, vh0, vh1);
                mma_bf16_16n8k16(accO[nt0], pah, vl0, vl1);
                mma_bf16_16n8k16(accO[nt0], pal, vh0, vh1);
                mma_bf16_16n8k16(accO[nt1], pah, vh2, vh3);
                mma_bf16_16n8k16(accO[nt1], pah, vl2, vl3);
                mma_bf16_16n8k16(accO[nt1], pal, vh2, vh3);
            }
        }
        __syncthreads();                      // all warps done reading V planes
        if (kb + 1 < ntiles) ISSUE_V(kb + 1);
    }

    // ---- epilogue: normalize + tf32 round + k-permuted scatter ----
    float inv0 = 1.f / l0s, inv1 = 1.f / l1s;
    float* Op = Og + (size_t)(b * T_ + q0 + rowA) * DM + h * HD;
    float* Op8 = Op + (size_t)8 * DM;
#pragma unroll
    for (int nt = 0; nt < 16; nt++) {
#pragma unroll
        for (int j = 0; j < 2; j++) {
            int col = nt * 8 + 2 * t + j;
            int jj = col & 15;
            int p = (col & ~15) + ((jj & 3) << 2) + (jj >> 2);
            Op[p]  = tf32f(accO[nt][j] * inv0);
            Op8[p] = tf32f(accO[nt][2 + j] * inv1);
        }
    }
}

// ============================ launcher ==================================
extern "C" void kernel_launch(void* const* d_in, const int* in_sizes, int n_in,
                              void* d_out, int out_size) {
    const float* x  = (const float*)d_in[0];
    const float* Wq = (const float*)d_in[1];
    const float* Wk = (const float*)d_in[2];
    const float* Wv = (const float*)d_in[3];
    const float* Wo = (const float*)d_in[4];
    float* out = (float*)d_out;

    float *pQ, *pK, *pV, *pA, *pXc, *pWc;
    unsigned short *pQh, *pQl, *pKh, *pKl, *pVh, *pVl;
    cudaGetSymbolAddress((void**)&pQ, g_Q);
    cudaGetSymbolAddress((void**)&pK, g_K);
    cudaGetSymbolAddress((void**)&pV, g_V);
    cudaGetSymbolAddress((void**)&pA, g_A);
    cudaGetSymbolAddress((void**)&pXc, g_xc);
    cudaGetSymbolAddress((void**)&pWc, g_Wc);
    cudaGetSymbolAddress((void**)&pQh, g_Qhi);
    cudaGetSymbolAddress((void**)&pQl, g_Qlo);
    cudaGetSymbolAddress((void**)&pKh, g_Khi);
    cudaGetSymbolAddress((void**)&pKl, g_Klo);
    cudaGetSymbolAddress((void**)&pVh, g_Vhi);
    cudaGetSymbolAddress((void**)&pVl, g_Vlo);
    float* pWqc = pWc;
    float* pWkc = pWc + (size_t)DM * DM;
    float* pWvc = pWc + 2 * (size_t)DM * DM;
    float* pWoc = pWc + 3 * (size_t)DM * DM;

    cudaFuncSetAttribute(gemm_perm, cudaFuncAttributeMaxDynamicSharedMemorySize, GEMM_SMEM);
    cudaFuncSetAttribute(flash_bf16, cudaFuncAttributeMaxDynamicSharedMemorySize, FLASH_SMEM);

    const int NWG = (DM * DM) / 16;
    dim3 ggrid3(DM / 128, NROWS / 128, 3);
    dim3 ggrid1(DM / 128, NROWS / 128, 1);
    dim3 fgrid(T_ / 64, B_ * NH);          // (32, 32) = 1024 CTAs

    cvt_all<<<dim3(NWG / 256, 1, 6), 256>>>(x, Wq, Wk, Wv, Wo, pXc, pWc, NWG);   // 1
    gemm_perm<<<ggrid3, 128, GEMM_SMEM>>>(pXc, pWqc, pQ, pWkc, pK, pWvc, pV);    // 2
    rope_split<<<(NROWS * NH * 16) / 256, 256>>>(pQ, pK, pV,
                                                 pQh, pQl, pKh, pKl, pVh, pVl);  // 3
    flash_bf16<<<fgrid, 128, FLASH_SMEM>>>(pQh, pQl, pKh, pKl, pVh, pVl, pA);    // 4
    gemm_perm<<<ggrid1, 128, GEMM_SMEM>>>(pA, pWoc, out, pWoc, out, pWoc, out);  // 5
}

// round 16
// speedup vs baseline: 1.3025x; 1.0038x over previous
#include <cuda_runtime.h>
#include <cuda_bf16.h>
#include <math.h>
#include <stdint.h>

#define B_  2
#define T_  2048
#define DM  2048
#define NH  16
#define HD  128
#define NROWS (B_ * T_)   // 4096

// ---------------- scratch (no runtime allocation allowed) ----------------
__device__ float g_Q[(size_t)NROWS * DM];
__device__ float g_K[(size_t)NROWS * DM];
__device__ float g_V[(size_t)NROWS * DM];
__device__ float g_A[(size_t)NROWS * DM];
__device__ float g_xc[(size_t)NROWS * DM];
__device__ float g_Wc[4][(size_t)DM * DM];
__device__ unsigned short g_Qhi[(size_t)NROWS * DM];
__device__ unsigned short g_Qlo[(size_t)NROWS * DM];
__device__ unsigned short g_Khi[(size_t)NROWS * DM];
__device__ unsigned short g_Klo[(size_t)NROWS * DM];
__device__ unsigned short g_Vhi[(size_t)NROWS * DM];
__device__ unsigned short g_Vlo[(size_t)NROWS * DM];

__device__ __forceinline__ uint32_t f2tf32(float x) {
    uint32_t r;
    asm("cvt.rna.tf32.f32 %0, %1;" : "=r"(r) : "f"(x));
    return r;
}
__device__ __forceinline__ float tf32f(float x) { return __uint_as_float(f2tf32(x)); }

__device__ __forceinline__ uint32_t smem_u32(const void* p) {
    uint32_t a;
    asm("{ .reg .u64 t; cvta.to.shared.u64 t, %1; cvt.u32.u64 %0, t; }" : "=r"(a) : "l"(p));
    return a;
}

__device__ __forceinline__ void mma_tf32_16n8k8(float c[4], const uint32_t a[4],
                                                const uint32_t b0, const uint32_t b1) {
    asm volatile(
        "mma.sync.aligned.m16n8k8.row.col.f32.tf32.tf32.f32 "
        "{%0,%1,%2,%3}, {%4,%5,%6,%7}, {%8,%9}, {%0,%1,%2,%3};"
        : "+f"(c[0]), "+f"(c[1]), "+f"(c[2]), "+f"(c[3])
        : "r"(a[0]), "r"(a[1]), "r"(a[2]), "r"(a[3]), "r"(b0), "r"(b1));
}

__device__ __forceinline__ void mma_bf16_16n8k16(float c[4], const uint32_t a[4],
                                                 const uint32_t b0, const uint32_t b1) {
    asm volatile(
        "mma.sync.aligned.m16n8k16.row.col.f32.bf16.bf16.f32 "
        "{%0,%1,%2,%3}, {%4,%5,%6,%7}, {%8,%9}, {%0,%1,%2,%3};"
        : "+f"(c[0]), "+f"(c[1]), "+f"(c[2]), "+f"(c[3])
        : "r"(a[0]), "r"(a[1]), "r"(a[2]), "r"(a[3]), "r"(b0), "r"(b1));
}

__device__ __forceinline__ void bf16_split2(float x, float y, uint32_t& hi, uint32_t& lo) {
    __nv_bfloat16 hx = __float2bfloat16(x);
    __nv_bfloat16 hy = __float2bfloat16(y);
    __nv_bfloat16 lx = __float2bfloat16(x - __bfloat162float(hx));
    __nv_bfloat16 ly = __float2bfloat16(y - __bfloat162float(hy));
    hi = (uint32_t)__bfloat16_as_ushort(hx) | ((uint32_t)__bfloat16_as_ushort(hy) << 16);
    lo = (uint32_t)__bfloat16_as_ushort(lx) | ((uint32_t)__bfloat16_as_ushort(ly) << 16);
}

#define LDSM_X4(r0, r1, r2, r3, addr) \
    asm volatile("ldmatrix.sync.aligned.m8n8.x4.shared.b16 {%0,%1,%2,%3}, [%4];" \
                 : "=r"(r0), "=r"(r1), "=r"(r2), "=r"(r3) : "r"(addr))

#define LDSM_X4_T(r0, r1, r2, r3, addr) \
    asm volatile("ldmatrix.sync.aligned.m8n8.x4.trans.shared.b16 {%0,%1,%2,%3}, [%4];" \
                 : "=r"(r0), "=r"(r1), "=r"(r2), "=r"(r3) : "r"(addr))

#define CP_ASYNC16(sp, gp) \
    asm volatile("cp.async.cg.shared.global [%0], [%1], 16;" :: "r"(sp), "l"(gp))

// ==== tf32 round + k-permute, batched over x (2 halves) + 4 weights ======
__global__ __launch_bounds__(256) void cvt_all(const float* __restrict__ x,
                                               const float* __restrict__ w0,
                                               const float* __restrict__ w1,
                                               const float* __restrict__ w2,
                                               const float* __restrict__ w3,
                                               float* __restrict__ xout,
                                               float* __restrict__ wout, int ngroups) {
    int z = blockIdx.z;
    const float* in;
    float* out;
    if (z < 2) {
        in = x + (size_t)z * ngroups * 16;
        out = xout + (size_t)z * ngroups * 16;
    } else {
        int w = z - 2;
        in = (w == 0) ? w0 : (w == 1) ? w1 : (w == 2) ? w2 : w3;
        out = wout + (size_t)w * DM * DM;
    }
    int i = blockIdx.x * 256 + threadIdx.x;
    if (i < ngroups) {
        const float4* ip = (const float4*)(in + (size_t)i * 16);
        float4 v0 = ip[0], v1 = ip[1], v2 = ip[2], v3 = ip[3];
        float4* op = (float4*)(out + (size_t)i * 16);
        op[0] = make_float4(tf32f(v0.x), tf32f(v1.x), tf32f(v2.x), tf32f(v3.x));
        op[1] = make_float4(tf32f(v0.y), tf32f(v1.y), tf32f(v2.y), tf32f(v3.y));
        op[2] = make_float4(tf32f(v0.z), tf32f(v1.z), tf32f(v2.z), tf32f(v3.z));
        op[3] = make_float4(tf32f(v0.w), tf32f(v1.w), tf32f(v2.w), tf32f(v3.w));
    }
}

// ======== fused RoPE + bf16 hi/lo split of Q (scaled), K, V ==============
__global__ __launch_bounds__(256) void rope_split(const float* __restrict__ Q,
                                                  const float* __restrict__ K,
                                                  const float* __restrict__ V,
                                                  unsigned short* __restrict__ Qhi_g,
                                                  unsigned short* __restrict__ Qlo_g,
                                                  unsigned short* __restrict__ Khi_g,
                                                  unsigned short* __restrict__ Klo_g,
                                                  unsigned short* __restrict__ Vhi_g,
                                                  unsigned short* __restrict__ Vlo_g) {
    const float scale = 0.08838834764831845f;
    const float LOG2_10000 = 13.287712379549449f;
    int idx = blockIdx.x * 256 + threadIdx.x;
    int d4 = (idx & 15) * 4;
    int h = (idx >> 4) & (NH - 1);
    int n = idx >> 8;
    int t = n & (T_ - 1);
    size_t base = (size_t)n * DM + h * HD;

    float c[4], s[4];
#pragma unroll
    for (int j = 0; j < 4; j++) {
        float inv = exp2f(-(float)(2 * (d4 + j)) * (LOG2_10000 / 128.0f));
        sincosf((float)t * inv, &s[j], &c[j]);
    }

    uint32_t h0, l0, h1, l1;
    {
        float4 q1 = *(const float4*)(Q + base + d4);
        float4 q2 = *(const float4*)(Q + base + d4 + 64);
        float a0 = (q1.x * c[0] - q2.x * s[0]) * scale;
        float a1 = (q1.y * c[1] - q2.y * s[1]) * scale;
        float a2 = (q1.z * c[2] - q2.z * s[2]) * scale;
        float a3 = (q1.w * c[3] - q2.w * s[3]) * scale;
        float b0 = (q2.x * c[0] + q1.x * s[0]) * scale;
        float b1 = (q2.y * c[1] + q1.y * s[1]) * scale;
        float b2 = (q2.z * c[2] + q1.z * s[2]) * scale;
        float b3 = (q2.w * c[3] + q1.w * s[3]) * scale;
        bf16_split2(a0, a1, h0, l0); bf16_split2(a2, a3, h1, l1);
        *(uint2*)(Qhi_g + base + d4) = make_uint2(h0, h1);
        *(uint2*)(Qlo_g + base + d4) = make_uint2(l0, l1);
        bf16_split2(b0, b1, h0, l0); bf16_split2(b2, b3, h1, l1);
        *(uint2*)(Qhi_g + base + d4 + 64) = make_uint2(h0, h1);
        *(uint2*)(Qlo_g + base + d4 + 64) = make_uint2(l0, l1);
    }
    {
        float4 k1 = *(const float4*)(K + base + d4);
        float4 k2 = *(const float4*)(K + base + d4 + 64);
        float a0 = k1.x * c[0] - k2.x * s[0];
        float a1 = k1.y * c[1] - k2.y * s[1];
        float a2 = k1.z * c[2] - k2.z * s[2];
        float a3 = k1.w * c[3] - k2.w * s[3];
        float b0 = k2.x * c[0] + k1.x * s[0];
        float b1 = k2.y * c[1] + k1.y * s[1];
        float b2 = k2.z * c[2] + k1.z * s[2];
        float b3 = k2.w * c[3] + k1.w * s[3];
        bf16_split2(a0, a1, h0, l0); bf16_split2(a2, a3, h1, l1);
        *(uint2*)(Khi_g + base + d4) = make_uint2(h0, h1);
        *(uint2*)(Klo_g + base + d4) = make_uint2(l0, l1);
        bf16_split2(b0, b1, h0, l0); bf16_split2(b2, b3, h1, l1);
        *(uint2*)(Khi_g + base + d4 + 64) = make_uint2(h0, h1);
        *(uint2*)(Klo_g + base + d4 + 64) = make_uint2(l0, l1);
    }
    {
        float4 v1 = *(const float4*)(V + base + d4);
        float4 v2 = *(const float4*)(V + base + d4 + 64);
        bf16_split2(v1.x, v1.y, h0, l0); bf16_split2(v1.z, v1.w, h1, l1);
        *(uint2*)(Vhi_g + base + d4) = make_uint2(h0, h1);
        *(uint2*)(Vlo_g + base + d4) = make_uint2(l0, l1);
        bf16_split2(v2.x, v2.y, h0, l0); bf16_split2(v2.z, v2.w, h1, l1);
        *(uint2*)(Vhi_g + base + d4 + 64) = make_uint2(h0, h1);
        *(uint2*)(Vlo_g + base + d4 + 64) = make_uint2(l0, l1);
    }
}

// == TF32 mma GEMM (R9 config): 128 thr, 4 warps (2x2), warp 64x64, 3-stage ==
#define GK 2048
#define GN 2048
#define CSTAGE_F (2 * 128 * 32)
#define GEMM_SMEM (3 * CSTAGE_F * 4)

__device__ __forceinline__ uint32_t sw_word(int row, int chunk) {
    return (uint32_t)(row * 32 + ((chunk ^ ((row & 1) << 2)) << 2));
}

__global__ __launch_bounds__(128) void gemm_perm(const float* __restrict__ A,
                                                 const float* __restrict__ B0, float* __restrict__ C0,
                                                 const float* __restrict__ B1, float* __restrict__ C1,
                                                 const float* __restrict__ B2, float* __restrict__ C2) {
    extern __shared__ float sh[];
    const int z = blockIdx.z;
    const float* Bm = (z == 0) ? B0 : (z == 1) ? B1 : B2;
    float* C = (z == 0) ? C0 : (z == 1) ? C1 : C2;
    const int tid = threadIdx.x;
    const int warp = tid >> 5;
    const int lane = tid & 31;
    const int g = lane >> 2;
    const int t = lane & 3;
    const int warp_m = warp & 1;
    const int warp_n = warp >> 1;
    const int m0 = blockIdx.y * 128;
    const int n0 = blockIdx.x * 128;
    const uint32_t sbase = smem_u32(sh);

    float acc[4][8][4];
#pragma unroll
    for (int mt = 0; mt < 4; mt++)
#pragma unroll
        for (int nt = 0; nt < 8; nt++)
#pragma unroll
            for (int j = 0; j < 4; j++) acc[mt][nt][j] = 0.f;

    const int NIT = GK / 32;

#define GEMM_ISSUE(stage, k0)                                                      \
    do {                                                                           \
        const uint32_t stb = sbase + (stage) * CSTAGE_F * 4;                       \
        _Pragma("unroll")                                                          \
        for (int i_ = 0; i_ < 16; i_++) {                                          \
            int idx = i_ * 128 + tid;                                              \
            int mat = idx >> 10;                                                   \
            int r = (idx >> 3) & 127;                                              \
            int ch = idx & 7;                                                      \
            const float* gp = (mat ? Bm + (size_t)(n0 + r) * GK                    \
                                   : A + (size_t)(m0 + r) * GK) + (k0) + ch * 4;   \
            uint32_t sp = stb + (mat * 128 * 32 + sw_word(r, ch)) * 4;             \
            CP_ASYNC16(sp, gp);                                                    \
        }                                                                          \
        asm volatile("cp.async.commit_group;" ::: "memory");                       \
    } while (0)

    GEMM_ISSUE(0, 0);
    GEMM_ISSUE(1, 32);

    for (int it = 0; it < NIT; it++) {
        if (it + 1 < NIT) asm volatile("cp.async.wait_group 1;" ::: "memory");
        else              asm volatile("cp.async.wait_group 0;" ::: "memory");
        __syncthreads();

        const float* As = sh + (it % 3) * CSTAGE_F;
        const float* Bs = As + 128 * 32;
#pragma unroll
        for (int ks2 = 0; ks2 < 2; ks2++) {
            const int c0 = 4 * ks2 + t;
            float4 alo[4], ahi[4];
#pragma unroll
            for (int mt = 0; mt < 4; mt++) {
                int r0 = warp_m * 64 + mt * 16 + g;
                alo[mt] = *(const float4*)&As[sw_word(r0, c0)];
                ahi[mt] = *(const float4*)&As[sw_word(r0 + 8, c0)];
            }
            float4 bv[8];
#pragma unroll
            for (int nt = 0; nt < 8; nt++) {
                int cn = warp_n * 64 + nt * 8 + g;
                bv[nt] = *(const float4*)&Bs[sw_word(cn, c0)];
            }
#pragma unroll
            for (int mt = 0; mt < 4; mt++) {
                uint32_t af[4] = {__float_as_uint(alo[mt].x), __float_as_uint(ahi[mt].x),
                                  __float_as_uint(alo[mt].y), __float_as_uint(ahi[mt].y)};
#pragma unroll
                for (int nt = 0; nt < 8; nt++)
                    mma_tf32_16n8k8(acc[mt][nt], af,
                                    __float_as_uint(bv[nt].x), __float_as_uint(bv[nt].y));
            }
#pragma unroll
            for (int mt = 0; mt < 4; mt++) {
                uint32_t af[4] = {__float_as_uint(alo[mt].z), __float_as_uint(ahi[mt].z),
                                  __float_as_uint(alo[mt].w), __float_as_uint(ahi[mt].w)};
#pragma unroll
                for (int nt = 0; nt < 8; nt++)
                    mma_tf32_16n8k8(acc[mt][nt], af,
                                    __float_as_uint(bv[nt].z), __float_as_uint(bv[nt].w));
            }
        }

        if (it + 2 < NIT) GEMM_ISSUE((it + 2) % 3, (it + 2) * 32);
    }

#pragma unroll
    for (int mt = 0; mt < 4; mt++) {
        int row = m0 + warp_m * 64 + mt * 16 + g;
#pragma unroll
        for (int nt = 0; nt < 8; nt++) {
            int col = n0 + warp_n * 64 + nt * 8 + 2 * t;
            *(float2*)(C + (size_t)row * GN + col) = make_float2(acc[mt][nt][0], acc[mt][nt][1]);
            *(float2*)(C + (size_t)(row + 8) * GN + col) = make_float2(acc[mt][nt][2], acc[mt][nt][3]);
        }
    }
}

// ===== Flash: 64-row CTA, double-buffered K, heavy-first schedule ======
#define KS 136
#define VS 136
#define PLANE (64 * KS)                      // 8704 u16 per plane
// layout: Khi0, Klo0, Khi1, Klo1, Vhi, Vlo
#define FLASH_SMEM (6 * PLANE * 2)           // 104448 bytes

__global__ __launch_bounds__(128, 2) void flash_bf16(const unsigned short* __restrict__ Qhi_g,
                                                     const unsigned short* __restrict__ Qlo_g,
                                                     const unsigned short* __restrict__ Khi_g,
                                                     const unsigned short* __restrict__ Klo_g,
                                                     const unsigned short* __restrict__ Vhi_g,
                                                     const unsigned short* __restrict__ Vlo_g,
                                                     float* __restrict__ Og) {
    extern __shared__ unsigned short su[];

    const int qb = gridDim.x - 1 - blockIdx.x;   // heavy CTAs first
    const int bh = blockIdx.y;
    const int b = bh >> 4, h = bh & 15;
    const int q0 = qb * 64;
    const int tid = threadIdx.x;
    const int warp = tid >> 5;
    const int lane = tid & 31;
    const int g = lane >> 2;
    const int t = lane & 3;
    const float NEG_INF = __int_as_float(0xff800000);

    const int lq = lane >> 3;
    const int lsl = lane & 7;
    const int srow_off = (lq & 1) * 8 + lsl;
    const int dcol_off = (lq >> 1) * 8;
    const uint32_t sbase = smem_u32(su);
    const uint32_t vhi_base = sbase + 4 * PLANE * 2;
    const uint32_t vlo_base = sbase + 5 * PLANE * 2;

    const int lrow = lane & 7;
    const int lk8 = ((lane >> 3) & 1) * 8;
    const int lnt8 = (lane >> 4) * 8;
    const uint32_t klane_off = (uint32_t)(((lnt8 + lrow) * KS + lk8) * 2);

    const int rowA = warp * 16 + g;
    const int ntiles = qb + 1;

    // ---- Q fragments in registers (loop-invariant) ----
    uint32_t Qh[8][4], Ql[8][4];
    {
        const unsigned short* q0p = Qhi_g + (size_t)(b * T_ + q0 + rowA) * DM + h * HD;
        const unsigned short* q1p = Qlo_g + (size_t)(b * T_ + q0 + rowA) * DM + h * HD;
#pragma unroll
        for (int ks = 0; ks < 8; ks++) {
            const int k16 = ks * 16;
            Qh[ks][0] = *(const uint32_t*)(q0p + k16 + 2 * t);
            Qh[ks][1] = *(const uint32_t*)(q0p + 8 * DM + k16 + 2 * t);
            Qh[ks][2] = *(const uint32_t*)(q0p + k16 + 8 + 2 * t);
            Qh[ks][3] = *(const uint32_t*)(q0p + 8 * DM + k16 + 8 + 2 * t);
            Ql[ks][0] = *(const uint32_t*)(q1p + k16 + 2 * t);
            Ql[ks][1] = *(const uint32_t*)(q1p + 8 * DM + k16 + 2 * t);
            Ql[ks][2] = *(const uint32_t*)(q1p + k16 + 8 + 2 * t);
            Ql[ks][3] = *(const uint32_t*)(q1p + 8 * DM + k16 + 8 + 2 * t);
        }
    }

    float accO[16][4];
#pragma unroll
    for (int nt = 0; nt < 16; nt++)
#pragma unroll
        for (int j = 0; j < 4; j++) accO[nt][j] = 0.f;
    float m0 = -1e30f, m1 = -1e30f, l0s = 0.f, l1s = 0.f;

#define ISSUE_K(kb_, dbuf)                                                        \
    do {                                                                          \
        const size_t gbase = (size_t)(b * T_ + (kb_) * 64) * DM + h * HD;         \
        const uint32_t kbb = sbase + (dbuf) * 2 * PLANE * 2;                      \
        _Pragma("unroll")                                                         \
        for (int i_ = 0; i_ < 8; i_++) {                                          \
            int idx = i_ * 128 + tid;                                             \
            int r = idx >> 4;                                                     \
            int ch = idx & 15;                                                    \
            size_t go = gbase + (size_t)r * DM + ch * 8;                          \
            uint32_t so = (uint32_t)(r * KS + ch * 8) * 2;                        \
            CP_ASYNC16(kbb + so, Khi_g + go);                                     \
            CP_ASYNC16(kbb + PLANE * 2 + so, Klo_g + go);                         \
        }                                                                         \
        asm volatile("cp.async.commit_group;" ::: "memory");                      \
    } while (0)

#define ISSUE_V(kb_)                                                              \
    do {                                                                          \
        const size_t gbase = (size_t)(b * T_ + (kb_) * 64) * DM + h * HD;         \
        _Pragma("unroll")                                                         \
        for (int i_ = 0; i_ < 8; i_++) {                                          \
            int idx = i_ * 128 + tid;                                             \
            int r = idx >> 4;                                                     \
            int ch = idx & 15;                                                    \
            size_t go = gbase + (size_t)r * DM + ch * 8;                          \
            uint32_t so = (uint32_t)(r * KS + ch * 8) * 2;                        \
            CP_ASYNC16(sbase + PLANE * 8 + so, Vhi_g + go);                       \
            CP_ASYNC16(sbase + PLANE * 10 + so, Vlo_g + go);                      \
        }                                                                         \
        asm volatile("cp.async.commit_group;" ::: "memory");                      \
    } while (0)

    ISSUE_K(0, 0);
    ISSUE_V(0);
    // commit order: K(0), V(0), K(1), V(1), ...

    for (int kb = 0; kb < ntiles; kb++) {
        const int k0 = kb * 64;
        const int buf = kb & 1;
        // pending: {K(kb), V(kb)} -> complete K(kb), leave V(kb)
        asm volatile("cp.async.wait_group 1;" ::: "memory");
        __syncthreads();
        // prefetch K(kb+1) into other buffer (its prior readers done >=1 iter ago)
        if (kb + 1 < ntiles) ISSUE_K(kb + 1, buf ^ 1);

        const unsigned short* Khi = su + buf * 2 * PLANE;
        const unsigned short* Klo = Khi + PLANE;
        const uint32_t kbuf_base = sbase + buf * 2 * PLANE * 2;

        // ---- S = Q K^T (K fragments via ldmatrix.x4) ----
        float accS[8][4];
#pragma unroll
        for (int nt = 0; nt < 8; nt++)
#pragma unroll
            for (int j = 0; j < 4; j++) accS[nt][j] = 0.f;

#pragma unroll
        for (int ks = 0; ks < 8; ks++) {
            const uint32_t kb_hi = kbuf_base + klane_off + ks * 32;
            const uint32_t kb_lo = kb_hi + PLANE * 2;
#pragma unroll
            for (int np = 0; np < 4; np++) {
                const uint32_t off = np * (32 * KS);
                uint32_t h0, h1, h2, h3, lo0, lo1, lo2, lo3;
                LDSM_X4(h0, h1, h2, h3, kb_hi + off);
                LDSM_X4(lo0, lo1, lo2, lo3, kb_lo + off);
                mma_bf16_16n8k16(accS[2 * np], Qh[ks], h0, h1);
                mma_bf16_16n8k16(accS[2 * np], Qh[ks], lo0, lo1);
                mma_bf16_16n8k16(accS[2 * np], Ql[ks], h0, h1);
                mma_bf16_16n8k16(accS[2 * np + 1], Qh[ks], h2, h3);
                mma_bf16_16n8k16(accS[2 * np + 1], Qh[ks], lo2, lo3);
                mma_bf16_16n8k16(accS[2 * np + 1], Ql[ks], h2, h3);
            }
        }

        // ---- mask + online softmax ----
        const int rowg0 = q0 + rowA;
        const int rowg1 = rowg0 + 8;
        const bool chk = (k0 + 63 > q0 + warp * 16);
        float mx0 = NEG_INF, mx1 = NEG_INF;
#pragma unroll
        for (int nt = 0; nt < 8; nt++) {
#pragma unroll
            for (int j = 0; j < 2; j++) {
                int col = k0 + nt * 8 + 2 * t + j;
                float s0 = accS[nt][j];
                float s1 = accS[nt][2 + j];
                if (chk) {
                    if (col > rowg0) s0 = NEG_INF;
                    if (col > rowg1) s1 = NEG_INF;
                }
                accS[nt][j] = s0;
                accS[nt][2 + j] = s1;
                mx0 = fmaxf(mx0, s0);
                mx1 = fmaxf(mx1, s1);
            }
        }
        mx0 = fmaxf(mx0, __shfl_xor_sync(0xffffffffu, mx0, 1));
        mx0 = fmaxf(mx0, __shfl_xor_sync(0xffffffffu, mx0, 2));
        mx1 = fmaxf(mx1, __shfl_xor_sync(0xffffffffu, mx1, 1));
        mx1 = fmaxf(mx1, __shfl_xor_sync(0xffffffffu, mx1, 2));

        float mn0 = fmaxf(m0, mx0), mn1 = fmaxf(m1, mx1);
        float al0 = __expf(m0 - mn0), al1 = __expf(m1 - mn1);
        float rs0 = 0.f, rs1 = 0.f;
        uint32_t Pha[8][2], Pla[8][2];
#pragma unroll
        for (int nt = 0; nt < 8; nt++) {
            float p00 = __expf(accS[nt][0] - mn0);
            float p01 = __expf(accS[nt][1] - mn0);
            float p10 = __expf(accS[nt][2] - mn1);
            float p11 = __expf(accS[nt][3] - mn1);
            rs0 += p00 + p01;
            rs1 += p10 + p11;
            bf16_split2(p00, p01, Pha[nt][0], Pla[nt][0]);
            bf16_split2(p10, p11, Pha[nt][1], Pla[nt][1]);
        }
        rs0 += __shfl_xor_sync(0xffffffffu, rs0, 1);
        rs0 += __shfl_xor_sync(0xffffffffu, rs0, 2);
        rs1 += __shfl_xor_sync(0xffffffffu, rs1, 1);
        rs1 += __shfl_xor_sync(0xffffffffu, rs1, 2);
        l0s = l0s * al0 + rs0;
        l1s = l1s * al1 + rs1;
        m0 = mn0;
        m1 = mn1;
#pragma unroll
        for (int nt = 0; nt < 16; nt++) {
            accO[nt][0] *= al0; accO[nt][1] *= al0;
            accO[nt][2] *= al1; accO[nt][3] *= al1;
        }

        // pending: {V(kb), K(kb+1)?} -> complete V(kb)
        if (kb + 1 < ntiles) asm volatile("cp.async.wait_group 1;" ::: "memory");
        else                 asm volatile("cp.async.wait_group 0;" ::: "memory");
        __syncthreads();

        // ---- O += P V ----
#pragma unroll
        for (int si = 0; si < 4; si++) {
            uint32_t pah[4] = {Pha[2 * si][0], Pha[2 * si][1],
                               Pha[2 * si + 1][0], Pha[2 * si + 1][1]};
            uint32_t pal[4] = {Pla[2 * si][0], Pla[2 * si][1],
                               Pla[2 * si + 1][0], Pla[2 * si + 1][1]};
            const int s16 = si * 16;
#pragma unroll
            for (int pr = 0; pr < 8; pr++) {
                uint32_t off = (uint32_t)((s16 + srow_off) * VS + pr * 16 + dcol_off) * 2;
                uint32_t vh0, vh1, vh2, vh3, vl0, vl1, vl2, vl3;
                LDSM_X4_T(vh0, vh1, vh2, vh3, vhi_base + off);
                LDSM_X4_T(vl0, vl1, vl2, vl3, vlo_base + off);
                const int nt0 = 2 * pr, nt1 = 2 * pr + 1;
                mma_bf16_16n8k16(accO[nt0], pah, vh0, vh1);
                mma_bf16_16n8k16(accO[nt0], pah, vl0, vl1);
                mma_bf16_16n8k16(accO[nt0], pal, vh0, vh1);
                mma_bf16_16n8k16(accO[nt1], pah, vh2, vh3);
                mma_bf16_16n8k16(accO[nt1], pah, vl2, vl3);
                mma_bf16_16n8k16(accO[nt1], pal, vh2, vh3);
            }
        }
        __syncthreads();                      // all warps done reading V planes
        if (kb + 1 < ntiles) ISSUE_V(kb + 1);
    }

    // ---- epilogue: normalize + tf32 round + k-permuted scatter ----
    float inv0 = 1.f / l0s, inv1 = 1.f / l1s;
    float* Op = Og + (size_t)(b * T_ + q0 + rowA) * DM + h * HD;
    float* Op8 = Op + (size_t)8 * DM;
#pragma unroll
    for (int nt = 0; nt < 16; nt++) {
#pragma unroll
        for (int j = 0; j < 2; j++) {
            int col = nt * 8 + 2 * t + j;
            int jj = col & 15;
            int p = (col & ~15) + ((jj & 3) << 2) + (jj >> 2);
            Op[p]  = tf32f(accO[nt][j] * inv0);
            Op8[p] = tf32f(accO[nt][2 + j] * inv1);
        }
    }
}

// ============================ launcher ==================================
extern "C" void kernel_launch(void* const* d_in, const int* in_sizes, int n_in,
                              void* d_out, int out_size) {
    const float* x  = (const float*)d_in[0];
    const float* Wq = (const float*)d_in[1];
    const float* Wk = (const float*)d_in[2];
    const float* Wv = (const float*)d_in[3];
    const float* Wo = (const float*)d_in[4];
    float* out = (float*)d_out;

    float *pQ, *pK, *pV, *pA, *pXc, *pWc;
    unsigned short *pQh, *pQl, *pKh, *pKl, *pVh, *pVl;
    cudaGetSymbolAddress((void**)&pQ, g_Q);
    cudaGetSymbolAddress((void**)&pK, g_K);
    cudaGetSymbolAddress((void**)&pV, g_V);
    cudaGetSymbolAddress((void**)&pA, g_A);
    cudaGetSymbolAddress((void**)&pXc, g_xc);
    cudaGetSymbolAddress((void**)&pWc, g_Wc);
    cudaGetSymbolAddress((void**)&pQh, g_Qhi);
    cudaGetSymbolAddress((void**)&pQl, g_Qlo);
    cudaGetSymbolAddress((void**)&pKh, g_Khi);
    cudaGetSymbolAddress((void**)&pKl, g_Klo);
    cudaGetSymbolAddress((void**)&pVh, g_Vhi);
    cudaGetSymbolAddress((void**)&pVl, g_Vlo);
    float* pWqc = pWc;
    float* pWkc = pWc + (size_t)DM * DM;
    float* pWvc = pWc + 2 * (size_t)DM * DM;
    float* pWoc = pWc + 3 * (size_t)DM * DM;

    cudaFuncSetAttribute(gemm_perm, cudaFuncAttributeMaxDynamicSharedMemorySize, GEMM_SMEM);
    cudaFuncSetAttribute(flash_bf16, cudaFuncAttributeMaxDynamicSharedMemorySize, FLASH_SMEM);

    const int NWG = (DM * DM) / 16;
    dim3 ggrid3(DM / 128, NROWS / 128, 3);
    dim3 ggrid1(DM / 128, NROWS / 128, 1);
    dim3 fgrid(T_ / 64, B_ * NH);          // (32, 32) = 1024 CTAs

    cvt_all<<<dim3(NWG / 256, 1, 6), 256>>>(x, Wq, Wk, Wv, Wo, pXc, pWc, NWG);   // 1
    gemm_perm<<<ggrid3, 128, GEMM_SMEM>>>(pXc, pWqc, pQ, pWkc, pK, pWvc, pV);    // 2
    rope_split<<<(NROWS * NH * 16) / 256, 256>>>(pQ, pK, pV,
                                                 pQh, pQl, pKh, pKl, pVh, pVl);  // 3
    flash_bf16<<<fgrid, 128, FLASH_SMEM>>>(pQh, pQl, pKh, pKl, pVh, pVl, pA);    // 4
    gemm_perm<<<ggrid1, 128, GEMM_SMEM>>>(pA, pWoc, out, pWoc, out, pWoc, out);  // 5
}